// round 10
// baseline (speedup 1.0000x reference)
#include <cuda_runtime.h>
#include <cuda_fp16.h>

#define NN  50000
#define EUN 200000
#define EDN 400000

// ---------------- scratch (device globals; no allocation) ----------------
__device__ __align__(16) unsigned g_ef16[EUN * 64];   // edge_feat fp16
__device__ __align__(16) unsigned g_nf16[NN * 64];    // node_feat fp16
__device__ __align__(16) unsigned g_msg16[EDN * 64];  // envelope-scaled messages fp16
__device__ __align__(16) unsigned g_ded16[EDN * 64];  // delta_edge_dir fp16
// GEMM1 partials (fp32, exact)
__device__ __align__(16) float g_pe[(size_t)EUN * 256];
__device__ __align__(16) float g_pt[(size_t)NN * 256];
__device__ __align__(16) float g_ps[(size_t)NN * 256];
// CSR over target_index
__device__ int g_csr_cnt[NN];
__device__ int g_csr_off[NN + 1];
__device__ int g_csr_cur[NN];
__device__ int g_csr_edges[EDN];
__device__ int g_part[256];
__device__ int g_pbase[256];

// pre-transposed fp16 weights, tile-blocked: [ktile32][n][16 words]
__device__ __align__(16) unsigned g_w1t[12 * 256 * 16];
__device__ __align__(16) unsigned g_w2ct[4 * 128 * 16];
__device__ __align__(16) unsigned g_w2gt[4 * 128 * 16];
__device__ __align__(16) unsigned g_we1t[4 * 128 * 16];
__device__ __align__(16) unsigned g_we2t[4 * 128 * 16];
__device__ __align__(16) unsigned g_wn1t[4 * 128 * 16];
__device__ __align__(16) unsigned g_wn2t[4 * 128 * 16];

__device__ __forceinline__ float tanhf_(float x) {
    float y;
    asm("tanh.approx.f32 %0, %1;" : "=f"(y) : "f"(x));
    return y;
}
__device__ __forceinline__ float sigmoidf_(float x) {
    return 0.5f * tanhf_(0.5f * x) + 0.5f;
}
__device__ __forceinline__ float siluf_(float x) { return x * sigmoidf_(x); }

__device__ __forceinline__ unsigned pack2(float x, float y) {
    __half2 h = __floats2half2_rn(x, y);
    return *reinterpret_cast<unsigned*>(&h);
}
__device__ __forceinline__ float2 unpack2(unsigned u) {
    __half2 h = *reinterpret_cast<__half2*>(&u);
    return __half22float2(h);
}
__device__ __forceinline__ unsigned sptr(const void* p) {
    return (unsigned)__cvta_generic_to_shared(p);
}
__device__ __forceinline__ void ldsm4(unsigned* r, unsigned a) {
    asm volatile("ldmatrix.sync.aligned.m8n8.x4.shared.b16 {%0,%1,%2,%3}, [%4];"
        : "=r"(r[0]), "=r"(r[1]), "=r"(r[2]), "=r"(r[3]) : "r"(a));
}
__device__ __forceinline__ void ldsm2(unsigned* r, unsigned a) {
    asm volatile("ldmatrix.sync.aligned.m8n8.x2.shared.b16 {%0,%1}, [%2];"
        : "=r"(r[0]), "=r"(r[1]) : "r"(a));
}
__device__ __forceinline__ void mma16(float* d, const unsigned* a, const unsigned* b) {
    asm volatile(
        "mma.sync.aligned.m16n8k16.row.col.f32.f16.f16.f32 "
        "{%0,%1,%2,%3}, {%4,%5,%6,%7}, {%8,%9}, {%0,%1,%2,%3};"
        : "+f"(d[0]), "+f"(d[1]), "+f"(d[2]), "+f"(d[3])
        : "r"(a[0]), "r"(a[1]), "r"(a[2]), "r"(a[3]), "r"(b[0]), "r"(b[1]));
}
__device__ __forceinline__ void cpa16(unsigned dst, const void* src) {
    asm volatile("cp.async.cg.shared.global [%0], [%1], 16;"
        :: "r"(dst), "l"(__cvta_generic_to_global(src)));
}
__device__ __forceinline__ void cpcommit() { asm volatile("cp.async.commit_group;"); }
__device__ __forceinline__ void cpwait0() { asm volatile("cp.async.wait_group 0;"); }
__device__ __forceinline__ void cpwait1() { asm volatile("cp.async.wait_group 1;"); }

// ---------------- weight prep ----------------
__global__ void k_prep(const float* __restrict__ Wc1, const float* __restrict__ Wg1,
                       const float* __restrict__ Wc2, const float* __restrict__ Wg2,
                       const float* __restrict__ We1, const float* __restrict__ We2,
                       const float* __restrict__ Wn1, const float* __restrict__ Wn2)
{
    int i = blockIdx.x * blockDim.x + threadIdx.x;
    if (i < 12 * 256 * 16) {
        int kt = i >> 12;
        int r = i & 4095;
        int n = r >> 4, kpl = r & 15;
        int kp = kt * 16 + kpl;
        const float* W = (n < 128) ? Wc1 : Wg1;
        int c = n & 127;
        g_w1t[i] = pack2(W[(size_t)(2 * kp) * 128 + c], W[(size_t)(2 * kp + 1) * 128 + c]);
        return;
    }
    int j = i - 12 * 256 * 16;
    if (j < 6 * 8192) {
        int mtx = j >> 13;
        int r = j & 8191;
        int kt = r >> 11, rr = r & 2047;
        int n = rr >> 4, kpl = rr & 15;
        int kp = kt * 16 + kpl;
        const float* W; unsigned* O;
        switch (mtx) {
            case 0: W = Wc2; O = g_w2ct; break;
            case 1: W = Wg2; O = g_w2gt; break;
            case 2: W = We1; O = g_we1t; break;
            case 3: W = We2; O = g_we2t; break;
            case 4: W = Wn1; O = g_wn1t; break;
            default: W = Wn2; O = g_wn2t; break;
        }
        O[r] = pack2(W[(size_t)(2 * kp) * 128 + n], W[(size_t)(2 * kp + 1) * 128 + n]);
    }
}

// ---------------- feature prep: fp32 -> packed fp16 (+ zero csr counters) ----------------
__global__ void k_prep2(const float* __restrict__ edge_feat, const float* __restrict__ node_feat)
{
    int i = blockIdx.x * blockDim.x + threadIdx.x;
    if (i < EUN * 64) {
        g_ef16[i] = pack2(edge_feat[2 * (size_t)i], edge_feat[2 * (size_t)i + 1]);
        return;
    }
    int j = i - EUN * 64;
    if (j < NN * 64) {
        g_nf16[j] = pack2(node_feat[2 * (size_t)j], node_feat[2 * (size_t)j + 1]);
        return;
    }
    int k = j - NN * 64;
    if (k < NN) g_csr_cnt[k] = 0;
}

// ---------------- k_pre1: GEMM1 partials (no gather, no activation, fp32 out) ----------
// seg 0: pe = ef16 @ W1[k 0:128]   (EUN rows)
// seg 1: pt = nf16 @ W1[k 128:256] (NN rows)
// seg 2: ps = nf16 @ W1[k 256:384] (NN rows)
// M=128 rows/block, N=256, K=128 (4 ktiles), 512 threads, warps 4m x 4n, warptile 32x64.
#define PE_BLKS ((EUN + 127) / 128)
#define PN_BLKS ((NN + 127) / 128)
#define PRE1_DYN ((2 * 2560 + 2 * 5120) * 4)   // 61440 B
__global__ __launch_bounds__(512) void k_pre1()
{
    extern __shared__ __align__(16) unsigned dyn[];
    const int tid = threadIdx.x;
    const unsigned sbase = sptr(dyn);

    int bid = blockIdx.x;
    int rBase, rowsMax, ktbase;
    const unsigned* feat;
    float* out;
    if (bid < PE_BLKS)              { rBase = bid * 128;              rowsMax = EUN; ktbase = 0; feat = g_ef16; out = g_pe; }
    else if (bid < PE_BLKS + PN_BLKS) { rBase = (bid - PE_BLKS) * 128;  rowsMax = NN;  ktbase = 4; feat = g_nf16; out = g_pt; }
    else                            { rBase = (bid - PE_BLKS - PN_BLKS) * 128; rowsMax = NN; ktbase = 8; feat = g_nf16; out = g_ps; }

    const int w = tid >> 5, lane = tid & 31;
    const int wm = w & 3, wn = w >> 2;
    const int grp = lane >> 2, qid = lane & 3;

    const int afm = tid >> 2, afc = tid & 3;
    int arow = rBase + afm;
    if (arow >= rowsMax) arow = rowsMax - 1;
    const unsigned* arowp = feat + (size_t)arow * 64 + afc * 4;

#define P1_FILL_A(kt, nb) \
    cpa16(sbase + ((nb) * 2560 + afm * 20 + afc * 4) * 4, arowp + (kt) * 16)
#define P1_FILL_B(kt, nb) do { \
    _Pragma("unroll") \
    for (int l = 0; l < 2; l++) { \
        int i4 = tid + l * 512; \
        int n_ = i4 >> 2, q_ = i4 & 3; \
        cpa16(sbase + (5120 + (nb) * 5120 + n_ * 20 + q_ * 4) * 4, \
              &g_w1t[(ktbase + (kt)) * 4096 + n_ * 16 + q_ * 4]); \
    } } while (0)

    P1_FILL_A(0, 0); P1_FILL_B(0, 0); cpcommit();

    const unsigned aOff = ((wm * 32 + (lane & 7) + ((lane >> 3) & 1) * 8) * 20 + ((lane >> 4) & 1) * 4) * 4;
    const unsigned bOff = ((wn * 64 + (lane & 7)) * 20 + ((lane >> 3) & 1) * 4) * 4;

    float acc[2][8][4];
#pragma unroll
    for (int mi = 0; mi < 2; mi++)
#pragma unroll
        for (int ni = 0; ni < 8; ni++)
#pragma unroll
            for (int q = 0; q < 4; q++) acc[mi][ni][q] = 0.f;

    for (int kt = 0; kt < 4; kt++) {
        if (kt < 3) {
            P1_FILL_A(kt + 1, (kt + 1) & 1);
            P1_FILL_B(kt + 1, (kt + 1) & 1);
            cpcommit();
            cpwait1();
        } else {
            cpwait0();
        }
        __syncthreads();
        const unsigned aB = sbase + ((kt & 1) * 2560) * 4 + aOff;
        const unsigned bB = sbase + (5120 + (kt & 1) * 5120) * 4 + bOff;
#pragma unroll
        for (int k16 = 0; k16 < 2; k16++) {
            unsigned a[2][4], b[8][2];
#pragma unroll
            for (int mi = 0; mi < 2; mi++) ldsm4(a[mi], aB + (mi * 16 * 20 + k16 * 8) * 4);
#pragma unroll
            for (int ni = 0; ni < 8; ni++) ldsm2(b[ni], bB + (ni * 8 * 20 + k16 * 8) * 4);
#pragma unroll
            for (int mi = 0; mi < 2; mi++)
#pragma unroll
                for (int ni = 0; ni < 8; ni++) mma16(acc[mi][ni], a[mi], b[ni]);
        }
        __syncthreads();
    }

#pragma unroll
    for (int mi = 0; mi < 2; mi++)
#pragma unroll
        for (int h = 0; h < 2; h++) {
            int grow = rBase + wm * 32 + mi * 16 + grp + 8 * h;
            if (grow >= rowsMax) continue;
            float* op = out + (size_t)grow * 256;
#pragma unroll
            for (int ni = 0; ni < 8; ni++) {
                int c = wn * 64 + ni * 8 + qid * 2;
                *(float2*)(op + c) = make_float2(acc[mi][ni][2 * h], acc[mi][ni][2 * h + 1]);
            }
        }
}

// ---------------- CSR build ----------------
__global__ void k_hist(const int* __restrict__ tgt_i) {
    int i = blockIdx.x * blockDim.x + threadIdx.x;
    if (i < EDN) atomicAdd(&g_csr_cnt[tgt_i[i]], 1);
}
__global__ void k_scan_part() {
    __shared__ int sm[256];
    int t = threadIdx.x;
    int i = blockIdx.x * 256 + t;
    sm[t] = (i < NN) ? g_csr_cnt[i] : 0;
    __syncthreads();
#pragma unroll
    for (int off = 128; off > 0; off >>= 1) {
        if (t < off) sm[t] += sm[t + off];
        __syncthreads();
    }
    if (t == 0) g_part[blockIdx.x] = sm[0];
}
__global__ void k_scan_top(int nparts) {
    __shared__ int sm[256];
    int t = threadIdx.x;
    sm[t] = (t < nparts) ? g_part[t] : 0;
    __syncthreads();
#pragma unroll
    for (int off = 1; off < 256; off <<= 1) {
        int v = (t >= off) ? sm[t - off] : 0;
        __syncthreads();
        sm[t] += v;
        __syncthreads();
    }
    if (t < nparts) g_pbase[t] = (t == 0) ? 0 : sm[t - 1];
    if (t == 0) g_csr_off[NN] = EDN;
}
__global__ void k_scan_apply() {
    __shared__ int sm[256];
    int t = threadIdx.x;
    int i = blockIdx.x * 256 + t;
    int v = (i < NN) ? g_csr_cnt[i] : 0;
    sm[t] = v;
    __syncthreads();
#pragma unroll
    for (int off = 1; off < 256; off <<= 1) {
        int u = (t >= off) ? sm[t - off] : 0;
        __syncthreads();
        sm[t] += u;
        __syncthreads();
    }
    if (i < NN) {
        int excl = sm[t] - v + g_pbase[blockIdx.x];
        g_csr_off[i] = excl;
        g_csr_cur[i] = excl;
    }
}
__global__ void k_scatter(const int* __restrict__ tgt_i) {
    int i = blockIdx.x * blockDim.x + threadIdx.x;
    if (i < EDN) {
        int pos = atomicAdd(&g_csr_cur[tgt_i[i]], 1);
        g_csr_edges[pos] = i;
    }
}

// ============ k_mega: edge pipeline, M=128 directed edges per block ============
// prologue: h = silu(pe[d2u] + pt[tgt] + ps[src]) -> smem (NO GEMM)
// stage A: core/gate (K=128); LN; msg. stage B: silu(t1@We1). stage C: t2@We2 -> ded.
#define FP 68
#define AcO 0
#define AgO 8704
#define BcO 17408
#define BgO 26112
#define MEGA_DYN ((BgO + 128 * FP) * 4)   // 139264 B
__global__ __launch_bounds__(512) void k_mega(
    const int* __restrict__ src_i, const int* __restrict__ tgt_i, const int* __restrict__ d2u,
    const float* __restrict__ lncg, const float* __restrict__ lncb,
    const float* __restrict__ lngg, const float* __restrict__ lngb,
    const float* __restrict__ smooth_weight, const float* __restrict__ W_env)
{
    extern __shared__ __align__(16) unsigned dyn[];
    __shared__ float Wenv_s[7][128];
    __shared__ float sw7[128][8];
    __shared__ float4 red[128][4];
    __shared__ int idxE[128], idxT[128], idxS[128];

    const int tid = threadIdx.x;
    const int eBase = blockIdx.x * 128;
    const int w = tid >> 5, lane = tid & 31;
    const int wm = w & 3, wn = w >> 2;
    const int grp = lane >> 2, qid = lane & 3;
    const unsigned sbase = sptr(dyn);

    if (tid < 128)      idxE[tid] = d2u[eBase + tid];
    else if (tid < 256) idxT[tid - 128] = tgt_i[eBase + tid - 128];
    else if (tid < 384) idxS[tid - 256] = src_i[eBase + tid - 256];
    __syncthreads();

    // prefetch Wc2/Wg2 for stage A
#pragma unroll
    for (int l = 0; l < 4; l++) {
        int i4 = tid + l * 512;
        int n_ = i4 >> 4, q_ = i4 & 15;
        int off = (q_ >> 2) * 2048 + n_ * 16 + (q_ & 3) * 4;
        unsigned d = (n_ * FP + (q_ >> 2) * 16 + (q_ & 3) * 4) * 4;
        cpa16(sbase + BcO * 4 + d, &g_w2ct[off]);
        cpa16(sbase + BgO * 4 + d, &g_w2gt[off]);
    }
    cpcommit();

    for (int f = tid; f < 896; f += 512) {
        int mm = f / 7, j = f % 7;
        sw7[mm][j] = smooth_weight[(size_t)d2u[eBase + mm] * 7 + j];
    }
    for (int f = tid; f < 896; f += 512) Wenv_s[f >> 7][f & 127] = W_env[f];

    // ---- prologue: h = silu(pe + pt + ps) -> Ac (n<128) / Ag (n>=128) ----
#pragma unroll
    for (int it = 0; it < 16; it++) {
        int f = tid + it * 512;          // 0..8191
        int m = f >> 6, cq = f & 63;     // row 0..127, col-quad 0..63 (c = cq*4)
        const float* pa = g_pe + (size_t)idxE[m] * 256 + cq * 4;
        const float* pb = g_pt + (size_t)idxT[m] * 256 + cq * 4;
        const float* pc = g_ps + (size_t)idxS[m] * 256 + cq * 4;
        float4 a = *(const float4*)pa;
        float4 b = *(const float4*)pb;
        float4 c = *(const float4*)pc;
        float h0 = siluf_(a.x + b.x + c.x);
        float h1 = siluf_(a.y + b.y + c.y);
        float h2 = siluf_(a.z + b.z + c.z);
        float h3 = siluf_(a.w + b.w + c.w);
        uint2 o = make_uint2(pack2(h0, h1), pack2(h2, h3));
        if (cq < 32) *(uint2*)&dyn[AcO + m * FP + cq * 2] = o;
        else         *(uint2*)&dyn[AgO + m * FP + (cq - 32) * 2] = o;
    }
    cpwait0();
    __syncthreads();

    const unsigned aFragOff = ((lane & 7) + ((lane >> 3) & 1) * 8) * FP + ((lane >> 4) & 1) * 4;
    const unsigned bRow2 = ((wn * 32 + (lane & 7)) * FP + ((lane >> 3) & 1) * 4) * 4;

    // ---- stage A: core & gate GEMM, K=128 ----
    float accc[2][4][4], accg[2][4][4];
#pragma unroll
    for (int mi = 0; mi < 2; mi++)
#pragma unroll
        for (int ni = 0; ni < 4; ni++)
#pragma unroll
            for (int q = 0; q < 4; q++) { accc[mi][ni][q] = 0.f; accg[mi][ni][q] = 0.f; }
    {
        const unsigned aC = sbase + (AcO + wm * 32 * FP + aFragOff) * 4;
        const unsigned aG = sbase + (AgO + wm * 32 * FP + aFragOff) * 4;
        const unsigned bC = sbase + BcO * 4 + bRow2;
        const unsigned bG = sbase + BgO * 4 + bRow2;
#pragma unroll
        for (int k16 = 0; k16 < 8; k16++) {
            unsigned ac[2][4], ag[2][4], bc[4][2], bg[4][2];
#pragma unroll
            for (int mi = 0; mi < 2; mi++) {
                ldsm4(ac[mi], aC + (mi * 16 * FP + k16 * 8) * 4);
                ldsm4(ag[mi], aG + (mi * 16 * FP + k16 * 8) * 4);
            }
#pragma unroll
            for (int ni = 0; ni < 4; ni++) {
                ldsm2(bc[ni], bC + (ni * 8 * FP + k16 * 8) * 4);
                ldsm2(bg[ni], bG + (ni * 8 * FP + k16 * 8) * 4);
            }
#pragma unroll
            for (int mi = 0; mi < 2; mi++)
#pragma unroll
                for (int ni = 0; ni < 4; ni++) {
                    mma16(accc[mi][ni], ac[mi], bc[ni]);
                    mma16(accg[mi][ni], ag[mi], bg[ni]);
                }
        }
    }

    // ---- LN partial sums ----
#pragma unroll
    for (int mi = 0; mi < 2; mi++)
#pragma unroll
        for (int h = 0; h < 2; h++) {
            float sc = 0.f, sc2 = 0.f, sg = 0.f, sg2 = 0.f;
#pragma unroll
            for (int ni = 0; ni < 4; ni++) {
                float c0 = accc[mi][ni][2 * h], c1 = accc[mi][ni][2 * h + 1];
                float g0 = accg[mi][ni][2 * h], g1 = accg[mi][ni][2 * h + 1];
                sc += c0 + c1; sc2 += c0 * c0 + c1 * c1;
                sg += g0 + g1; sg2 += g0 * g0 + g1 * g1;
            }
#pragma unroll
            for (int off = 1; off < 4; off <<= 1) {
                sc  += __shfl_xor_sync(0xffffffffu, sc,  off, 4);
                sc2 += __shfl_xor_sync(0xffffffffu, sc2, off, 4);
                sg  += __shfl_xor_sync(0xffffffffu, sg,  off, 4);
                sg2 += __shfl_xor_sync(0xffffffffu, sg2, off, 4);
            }
            if (qid == 0) red[wm * 32 + mi * 16 + grp + 8 * h][wn] = make_float4(sc, sc2, sg, sg2);
        }
    __syncthreads();

    // prefetch We1 / We2 into Bc/Bg regions
#pragma unroll
    for (int l = 0; l < 4; l++) {
        int i4 = tid + l * 512;
        int n_ = i4 >> 4, q_ = i4 & 15;
        int off = (q_ >> 2) * 2048 + n_ * 16 + (q_ & 3) * 4;
        unsigned d = (n_ * FP + (q_ >> 2) * 16 + (q_ & 3) * 4) * 4;
        cpa16(sbase + BcO * 4 + d, &g_we1t[off]);
        cpa16(sbase + BgO * 4 + d, &g_we2t[off]);
    }
    cpcommit();

    // ---- LN epilogue: nl -> t1 (Ac region), msg -> g_msg16 ----
#pragma unroll
    for (int mi = 0; mi < 2; mi++)
#pragma unroll
        for (int h = 0; h < 2; h++) {
            int rloc = wm * 32 + mi * 16 + grp + 8 * h;
            float4 p0 = red[rloc][0], p1 = red[rloc][1], p2 = red[rloc][2], p3 = red[rloc][3];
            float sc = p0.x + p1.x + p2.x + p3.x;
            float sc2 = p0.y + p1.y + p2.y + p3.y;
            float sg = p0.z + p1.z + p2.z + p3.z;
            float sg2 = p0.w + p1.w + p2.w + p3.w;
            float mc = sc * (1.f / 128.f);
            float vc = fmaxf(sc2 * (1.f / 128.f) - mc * mc, 0.f);
            float rc = rsqrtf(vc + 1e-5f);
            float mg = sg * (1.f / 128.f);
            float vg = fmaxf(sg2 * (1.f / 128.f) - mg * mg, 0.f);
            float rg = rsqrtf(vg + 1e-5f);

            float s0 = sw7[rloc][0], s1 = sw7[rloc][1], s2 = sw7[rloc][2], s3 = sw7[rloc][3];
            float s4 = sw7[rloc][4], s5 = sw7[rloc][5], s6 = sw7[rloc][6];
            unsigned* mp = g_msg16 + (size_t)(eBase + rloc) * 64;
#pragma unroll
            for (int ni = 0; ni < 4; ni++) {
                int c = wn * 32 + ni * 8 + qid * 2;
                float hc0 = (accc[mi][ni][2 * h] - mc) * rc * __ldg(&lncg[c]) + __ldg(&lncb[c]);
                float hg0 = (accg[mi][ni][2 * h] - mg) * rg * __ldg(&lngg[c]) + __ldg(&lngb[c]);
                float nl0 = siluf_(hc0) * sigmoidf_(hg0);
                float hc1 = (accc[mi][ni][2 * h + 1] - mc) * rc * __ldg(&lncg[c + 1]) + __ldg(&lncb[c + 1]);
                float hg1 = (accg[mi][ni][2 * h + 1] - mg) * rg * __ldg(&lngg[c + 1]) + __ldg(&lngb[c + 1]);
                float nl1 = siluf_(hc1) * sigmoidf_(hg1);
                dyn[AcO + rloc * FP + (c >> 1)] = pack2(nl0, nl1);
                float sw0 = s0 * Wenv_s[0][c] + s1 * Wenv_s[1][c] + s2 * Wenv_s[2][c]
                          + s3 * Wenv_s[3][c] + s4 * Wenv_s[4][c] + s5 * Wenv_s[5][c]
                          + s6 * Wenv_s[6][c];
                float sw1 = s0 * Wenv_s[0][c + 1] + s1 * Wenv_s[1][c + 1] + s2 * Wenv_s[2][c + 1]
                          + s3 * Wenv_s[3][c + 1] + s4 * Wenv_s[4][c + 1] + s5 * Wenv_s[5][c + 1]
                          + s6 * Wenv_s[6][c + 1];
                mp[c >> 1] = pack2(nl0 * sw0, nl1 * sw1);
            }
        }
    cpwait0();
    __syncthreads();

    // ---- stage B: silu(t1 @ We1) -> t2 (Ag region) ----
    float acc1[2][4][4];
#pragma unroll
    for (int mi = 0; mi < 2; mi++)
#pragma unroll
        for (int ni = 0; ni < 4; ni++)
#pragma unroll
            for (int q = 0; q < 4; q++) acc1[mi][ni][q] = 0.f;
    {
        const unsigned aT = sbase + (AcO + wm * 32 * FP + aFragOff) * 4;
        const unsigned bW = sbase + BcO * 4 + bRow2;
#pragma unroll
        for (int k16 = 0; k16 < 8; k16++) {
            unsigned a[2][4], b[4][2];
#pragma unroll
            for (int mi = 0; mi < 2; mi++) ldsm4(a[mi], aT + (mi * 16 * FP + k16 * 8) * 4);
#pragma unroll
            for (int ni = 0; ni < 4; ni++) ldsm2(b[ni], bW + (ni * 8 * FP + k16 * 8) * 4);
#pragma unroll
            for (int mi = 0; mi < 2; mi++)
#pragma unroll
                for (int ni = 0; ni < 4; ni++) mma16(acc1[mi][ni], a[mi], b[ni]);
        }
    }
#pragma unroll
    for (int mi = 0; mi < 2; mi++)
#pragma unroll
        for (int h = 0; h < 2; h++) {
            int rloc = wm * 32 + mi * 16 + grp + 8 * h;
#pragma unroll
            for (int ni = 0; ni < 4; ni++) {
                int c = wn * 32 + ni * 8 + qid * 2;
                dyn[AgO + rloc * FP + (c >> 1)] =
                    pack2(siluf_(acc1[mi][ni][2 * h]), siluf_(acc1[mi][ni][2 * h + 1]));
            }
        }
    __syncthreads();

    // ---- stage C: t2 @ We2 -> g_ded16 ----
    float acc2[2][4][4];
#pragma unroll
    for (int mi = 0; mi < 2; mi++)
#pragma unroll
        for (int ni = 0; ni < 4; ni++)
#pragma unroll
            for (int q = 0; q < 4; q++) acc2[mi][ni][q] = 0.f;
    {
        const unsigned aT = sbase + (AgO + wm * 32 * FP + aFragOff) * 4;
        const unsigned bW = sbase + BgO * 4 + bRow2;
#pragma unroll
        for (int k16 = 0; k16 < 8; k16++) {
            unsigned a[2][4], b[4][2];
#pragma unroll
            for (int mi = 0; mi < 2; mi++) ldsm4(a[mi], aT + (mi * 16 * FP + k16 * 8) * 4);
#pragma unroll
            for (int ni = 0; ni < 4; ni++) ldsm2(b[ni], bW + (ni * 8 * FP + k16 * 8) * 4);
#pragma unroll
            for (int mi = 0; mi < 2; mi++)
#pragma unroll
                for (int ni = 0; ni < 4; ni++) mma16(acc2[mi][ni], a[mi], b[ni]);
        }
    }
#pragma unroll
    for (int mi = 0; mi < 2; mi++)
#pragma unroll
        for (int h = 0; h < 2; h++) {
            int rloc = wm * 32 + mi * 16 + grp + 8 * h;
            unsigned* dp = g_ded16 + (size_t)(eBase + rloc) * 64;
#pragma unroll
            for (int ni = 0; ni < 4; ni++) {
                int c = wn * 32 + ni * 8 + qid * 2;
                dp[c >> 1] = pack2(acc2[mi][ni][2 * h], acc2[mi][ni][2 * h + 1]);
            }
        }
}

// ============ k_node_fused: CSR gather (smem) + 2-stage node FFN + residual ============
__global__ __launch_bounds__(256) void k_node_fused(
    const float* __restrict__ node_feat, const float* __restrict__ node_res_w,
    float* __restrict__ out_node)
{
    __shared__ __align__(16) unsigned As[64 * 68];
    __shared__ __align__(16) unsigned Bs[128 * 20];
    __shared__ __align__(16) unsigned t1[64 * 68];

    const int tid = threadIdx.x;
    const int nBase = blockIdx.x * 64;
    const int w = tid >> 5, lane = tid & 31;
    const int wm = w & 1, wn = w >> 1;
    const int grp = lane >> 2, qid = lane & 3;

    for (int s = 0; s < 8; s++) {
        int m = w * 8 + s;
        int node = nBase + m;
        float4 acc = make_float4(0.f, 0.f, 0.f, 0.f);
        if (node < NN) {
            int b = g_csr_off[node], e2 = g_csr_off[node + 1];
            int j = b;
            for (; j + 1 < e2; j += 2) {
                int ed0 = g_csr_edges[j], ed1 = g_csr_edges[j + 1];
                uint2 v0 = *(const uint2*)&g_msg16[(size_t)ed0 * 64 + lane * 2];
                uint2 v1 = *(const uint2*)&g_msg16[(size_t)ed1 * 64 + lane * 2];
                float2 a0 = unpack2(v0.x), b0 = unpack2(v0.y);
                float2 a1 = unpack2(v1.x), b1 = unpack2(v1.y);
                acc.x += a0.x + a1.x; acc.y += a0.y + a1.y;
                acc.z += b0.x + b1.x; acc.w += b0.y + b1.y;
            }
            if (j < e2) {
                int ed = g_csr_edges[j];
                uint2 v = *(const uint2*)&g_msg16[(size_t)ed * 64 + lane * 2];
                float2 a = unpack2(v.x), bb = unpack2(v.y);
                acc.x += a.x; acc.y += a.y; acc.z += bb.x; acc.w += bb.y;
            }
        }
        *(uint2*)&As[m * 68 + lane * 2] = make_uint2(pack2(acc.x, acc.y), pack2(acc.z, acc.w));
    }
    __syncthreads();

    const int aRow = wm * 32 + (lane & 7) + ((lane >> 3) & 1) * 8;
    const int aCol = ((lane >> 4) & 1) * 4;
    const unsigned aBase = sptr(As) + (aRow * 68 + aCol) * 4;
    const unsigned tBase = sptr(t1) + (aRow * 68 + aCol) * 4;
    const unsigned bBase = sptr(Bs) + ((wn * 32 + (lane & 7)) * 20 + ((lane >> 3) & 1) * 4) * 4;

    float acc[2][4][4];
#pragma unroll
    for (int mi = 0; mi < 2; mi++)
#pragma unroll
        for (int ni = 0; ni < 4; ni++)
#pragma unroll
            for (int q = 0; q < 4; q++) acc[mi][ni][q] = 0.f;

    for (int kt = 0; kt < 4; kt++) {
        {
            const uint4* src = (const uint4*)&g_wn1t[kt * 2048];
#pragma unroll
            for (int l = 0; l < 2; l++) {
                int i4 = tid + l * 256;
                int n = i4 >> 2, wq = (i4 & 3) * 4;
                *(uint4*)&Bs[n * 20 + wq] = src[i4];
            }
        }
        __syncthreads();
#pragma unroll
        for (int k16 = 0; k16 < 2; k16++) {
            unsigned a[2][4], b[4][2];
#pragma unroll
            for (int mi = 0; mi < 2; mi++)
                ldsm4(a[mi], aBase + (mi * 16 * 68 + kt * 16 + k16 * 8) * 4);
#pragma unroll
            for (int ni = 0; ni < 4; ni++) ldsm2(b[ni], bBase + (ni * 8 * 20 + k16 * 8) * 4);
#pragma unroll
            for (int mi = 0; mi < 2; mi++)
#pragma unroll
                for (int ni = 0; ni < 4; ni++) mma16(acc[mi][ni], a[mi], b[ni]);
        }
        __syncthreads();
    }
#pragma unroll
    for (int mi = 0; mi < 2; mi++)
#pragma unroll
        for (int h = 0; h < 2; h++) {
            int r = wm * 32 + mi * 16 + grp + 8 * h;
#pragma unroll
            for (int ni = 0; ni < 4; ni++) {
                int c = wn * 32 + ni * 8 + qid * 2;
                t1[r * 68 + (c >> 1)] = pack2(siluf_(acc[mi][ni][2 * h]), siluf_(acc[mi][ni][2 * h + 1]));
            }
        }
    __syncthreads();

    float acc2[2][4][4];
#pragma unroll
    for (int mi = 0; mi < 2; mi++)
#pragma unroll
        for (int ni = 0; ni < 4; ni++)
#pragma unroll
            for (int q = 0; q < 4; q++) acc2[mi][ni][q] = 0.f;

    for (int kt = 0; kt < 4; kt++) {
        {
            const uint4* src = (const uint4*)&g_wn2t[kt * 2048];
#pragma unroll
            for (int l = 0; l < 2; l++) {
                int i4 = tid + l * 256;
                int n = i4 >> 2, wq = (i4 & 3) * 4;
                *(uint4*)&Bs[n * 20 + wq] = src[i4];
            }
        }
        __syncthreads();
#pragma unroll
        for (int k16 = 0; k16 < 2; k16++) {
            unsigned a[2][4], b[4][2];
#pragma unroll
            for (int mi = 0; mi < 2; mi++)
                ldsm4(a[mi], tBase + (mi * 16 * 68 + kt * 16 + k16 * 8) * 4);
#pragma unroll
            for (int ni = 0; ni < 4; ni++) ldsm2(b[ni], bBase + (ni * 8 * 20 + k16 * 8) * 4);
#pragma unroll
            for (int mi = 0; mi < 2; mi++)
#pragma unroll
                for (int ni = 0; ni < 4; ni++) mma16(acc2[mi][ni], a[mi], b[ni]);
        }
        __syncthreads();
    }

#pragma unroll
    for (int mi = 0; mi < 2; mi++)
#pragma unroll
        for (int h = 0; h < 2; h++) {
            int row = nBase + wm * 32 + mi * 16 + grp + 8 * h;
            if (row >= NN) continue;
            const float* nf = node_feat + ((size_t)row << 7);
            float* op = out_node + ((size_t)row << 7);
#pragma unroll
            for (int ni = 0; ni < 4; ni++) {
                int c = wn * 32 + ni * 8 + qid * 2;
                float o0 = acc2[mi][ni][2 * h]     + __ldg(&node_res_w[c])     * nf[c];
                float o1 = acc2[mi][ni][2 * h + 1] + __ldg(&node_res_w[c + 1]) * nf[c + 1];
                *(float2*)(op + c) = make_float2(o0, o1);
            }
        }
}

// ============ edge output = (ded[u]+ded[u+EU])/2 + res*edge_feat ============
__global__ void k_edge_final(const float* __restrict__ edge_feat,
                             const float* __restrict__ edge_res_w,
                             float* __restrict__ out_edge)
{
    size_t i = (size_t)blockIdx.x * blockDim.x + threadIdx.x;
    const size_t total = (size_t)EUN * 32;
    if (i >= total) return;
    size_t u = i >> 5;
    int cw = (int)(i & 31);
    uint2 da = *(const uint2*)&g_ded16[u * 64 + cw * 2];
    uint2 db = *(const uint2*)&g_ded16[(u + EUN) * 64 + cw * 2];
    float2 a0 = unpack2(da.x), a1 = unpack2(da.y);
    float2 b0 = unpack2(db.x), b1 = unpack2(db.y);
    float4 ef = *(const float4*)&edge_feat[u * 128 + cw * 4];
    float4 rw = *(const float4*)&edge_res_w[cw * 4];
    float4 o;
    o.x = (a0.x + b0.x) * 0.5f + rw.x * ef.x;
    o.y = (a0.y + b0.y) * 0.5f + rw.y * ef.y;
    o.z = (a1.x + b1.x) * 0.5f + rw.z * ef.z;
    o.w = (a1.y + b1.y) * 0.5f + rw.w * ef.w;
    *(float4*)&out_edge[u * 128 + cw * 4] = o;
}

// ---------------- launch ----------------
extern "C" void kernel_launch(void* const* d_in, const int* in_sizes, int n_in,
                              void* d_out, int out_size)
{
    (void)in_sizes; (void)n_in; (void)out_size;
    const float* node_feat     = (const float*)d_in[0];
    const float* edge_feat     = (const float*)d_in[1];
    const float* smooth_weight = (const float*)d_in[2];
    const int*   source_index  = (const int*)d_in[3];
    const int*   target_index  = (const int*)d_in[4];
    const int*   d2u           = (const int*)d_in[5];
    const float* W_env         = (const float*)d_in[6];
    const float* Wc1           = (const float*)d_in[7];
    const float* Wc2           = (const float*)d_in[8];
    const float* Wg1           = (const float*)d_in[9];
    const float* Wg2           = (const float*)d_in[10];
    const float* ln_c_g        = (const float*)d_in[11];
    const float* ln_c_b        = (const float*)d_in[12];
    const float* ln_g_g        = (const float*)d_in[13];
    const float* ln_g_b        = (const float*)d_in[14];
    const float* Wn1           = (const float*)d_in[15];
    const float* Wn2           = (const float*)d_in[16];
    const float* We1           = (const float*)d_in[17];
    const float* We2           = (const float*)d_in[18];
    const float* node_res_w    = (const float*)d_in[19];
    const float* edge_res_w    = (const float*)d_in[20];

    float* out_node = (float*)d_out;
    float* out_edge = out_node + (size_t)NN * 128;

    cudaFuncSetAttribute(k_mega, cudaFuncAttributeMaxDynamicSharedMemorySize, MEGA_DYN);
    cudaFuncSetAttribute(k_pre1, cudaFuncAttributeMaxDynamicSharedMemorySize, PRE1_DYN);

    const int NPART = (NN + 255) / 256;

    k_prep<<<(12 * 256 * 16 + 6 * 8192 + 255) / 256, 256>>>(Wc1, Wg1, Wc2, Wg2, We1, We2, Wn1, Wn2);
    k_prep2<<<((EUN + NN) * 64 + NN + 255) / 256, 256>>>(edge_feat, node_feat);
    k_pre1<<<PE_BLKS + 2 * PN_BLKS, 512, PRE1_DYN>>>();

    k_mega<<<EDN / 128, 512, MEGA_DYN>>>(source_index, target_index, d2u,
                                         ln_c_g, ln_c_b, ln_g_g, ln_g_b,
                                         smooth_weight, W_env);

    k_hist<<<(EDN + 255) / 256, 256>>>(target_index);
    k_scan_part<<<NPART, 256>>>();
    k_scan_top<<<1, 256>>>(NPART);
    k_scan_apply<<<NPART, 256>>>();
    k_scatter<<<(EDN + 255) / 256, 256>>>(target_index);

    k_node_fused<<<(NN + 63) / 64, 256>>>(node_feat, node_res_w, out_node);

    k_edge_final<<<((int)((size_t)EUN * 32) + 255) / 256, 256>>>(edge_feat, edge_res_w, out_edge);
}

// round 11
// speedup vs baseline: 1.5584x; 1.5584x over previous
#include <cuda_runtime.h>
#include <cuda_fp16.h>

#define NN  50000
#define EUN 200000
#define EDN 400000

// ---------------- scratch (device globals; no allocation) ----------------
__device__ __align__(16) unsigned g_ef16[EUN * 64];   // edge_feat fp16
__device__ __align__(16) unsigned g_nf16[NN * 64];    // node_feat fp16
__device__ __align__(16) unsigned g_msg16[EDN * 64];  // envelope-scaled messages fp16
__device__ __align__(16) unsigned g_ded16[EDN * 64];  // delta_edge_dir fp16
// GEMM1 partials, fp16 packed: [row][128 words] (256 halves)
__device__ __align__(16) unsigned g_pe16[(size_t)EUN * 128];
__device__ __align__(16) unsigned g_pt16[(size_t)NN * 128];
__device__ __align__(16) unsigned g_ps16[(size_t)NN * 128];
// h = silu(pe+pt+ps) per directed edge, fp16 packed [e][128 words]
__device__ __align__(16) unsigned g_h16[(size_t)EDN * 128];
// CSR over target_index
__device__ int g_csr_cnt[NN];
__device__ int g_csr_off[NN + 1];
__device__ int g_csr_cur[NN];
__device__ int g_csr_edges[EDN];
__device__ int g_part[256];
__device__ int g_pbase[256];

// pre-transposed fp16 weights, tile-blocked: [ktile32][n][16 words]
__device__ __align__(16) unsigned g_w1t[12 * 256 * 16];
__device__ __align__(16) unsigned g_w2ct[4 * 128 * 16];
__device__ __align__(16) unsigned g_w2gt[4 * 128 * 16];
__device__ __align__(16) unsigned g_we1t[4 * 128 * 16];
__device__ __align__(16) unsigned g_we2t[4 * 128 * 16];
__device__ __align__(16) unsigned g_wn1t[4 * 128 * 16];
__device__ __align__(16) unsigned g_wn2t[4 * 128 * 16];

__device__ __forceinline__ float tanhf_(float x) {
    float y;
    asm("tanh.approx.f32 %0, %1;" : "=f"(y) : "f"(x));
    return y;
}
__device__ __forceinline__ float sigmoidf_(float x) {
    return 0.5f * tanhf_(0.5f * x) + 0.5f;
}
__device__ __forceinline__ float siluf_(float x) { return x * sigmoidf_(x); }

__device__ __forceinline__ unsigned pack2(float x, float y) {
    __half2 h = __floats2half2_rn(x, y);
    return *reinterpret_cast<unsigned*>(&h);
}
__device__ __forceinline__ float2 unpack2(unsigned u) {
    __half2 h = *reinterpret_cast<__half2*>(&u);
    return __half22float2(h);
}
__device__ __forceinline__ unsigned sptr(const void* p) {
    return (unsigned)__cvta_generic_to_shared(p);
}
__device__ __forceinline__ void ldsm4(unsigned* r, unsigned a) {
    asm volatile("ldmatrix.sync.aligned.m8n8.x4.shared.b16 {%0,%1,%2,%3}, [%4];"
        : "=r"(r[0]), "=r"(r[1]), "=r"(r[2]), "=r"(r[3]) : "r"(a));
}
__device__ __forceinline__ void ldsm2(unsigned* r, unsigned a) {
    asm volatile("ldmatrix.sync.aligned.m8n8.x2.shared.b16 {%0,%1}, [%2];"
        : "=r"(r[0]), "=r"(r[1]) : "r"(a));
}
__device__ __forceinline__ void mma16(float* d, const unsigned* a, const unsigned* b) {
    asm volatile(
        "mma.sync.aligned.m16n8k16.row.col.f32.f16.f16.f32 "
        "{%0,%1,%2,%3}, {%4,%5,%6,%7}, {%8,%9}, {%0,%1,%2,%3};"
        : "+f"(d[0]), "+f"(d[1]), "+f"(d[2]), "+f"(d[3])
        : "r"(a[0]), "r"(a[1]), "r"(a[2]), "r"(a[3]), "r"(b[0]), "r"(b[1]));
}
__device__ __forceinline__ void cpa16(unsigned dst, const void* src) {
    asm volatile("cp.async.cg.shared.global [%0], [%1], 16;"
        :: "r"(dst), "l"(__cvta_generic_to_global(src)));
}
__device__ __forceinline__ void cpcommit() { asm volatile("cp.async.commit_group;"); }
__device__ __forceinline__ void cpwait0() { asm volatile("cp.async.wait_group 0;"); }
__device__ __forceinline__ void cpwait1() { asm volatile("cp.async.wait_group 1;"); }

// ---------------- k_prepA: weights + features fp16 + csr zero (merged) ----------------
__global__ void k_prepA(const float* __restrict__ Wc1, const float* __restrict__ Wg1,
                        const float* __restrict__ Wc2, const float* __restrict__ Wg2,
                        const float* __restrict__ We1, const float* __restrict__ We2,
                        const float* __restrict__ Wn1, const float* __restrict__ Wn2,
                        const float* __restrict__ edge_feat, const float* __restrict__ node_feat)
{
    int i = blockIdx.x * blockDim.x + threadIdx.x;
    if (i < 12 * 256 * 16) {
        int kt = i >> 12;
        int r = i & 4095;
        int n = r >> 4, kpl = r & 15;
        int kp = kt * 16 + kpl;
        const float* W = (n < 128) ? Wc1 : Wg1;
        int c = n & 127;
        g_w1t[i] = pack2(W[(size_t)(2 * kp) * 128 + c], W[(size_t)(2 * kp + 1) * 128 + c]);
        return;
    }
    int j = i - 12 * 256 * 16;
    if (j < 6 * 8192) {
        int mtx = j >> 13;
        int r = j & 8191;
        int kt = r >> 11, rr = r & 2047;
        int n = rr >> 4, kpl = rr & 15;
        int kp = kt * 16 + kpl;
        const float* W; unsigned* O;
        switch (mtx) {
            case 0: W = Wc2; O = g_w2ct; break;
            case 1: W = Wg2; O = g_w2gt; break;
            case 2: W = We1; O = g_we1t; break;
            case 3: W = We2; O = g_we2t; break;
            case 4: W = Wn1; O = g_wn1t; break;
            default: W = Wn2; O = g_wn2t; break;
        }
        O[r] = pack2(W[(size_t)(2 * kp) * 128 + n], W[(size_t)(2 * kp + 1) * 128 + n]);
        return;
    }
    int k = j - 6 * 8192;
    if (k < EUN * 64) {
        g_ef16[k] = pack2(edge_feat[2 * (size_t)k], edge_feat[2 * (size_t)k + 1]);
        return;
    }
    int m = k - EUN * 64;
    if (m < NN * 64) {
        g_nf16[m] = pack2(node_feat[2 * (size_t)m], node_feat[2 * (size_t)m + 1]);
        return;
    }
    int z = m - NN * 64;
    if (z < NN) g_csr_cnt[z] = 0;
}
#define PREPA_ITEMS (12 * 256 * 16 + 6 * 8192 + EUN * 64 + NN * 64 + NN)

// ---------------- k_pre1: GEMM1 partials (fp16 out) ----------
// seg 0: pe = ef16 @ W1[k 0:128] (EUN rows); seg1: pt; seg2: ps (NN rows each)
#define PE_BLKS ((EUN + 127) / 128)
#define PN_BLKS ((NN + 127) / 128)
#define PRE1_DYN ((2 * 2560 + 2 * 5120) * 4)
__global__ __launch_bounds__(512) void k_pre1()
{
    extern __shared__ __align__(16) unsigned dyn[];
    const int tid = threadIdx.x;
    const unsigned sbase = sptr(dyn);

    int bid = blockIdx.x;
    int rBase, rowsMax, ktbase;
    const unsigned* feat;
    unsigned* out;
    if (bid < PE_BLKS)                { rBase = bid * 128;                       rowsMax = EUN; ktbase = 0; feat = g_ef16; out = g_pe16; }
    else if (bid < PE_BLKS + PN_BLKS) { rBase = (bid - PE_BLKS) * 128;           rowsMax = NN;  ktbase = 4; feat = g_nf16; out = g_pt16; }
    else                              { rBase = (bid - PE_BLKS - PN_BLKS) * 128; rowsMax = NN;  ktbase = 8; feat = g_nf16; out = g_ps16; }

    const int w = tid >> 5, lane = tid & 31;
    const int wm = w & 3, wn = w >> 2;
    const int grp = lane >> 2, qid = lane & 3;

    const int afm = tid >> 2, afc = tid & 3;
    int arow = rBase + afm;
    if (arow >= rowsMax) arow = rowsMax - 1;
    const unsigned* arowp = feat + (size_t)arow * 64 + afc * 4;

#define P1_FILL_A(kt, nb) \
    cpa16(sbase + ((nb) * 2560 + afm * 20 + afc * 4) * 4, arowp + (kt) * 16)
#define P1_FILL_B(kt, nb) do { \
    _Pragma("unroll") \
    for (int l = 0; l < 2; l++) { \
        int i4 = tid + l * 512; \
        int n_ = i4 >> 2, q_ = i4 & 3; \
        cpa16(sbase + (5120 + (nb) * 5120 + n_ * 20 + q_ * 4) * 4, \
              &g_w1t[(ktbase + (kt)) * 4096 + n_ * 16 + q_ * 4]); \
    } } while (0)

    P1_FILL_A(0, 0); P1_FILL_B(0, 0); cpcommit();

    const unsigned aOff = ((wm * 32 + (lane & 7) + ((lane >> 3) & 1) * 8) * 20 + ((lane >> 4) & 1) * 4) * 4;
    const unsigned bOff = ((wn * 64 + (lane & 7)) * 20 + ((lane >> 3) & 1) * 4) * 4;

    float acc[2][8][4];
#pragma unroll
    for (int mi = 0; mi < 2; mi++)
#pragma unroll
        for (int ni = 0; ni < 8; ni++)
#pragma unroll
            for (int q = 0; q < 4; q++) acc[mi][ni][q] = 0.f;

    for (int kt = 0; kt < 4; kt++) {
        if (kt < 3) {
            P1_FILL_A(kt + 1, (kt + 1) & 1);
            P1_FILL_B(kt + 1, (kt + 1) & 1);
            cpcommit();
            cpwait1();
        } else {
            cpwait0();
        }
        __syncthreads();
        const unsigned aB = sbase + ((kt & 1) * 2560) * 4 + aOff;
        const unsigned bB = sbase + (5120 + (kt & 1) * 5120) * 4 + bOff;
#pragma unroll
        for (int k16 = 0; k16 < 2; k16++) {
            unsigned a[2][4], b[8][2];
#pragma unroll
            for (int mi = 0; mi < 2; mi++) ldsm4(a[mi], aB + (mi * 16 * 20 + k16 * 8) * 4);
#pragma unroll
            for (int ni = 0; ni < 8; ni++) ldsm2(b[ni], bB + (ni * 8 * 20 + k16 * 8) * 4);
#pragma unroll
            for (int mi = 0; mi < 2; mi++)
#pragma unroll
                for (int ni = 0; ni < 8; ni++) mma16(acc[mi][ni], a[mi], b[ni]);
        }
        __syncthreads();
    }

#pragma unroll
    for (int mi = 0; mi < 2; mi++)
#pragma unroll
        for (int h = 0; h < 2; h++) {
            int grow = rBase + wm * 32 + mi * 16 + grp + 8 * h;
            if (grow >= rowsMax) continue;
            unsigned* op = out + (size_t)grow * 128;
#pragma unroll
            for (int ni = 0; ni < 8; ni++) {
                int c = wn * 64 + ni * 8 + qid * 2;
                op[c >> 1] = pack2(acc[mi][ni][2 * h], acc[mi][ni][2 * h + 1]);
            }
        }
}

// ---------------- k_h: high-occupancy streaming  h = silu(pe[u]+pt[tgt]+ps[src]) ------
__device__ __forceinline__ unsigned hss(unsigned a, unsigned b, unsigned c) {
    float2 fa = unpack2(a), fb = unpack2(b), fc = unpack2(c);
    return pack2(siluf_(fa.x + fb.x + fc.x), siluf_(fa.y + fb.y + fc.y));
}
__global__ __launch_bounds__(256) void k_h(
    const int* __restrict__ tgt_i, const int* __restrict__ src_i, const int* __restrict__ d2u)
{
    size_t i = (size_t)blockIdx.x * 256 + threadIdx.x;   // EDN*32 items (uint4 chunks)
    if (i >= (size_t)EDN * 32) return;
    int e = (int)(i >> 5), ch = (int)(i & 31);
    int u = __ldg(&d2u[e]);
    int t = __ldg(&tgt_i[e]);
    int s = __ldg(&src_i[e]);
    uint4 A = *(const uint4*)&g_pe16[(size_t)u * 128 + ch * 4];
    uint4 B = *(const uint4*)&g_pt16[(size_t)t * 128 + ch * 4];
    uint4 C = *(const uint4*)&g_ps16[(size_t)s * 128 + ch * 4];
    uint4 O;
    O.x = hss(A.x, B.x, C.x);
    O.y = hss(A.y, B.y, C.y);
    O.z = hss(A.z, B.z, C.z);
    O.w = hss(A.w, B.w, C.w);
    *(uint4*)&g_h16[i * 4] = O;
}

// ---------------- CSR build ----------------
__global__ void k_hist(const int* __restrict__ tgt_i) {
    int i = blockIdx.x * blockDim.x + threadIdx.x;
    if (i < EDN) atomicAdd(&g_csr_cnt[tgt_i[i]], 1);
}
__global__ void k_scan_part() {
    __shared__ int sm[256];
    int t = threadIdx.x;
    int i = blockIdx.x * 256 + t;
    sm[t] = (i < NN) ? g_csr_cnt[i] : 0;
    __syncthreads();
#pragma unroll
    for (int off = 128; off > 0; off >>= 1) {
        if (t < off) sm[t] += sm[t + off];
        __syncthreads();
    }
    if (t == 0) g_part[blockIdx.x] = sm[0];
}
__global__ void k_scan_top(int nparts) {
    __shared__ int sm[256];
    int t = threadIdx.x;
    sm[t] = (t < nparts) ? g_part[t] : 0;
    __syncthreads();
#pragma unroll
    for (int off = 1; off < 256; off <<= 1) {
        int v = (t >= off) ? sm[t - off] : 0;
        __syncthreads();
        sm[t] += v;
        __syncthreads();
    }
    if (t < nparts) g_pbase[t] = (t == 0) ? 0 : sm[t - 1];
    if (t == 0) g_csr_off[NN] = EDN;
}
__global__ void k_scan_apply() {
    __shared__ int sm[256];
    int t = threadIdx.x;
    int i = blockIdx.x * 256 + t;
    int v = (i < NN) ? g_csr_cnt[i] : 0;
    sm[t] = v;
    __syncthreads();
#pragma unroll
    for (int off = 1; off < 256; off <<= 1) {
        int u = (t >= off) ? sm[t - off] : 0;
        __syncthreads();
        sm[t] += u;
        __syncthreads();
    }
    if (i < NN) {
        int excl = sm[t] - v + g_pbase[blockIdx.x];
        g_csr_off[i] = excl;
        g_csr_cur[i] = excl;
    }
}
__global__ void k_scatter(const int* __restrict__ tgt_i) {
    int i = blockIdx.x * blockDim.x + threadIdx.x;
    if (i < EDN) {
        int pos = atomicAdd(&g_csr_cur[tgt_i[i]], 1);
        g_csr_edges[pos] = i;
    }
}

// ============ k_mega: stages A-C only; h prefetched via cp.async ============
#define FP 68
#define AcO 0
#define AgO 8704
#define BcO 17408
#define BgO 26112
#define MEGA_DYN ((BgO + 128 * FP) * 4)   // 139264 B
__global__ __launch_bounds__(512) void k_mega(
    const int* __restrict__ d2u,
    const float* __restrict__ lncg, const float* __restrict__ lncb,
    const float* __restrict__ lngg, const float* __restrict__ lngb,
    const float* __restrict__ smooth_weight, const float* __restrict__ W_env)
{
    extern __shared__ __align__(16) unsigned dyn[];
    __shared__ float Wenv_s[7][128];
    __shared__ float sw7[128][8];
    __shared__ float4 red[128][4];

    const int tid = threadIdx.x;
    const int eBase = blockIdx.x * 128;
    const int w = tid >> 5, lane = tid & 31;
    const int wm = w & 3, wn = w >> 2;
    const int grp = lane >> 2, qid = lane & 3;
    const unsigned sbase = sptr(dyn);

    // async fill: h rows (contiguous) -> Ac/Ag, plus Wc2/Wg2 -> Bc/Bg
#pragma unroll
    for (int l = 0; l < 8; l++) {
        int i4 = tid + l * 512;              // 0..4095
        int m = i4 >> 5, ch = i4 & 31;
        unsigned dst = (ch < 16) ? (AcO + m * FP + ch * 4)
                                 : (AgO + m * FP + (ch - 16) * 4);
        cpa16(sbase + dst * 4, &g_h16[((size_t)(eBase + m)) * 128 + ch * 4]);
    }
#pragma unroll
    for (int l = 0; l < 4; l++) {
        int i4 = tid + l * 512;
        int n_ = i4 >> 4, q_ = i4 & 15;
        int off = (q_ >> 2) * 2048 + n_ * 16 + (q_ & 3) * 4;
        unsigned d = (n_ * FP + (q_ >> 2) * 16 + (q_ & 3) * 4) * 4;
        cpa16(sbase + BcO * 4 + d, &g_w2ct[off]);
        cpa16(sbase + BgO * 4 + d, &g_w2gt[off]);
    }
    cpcommit();

    for (int f = tid; f < 896; f += 512) {
        int mm = f / 7, j = f % 7;
        sw7[mm][j] = smooth_weight[(size_t)d2u[eBase + mm] * 7 + j];
    }
    for (int f = tid; f < 896; f += 512) Wenv_s[f >> 7][f & 127] = W_env[f];

    cpwait0();
    __syncthreads();

    const unsigned aFragOff = ((lane & 7) + ((lane >> 3) & 1) * 8) * FP + ((lane >> 4) & 1) * 4;
    const unsigned bRow2 = ((wn * 32 + (lane & 7)) * FP + ((lane >> 3) & 1) * 4) * 4;

    // ---- stage A: core & gate GEMM, K=128 ----
    float accc[2][4][4], accg[2][4][4];
#pragma unroll
    for (int mi = 0; mi < 2; mi++)
#pragma unroll
        for (int ni = 0; ni < 4; ni++)
#pragma unroll
            for (int q = 0; q < 4; q++) { accc[mi][ni][q] = 0.f; accg[mi][ni][q] = 0.f; }
    {
        const unsigned aC = sbase + (AcO + wm * 32 * FP + aFragOff) * 4;
        const unsigned aG = sbase + (AgO + wm * 32 * FP + aFragOff) * 4;
        const unsigned bC = sbase + BcO * 4 + bRow2;
        const unsigned bG = sbase + BgO * 4 + bRow2;
#pragma unroll
        for (int k16 = 0; k16 < 8; k16++) {
            unsigned ac[2][4], ag[2][4], bc[4][2], bg[4][2];
#pragma unroll
            for (int mi = 0; mi < 2; mi++) {
                ldsm4(ac[mi], aC + (mi * 16 * FP + k16 * 8) * 4);
                ldsm4(ag[mi], aG + (mi * 16 * FP + k16 * 8) * 4);
            }
#pragma unroll
            for (int ni = 0; ni < 4; ni++) {
                ldsm2(bc[ni], bC + (ni * 8 * FP + k16 * 8) * 4);
                ldsm2(bg[ni], bG + (ni * 8 * FP + k16 * 8) * 4);
            }
#pragma unroll
            for (int mi = 0; mi < 2; mi++)
#pragma unroll
                for (int ni = 0; ni < 4; ni++) {
                    mma16(accc[mi][ni], ac[mi], bc[ni]);
                    mma16(accg[mi][ni], ag[mi], bg[ni]);
                }
        }
    }

    // ---- LN partial sums ----
#pragma unroll
    for (int mi = 0; mi < 2; mi++)
#pragma unroll
        for (int h = 0; h < 2; h++) {
            float sc = 0.f, sc2 = 0.f, sg = 0.f, sg2 = 0.f;
#pragma unroll
            for (int ni = 0; ni < 4; ni++) {
                float c0 = accc[mi][ni][2 * h], c1 = accc[mi][ni][2 * h + 1];
                float g0 = accg[mi][ni][2 * h], g1 = accg[mi][ni][2 * h + 1];
                sc += c0 + c1; sc2 += c0 * c0 + c1 * c1;
                sg += g0 + g1; sg2 += g0 * g0 + g1 * g1;
            }
#pragma unroll
            for (int off = 1; off < 4; off <<= 1) {
                sc  += __shfl_xor_sync(0xffffffffu, sc,  off, 4);
                sc2 += __shfl_xor_sync(0xffffffffu, sc2, off, 4);
                sg  += __shfl_xor_sync(0xffffffffu, sg,  off, 4);
                sg2 += __shfl_xor_sync(0xffffffffu, sg2, off, 4);
            }
            if (qid == 0) red[wm * 32 + mi * 16 + grp + 8 * h][wn] = make_float4(sc, sc2, sg, sg2);
        }
    __syncthreads();

    // prefetch We1 / We2 into Bc/Bg regions
#pragma unroll
    for (int l = 0; l < 4; l++) {
        int i4 = tid + l * 512;
        int n_ = i4 >> 4, q_ = i4 & 15;
        int off = (q_ >> 2) * 2048 + n_ * 16 + (q_ & 3) * 4;
        unsigned d = (n_ * FP + (q_ >> 2) * 16 + (q_ & 3) * 4) * 4;
        cpa16(sbase + BcO * 4 + d, &g_we1t[off]);
        cpa16(sbase + BgO * 4 + d, &g_we2t[off]);
    }
    cpcommit();

    // ---- LN epilogue: nl -> t1 (Ac region), msg -> g_msg16 ----
#pragma unroll
    for (int mi = 0; mi < 2; mi++)
#pragma unroll
        for (int h = 0; h < 2; h++) {
            int rloc = wm * 32 + mi * 16 + grp + 8 * h;
            float4 p0 = red[rloc][0], p1 = red[rloc][1], p2 = red[rloc][2], p3 = red[rloc][3];
            float sc = p0.x + p1.x + p2.x + p3.x;
            float sc2 = p0.y + p1.y + p2.y + p3.y;
            float sg = p0.z + p1.z + p2.z + p3.z;
            float sg2 = p0.w + p1.w + p2.w + p3.w;
            float mc = sc * (1.f / 128.f);
            float vc = fmaxf(sc2 * (1.f / 128.f) - mc * mc, 0.f);
            float rc = rsqrtf(vc + 1e-5f);
            float mg = sg * (1.f / 128.f);
            float vg = fmaxf(sg2 * (1.f / 128.f) - mg * mg, 0.f);
            float rg = rsqrtf(vg + 1e-5f);

            float s0 = sw7[rloc][0], s1 = sw7[rloc][1], s2 = sw7[rloc][2], s3 = sw7[rloc][3];
            float s4 = sw7[rloc][4], s5 = sw7[rloc][5], s6 = sw7[rloc][6];
            unsigned* mp = g_msg16 + (size_t)(eBase + rloc) * 64;
#pragma unroll
            for (int ni = 0; ni < 4; ni++) {
                int c = wn * 32 + ni * 8 + qid * 2;
                float hc0 = (accc[mi][ni][2 * h] - mc) * rc * __ldg(&lncg[c]) + __ldg(&lncb[c]);
                float hg0 = (accg[mi][ni][2 * h] - mg) * rg * __ldg(&lngg[c]) + __ldg(&lngb[c]);
                float nl0 = siluf_(hc0) * sigmoidf_(hg0);
                float hc1 = (accc[mi][ni][2 * h + 1] - mc) * rc * __ldg(&lncg[c + 1]) + __ldg(&lncb[c + 1]);
                float hg1 = (accg[mi][ni][2 * h + 1] - mg) * rg * __ldg(&lngg[c + 1]) + __ldg(&lngb[c + 1]);
                float nl1 = siluf_(hc1) * sigmoidf_(hg1);
                dyn[AcO + rloc * FP + (c >> 1)] = pack2(nl0, nl1);
                float sw0 = s0 * Wenv_s[0][c] + s1 * Wenv_s[1][c] + s2 * Wenv_s[2][c]
                          + s3 * Wenv_s[3][c] + s4 * Wenv_s[4][c] + s5 * Wenv_s[5][c]
                          + s6 * Wenv_s[6][c];
                float sw1 = s0 * Wenv_s[0][c + 1] + s1 * Wenv_s[1][c + 1] + s2 * Wenv_s[2][c + 1]
                          + s3 * Wenv_s[3][c + 1] + s4 * Wenv_s[4][c + 1] + s5 * Wenv_s[5][c + 1]
                          + s6 * Wenv_s[6][c + 1];
                mp[c >> 1] = pack2(nl0 * sw0, nl1 * sw1);
            }
        }
    cpwait0();
    __syncthreads();

    // ---- stage B: silu(t1 @ We1) -> t2 (Ag region) ----
    float acc1[2][4][4];
#pragma unroll
    for (int mi = 0; mi < 2; mi++)
#pragma unroll
        for (int ni = 0; ni < 4; ni++)
#pragma unroll
            for (int q = 0; q < 4; q++) acc1[mi][ni][q] = 0.f;
    {
        const unsigned aT = sbase + (AcO + wm * 32 * FP + aFragOff) * 4;
        const unsigned bW = sbase + BcO * 4 + bRow2;
#pragma unroll
        for (int k16 = 0; k16 < 8; k16++) {
            unsigned a[2][4], b[4][2];
#pragma unroll
            for (int mi = 0; mi < 2; mi++) ldsm4(a[mi], aT + (mi * 16 * FP + k16 * 8) * 4);
#pragma unroll
            for (int ni = 0; ni < 4; ni++) ldsm2(b[ni], bW + (ni * 8 * FP + k16 * 8) * 4);
#pragma unroll
            for (int mi = 0; mi < 2; mi++)
#pragma unroll
                for (int ni = 0; ni < 4; ni++) mma16(acc1[mi][ni], a[mi], b[ni]);
        }
    }
#pragma unroll
    for (int mi = 0; mi < 2; mi++)
#pragma unroll
        for (int h = 0; h < 2; h++) {
            int rloc = wm * 32 + mi * 16 + grp + 8 * h;
#pragma unroll
            for (int ni = 0; ni < 4; ni++) {
                int c = wn * 32 + ni * 8 + qid * 2;
                dyn[AgO + rloc * FP + (c >> 1)] =
                    pack2(siluf_(acc1[mi][ni][2 * h]), siluf_(acc1[mi][ni][2 * h + 1]));
            }
        }
    __syncthreads();

    // ---- stage C: t2 @ We2 -> g_ded16 ----
    float acc2[2][4][4];
#pragma unroll
    for (int mi = 0; mi < 2; mi++)
#pragma unroll
        for (int ni = 0; ni < 4; ni++)
#pragma unroll
            for (int q = 0; q < 4; q++) acc2[mi][ni][q] = 0.f;
    {
        const unsigned aT = sbase + (AgO + wm * 32 * FP + aFragOff) * 4;
        const unsigned bW = sbase + BgO * 4 + bRow2;
#pragma unroll
        for (int k16 = 0; k16 < 8; k16++) {
            unsigned a[2][4], b[4][2];
#pragma unroll
            for (int mi = 0; mi < 2; mi++) ldsm4(a[mi], aT + (mi * 16 * FP + k16 * 8) * 4);
#pragma unroll
            for (int ni = 0; ni < 4; ni++) ldsm2(b[ni], bW + (ni * 8 * FP + k16 * 8) * 4);
#pragma unroll
            for (int mi = 0; mi < 2; mi++)
#pragma unroll
                for (int ni = 0; ni < 4; ni++) mma16(acc2[mi][ni], a[mi], b[ni]);
        }
    }
#pragma unroll
    for (int mi = 0; mi < 2; mi++)
#pragma unroll
        for (int h = 0; h < 2; h++) {
            int rloc = wm * 32 + mi * 16 + grp + 8 * h;
            unsigned* dp = g_ded16 + (size_t)(eBase + rloc) * 64;
#pragma unroll
            for (int ni = 0; ni < 4; ni++) {
                int c = wn * 32 + ni * 8 + qid * 2;
                dp[c >> 1] = pack2(acc2[mi][ni][2 * h], acc2[mi][ni][2 * h + 1]);
            }
        }
}

// ============ k_node_fused: CSR gather (smem) + 2-stage node FFN + residual ============
__global__ __launch_bounds__(256) void k_node_fused(
    const float* __restrict__ node_feat, const float* __restrict__ node_res_w,
    float* __restrict__ out_node)
{
    __shared__ __align__(16) unsigned As[64 * 68];
    __shared__ __align__(16) unsigned Bs[128 * 20];
    __shared__ __align__(16) unsigned t1[64 * 68];

    const int tid = threadIdx.x;
    const int nBase = blockIdx.x * 64;
    const int w = tid >> 5, lane = tid & 31;
    const int wm = w & 1, wn = w >> 1;
    const int grp = lane >> 2, qid = lane & 3;

    for (int s = 0; s < 8; s++) {
        int m = w * 8 + s;
        int node = nBase + m;
        float4 acc = make_float4(0.f, 0.f, 0.f, 0.f);
        if (node < NN) {
            int b = g_csr_off[node], e2 = g_csr_off[node + 1];
            int j = b;
            for (; j + 1 < e2; j += 2) {
                int ed0 = g_csr_edges[j], ed1 = g_csr_edges[j + 1];
                uint2 v0 = *(const uint2*)&g_msg16[(size_t)ed0 * 64 + lane * 2];
                uint2 v1 = *(const uint2*)&g_msg16[(size_t)ed1 * 64 + lane * 2];
                float2 a0 = unpack2(v0.x), b0 = unpack2(v0.y);
                float2 a1 = unpack2(v1.x), b1 = unpack2(v1.y);
                acc.x += a0.x + a1.x; acc.y += a0.y + a1.y;
                acc.z += b0.x + b1.x; acc.w += b0.y + b1.y;
            }
            if (j < e2) {
                int ed = g_csr_edges[j];
                uint2 v = *(const uint2*)&g_msg16[(size_t)ed * 64 + lane * 2];
                float2 a = unpack2(v.x), bb = unpack2(v.y);
                acc.x += a.x; acc.y += a.y; acc.z += bb.x; acc.w += bb.y;
            }
        }
        *(uint2*)&As[m * 68 + lane * 2] = make_uint2(pack2(acc.x, acc.y), pack2(acc.z, acc.w));
    }
    __syncthreads();

    const int aRow = wm * 32 + (lane & 7) + ((lane >> 3) & 1) * 8;
    const int aCol = ((lane >> 4) & 1) * 4;
    const unsigned aBase = sptr(As) + (aRow * 68 + aCol) * 4;
    const unsigned tBase = sptr(t1) + (aRow * 68 + aCol) * 4;
    const unsigned bBase = sptr(Bs) + ((wn * 32 + (lane & 7)) * 20 + ((lane >> 3) & 1) * 4) * 4;

    float acc[2][4][4];
#pragma unroll
    for (int mi = 0; mi < 2; mi++)
#pragma unroll
        for (int ni = 0; ni < 4; ni++)
#pragma unroll
            for (int q = 0; q < 4; q++) acc[mi][ni][q] = 0.f;

    for (int kt = 0; kt < 4; kt++) {
        {
            const uint4* src = (const uint4*)&g_wn1t[kt * 2048];
#pragma unroll
            for (int l = 0; l < 2; l++) {
                int i4 = tid + l * 256;
                int n = i4 >> 2, wq = (i4 & 3) * 4;
                *(uint4*)&Bs[n * 20 + wq] = src[i4];
            }
        }
        __syncthreads();
#pragma unroll
        for (int k16 = 0; k16 < 2; k16++) {
            unsigned a[2][4], b[4][2];
#pragma unroll
            for (int mi = 0; mi < 2; mi++)
                ldsm4(a[mi], aBase + (mi * 16 * 68 + kt * 16 + k16 * 8) * 4);
#pragma unroll
            for (int ni = 0; ni < 4; ni++) ldsm2(b[ni], bBase + (ni * 8 * 20 + k16 * 8) * 4);
#pragma unroll
            for (int mi = 0; mi < 2; mi++)
#pragma unroll
                for (int ni = 0; ni < 4; ni++) mma16(acc[mi][ni], a[mi], b[ni]);
        }
        __syncthreads();
    }
#pragma unroll
    for (int mi = 0; mi < 2; mi++)
#pragma unroll
        for (int h = 0; h < 2; h++) {
            int r = wm * 32 + mi * 16 + grp + 8 * h;
#pragma unroll
            for (int ni = 0; ni < 4; ni++) {
                int c = wn * 32 + ni * 8 + qid * 2;
                t1[r * 68 + (c >> 1)] = pack2(siluf_(acc[mi][ni][2 * h]), siluf_(acc[mi][ni][2 * h + 1]));
            }
        }
    __syncthreads();

    float acc2[2][4][4];
#pragma unroll
    for (int mi = 0; mi < 2; mi++)
#pragma unroll
        for (int ni = 0; ni < 4; ni++)
#pragma unroll
            for (int q = 0; q < 4; q++) acc2[mi][ni][q] = 0.f;

    for (int kt = 0; kt < 4; kt++) {
        {
            const uint4* src = (const uint4*)&g_wn2t[kt * 2048];
#pragma unroll
            for (int l = 0; l < 2; l++) {
                int i4 = tid + l * 256;
                int n = i4 >> 2, wq = (i4 & 3) * 4;
                *(uint4*)&Bs[n * 20 + wq] = src[i4];
            }
        }
        __syncthreads();
#pragma unroll
        for (int k16 = 0; k16 < 2; k16++) {
            unsigned a[2][4], b[4][2];
#pragma unroll
            for (int mi = 0; mi < 2; mi++)
                ldsm4(a[mi], tBase + (mi * 16 * 68 + kt * 16 + k16 * 8) * 4);
#pragma unroll
            for (int ni = 0; ni < 4; ni++) ldsm2(b[ni], bBase + (ni * 8 * 20 + k16 * 8) * 4);
#pragma unroll
            for (int mi = 0; mi < 2; mi++)
#pragma unroll
                for (int ni = 0; ni < 4; ni++) mma16(acc2[mi][ni], a[mi], b[ni]);
        }
        __syncthreads();
    }

#pragma unroll
    for (int mi = 0; mi < 2; mi++)
#pragma unroll
        for (int h = 0; h < 2; h++) {
            int row = nBase + wm * 32 + mi * 16 + grp + 8 * h;
            if (row >= NN) continue;
            const float* nf = node_feat + ((size_t)row << 7);
            float* op = out_node + ((size_t)row << 7);
#pragma unroll
            for (int ni = 0; ni < 4; ni++) {
                int c = wn * 32 + ni * 8 + qid * 2;
                float o0 = acc2[mi][ni][2 * h]     + __ldg(&node_res_w[c])     * nf[c];
                float o1 = acc2[mi][ni][2 * h + 1] + __ldg(&node_res_w[c + 1]) * nf[c + 1];
                *(float2*)(op + c) = make_float2(o0, o1);
            }
        }
}

// ============ edge output = (ded[u]+ded[u+EU])/2 + res*edge_feat ============
__global__ void k_edge_final(const float* __restrict__ edge_feat,
                             const float* __restrict__ edge_res_w,
                             float* __restrict__ out_edge)
{
    size_t i = (size_t)blockIdx.x * blockDim.x + threadIdx.x;
    const size_t total = (size_t)EUN * 32;
    if (i >= total) return;
    size_t u = i >> 5;
    int cw = (int)(i & 31);
    uint2 da = *(const uint2*)&g_ded16[u * 64 + cw * 2];
    uint2 db = *(const uint2*)&g_ded16[(u + EUN) * 64 + cw * 2];
    float2 a0 = unpack2(da.x), a1 = unpack2(da.y);
    float2 b0 = unpack2(db.x), b1 = unpack2(db.y);
    float4 ef = *(const float4*)&edge_feat[u * 128 + cw * 4];
    float4 rw = *(const float4*)&edge_res_w[cw * 4];
    float4 o;
    o.x = (a0.x + b0.x) * 0.5f + rw.x * ef.x;
    o.y = (a0.y + b0.y) * 0.5f + rw.y * ef.y;
    o.z = (a1.x + b1.x) * 0.5f + rw.z * ef.z;
    o.w = (a1.y + b1.y) * 0.5f + rw.w * ef.w;
    *(float4*)&out_edge[u * 128 + cw * 4] = o;
}

// ---------------- launch ----------------
extern "C" void kernel_launch(void* const* d_in, const int* in_sizes, int n_in,
                              void* d_out, int out_size)
{
    (void)in_sizes; (void)n_in; (void)out_size;
    const float* node_feat     = (const float*)d_in[0];
    const float* edge_feat     = (const float*)d_in[1];
    const float* smooth_weight = (const float*)d_in[2];
    const int*   source_index  = (const int*)d_in[3];
    const int*   target_index  = (const int*)d_in[4];
    const int*   d2u           = (const int*)d_in[5];
    const float* W_env         = (const float*)d_in[6];
    const float* Wc1           = (const float*)d_in[7];
    const float* Wc2           = (const float*)d_in[8];
    const float* Wg1           = (const float*)d_in[9];
    const float* Wg2           = (const float*)d_in[10];
    const float* ln_c_g        = (const float*)d_in[11];
    const float* ln_c_b        = (const float*)d_in[12];
    const float* ln_g_g        = (const float*)d_in[13];
    const float* ln_g_b        = (const float*)d_in[14];
    const float* Wn1           = (const float*)d_in[15];
    const float* Wn2           = (const float*)d_in[16];
    const float* We1           = (const float*)d_in[17];
    const float* We2           = (const float*)d_in[18];
    const float* node_res_w    = (const float*)d_in[19];
    const float* edge_res_w    = (const float*)d_in[20];

    float* out_node = (float*)d_out;
    float* out_edge = out_node + (size_t)NN * 128;

    cudaFuncSetAttribute(k_mega, cudaFuncAttributeMaxDynamicSharedMemorySize, MEGA_DYN);
    cudaFuncSetAttribute(k_pre1, cudaFuncAttributeMaxDynamicSharedMemorySize, PRE1_DYN);

    const int NPART = (NN + 255) / 256;

    k_prepA<<<(PREPA_ITEMS + 255) / 256, 256>>>(Wc1, Wg1, Wc2, Wg2, We1, We2, Wn1, Wn2,
                                                edge_feat, node_feat);
    k_pre1<<<PE_BLKS + 2 * PN_BLKS, 512, PRE1_DYN>>>();
    k_h<<<(int)(((size_t)EDN * 32 + 255) / 256), 256>>>(target_index, source_index, d2u);

    k_mega<<<EDN / 128, 512, MEGA_DYN>>>(d2u, ln_c_g, ln_c_b, ln_g_g, ln_g_b,
                                         smooth_weight, W_env);

    k_hist<<<(EDN + 255) / 256, 256>>>(target_index);
    k_scan_part<<<NPART, 256>>>();
    k_scan_top<<<1, 256>>>(NPART);
    k_scan_apply<<<NPART, 256>>>();
    k_scatter<<<(EDN + 255) / 256, 256>>>(target_index);

    k_node_fused<<<(NN + 63) / 64, 256>>>(node_feat, node_res_w, out_node);

    k_edge_final<<<((int)((size_t)EUN * 32) + 255) / 256, 256>>>(edge_feat, edge_res_w, out_edge);
}

// round 12
// speedup vs baseline: 1.6165x; 1.0373x over previous
#include <cuda_runtime.h>
#include <cuda_fp16.h>

#define NN  50000
#define EUN 200000
#define EDN 400000

// ---------------- scratch (device globals; no allocation) ----------------
__device__ __align__(16) unsigned g_ef16[EUN * 64];   // edge_feat fp16
__device__ __align__(16) unsigned g_nf16[NN * 64];    // node_feat fp16
__device__ __align__(16) unsigned g_msg16[EDN * 64];  // envelope-scaled messages fp16
__device__ __align__(16) unsigned g_ded16[EDN * 64];  // delta_edge_dir fp16
// GEMM1 partials, fp16 packed: [row][128 words] (256 halves)
__device__ __align__(16) unsigned g_pe16[(size_t)EUN * 128];
__device__ __align__(16) unsigned g_pt16[(size_t)NN * 128];
__device__ __align__(16) unsigned g_ps16[(size_t)NN * 128];
// h = silu(pe+pt+ps) per directed edge, fp16 packed [e][128 words]
__device__ __align__(16) unsigned g_h16[(size_t)EDN * 128];
// CSR over target_index
__device__ int g_csr_cnt[NN];
__device__ int g_csr_off[NN + 1];
__device__ int g_csr_cur[NN];
__device__ int g_csr_edges[EDN];
__device__ int g_part[256];
__device__ int g_pbase[256];

// pre-transposed fp16 weights, tile-blocked: [ktile32][n][16 words]
__device__ __align__(16) unsigned g_w1t[12 * 256 * 16];
__device__ __align__(16) unsigned g_w2ct[4 * 128 * 16];
__device__ __align__(16) unsigned g_w2gt[4 * 128 * 16];
__device__ __align__(16) unsigned g_we1t[4 * 128 * 16];
__device__ __align__(16) unsigned g_we2t[4 * 128 * 16];
__device__ __align__(16) unsigned g_wn1t[4 * 128 * 16];
__device__ __align__(16) unsigned g_wn2t[4 * 128 * 16];

__device__ __forceinline__ float tanhf_(float x) {
    float y;
    asm("tanh.approx.f32 %0, %1;" : "=f"(y) : "f"(x));
    return y;
}
__device__ __forceinline__ float sigmoidf_(float x) {
    return 0.5f * tanhf_(0.5f * x) + 0.5f;
}
__device__ __forceinline__ float siluf_(float x) { return x * sigmoidf_(x); }

__device__ __forceinline__ unsigned pack2(float x, float y) {
    __half2 h = __floats2half2_rn(x, y);
    return *reinterpret_cast<unsigned*>(&h);
}
__device__ __forceinline__ float2 unpack2(unsigned u) {
    __half2 h = *reinterpret_cast<__half2*>(&u);
    return __half22float2(h);
}
__device__ __forceinline__ unsigned sptr(const void* p) {
    return (unsigned)__cvta_generic_to_shared(p);
}
__device__ __forceinline__ void ldsm4(unsigned* r, unsigned a) {
    asm volatile("ldmatrix.sync.aligned.m8n8.x4.shared.b16 {%0,%1,%2,%3}, [%4];"
        : "=r"(r[0]), "=r"(r[1]), "=r"(r[2]), "=r"(r[3]) : "r"(a));
}
__device__ __forceinline__ void ldsm2(unsigned* r, unsigned a) {
    asm volatile("ldmatrix.sync.aligned.m8n8.x2.shared.b16 {%0,%1}, [%2];"
        : "=r"(r[0]), "=r"(r[1]) : "r"(a));
}
__device__ __forceinline__ void mma16(float* d, const unsigned* a, const unsigned* b) {
    asm volatile(
        "mma.sync.aligned.m16n8k16.row.col.f32.f16.f16.f32 "
        "{%0,%1,%2,%3}, {%4,%5,%6,%7}, {%8,%9}, {%0,%1,%2,%3};"
        : "+f"(d[0]), "+f"(d[1]), "+f"(d[2]), "+f"(d[3])
        : "r"(a[0]), "r"(a[1]), "r"(a[2]), "r"(a[3]), "r"(b[0]), "r"(b[1]));
}
__device__ __forceinline__ void cpa16(unsigned dst, const void* src) {
    asm volatile("cp.async.cg.shared.global [%0], [%1], 16;"
        :: "r"(dst), "l"(__cvta_generic_to_global(src)));
}
__device__ __forceinline__ void cpcommit() { asm volatile("cp.async.commit_group;"); }
__device__ __forceinline__ void cpwait0() { asm volatile("cp.async.wait_group 0;"); }
__device__ __forceinline__ void cpwait1() { asm volatile("cp.async.wait_group 1;"); }

// ---------------- k_prepA: weights + features fp16 + csr zero (merged) ----------------
__global__ void k_prepA(const float* __restrict__ Wc1, const float* __restrict__ Wg1,
                        const float* __restrict__ Wc2, const float* __restrict__ Wg2,
                        const float* __restrict__ We1, const float* __restrict__ We2,
                        const float* __restrict__ Wn1, const float* __restrict__ Wn2,
                        const float* __restrict__ edge_feat, const float* __restrict__ node_feat)
{
    int i = blockIdx.x * blockDim.x + threadIdx.x;
    if (i < 12 * 256 * 16) {
        int kt = i >> 12;
        int r = i & 4095;
        int n = r >> 4, kpl = r & 15;
        int kp = kt * 16 + kpl;
        const float* W = (n < 128) ? Wc1 : Wg1;
        int c = n & 127;
        g_w1t[i] = pack2(W[(size_t)(2 * kp) * 128 + c], W[(size_t)(2 * kp + 1) * 128 + c]);
        return;
    }
    int j = i - 12 * 256 * 16;
    if (j < 6 * 8192) {
        int mtx = j >> 13;
        int r = j & 8191;
        int kt = r >> 11, rr = r & 2047;
        int n = rr >> 4, kpl = rr & 15;
        int kp = kt * 16 + kpl;
        const float* W; unsigned* O;
        switch (mtx) {
            case 0: W = Wc2; O = g_w2ct; break;
            case 1: W = Wg2; O = g_w2gt; break;
            case 2: W = We1; O = g_we1t; break;
            case 3: W = We2; O = g_we2t; break;
            case 4: W = Wn1; O = g_wn1t; break;
            default: W = Wn2; O = g_wn2t; break;
        }
        O[r] = pack2(W[(size_t)(2 * kp) * 128 + n], W[(size_t)(2 * kp + 1) * 128 + n]);
        return;
    }
    int k = j - 6 * 8192;
    if (k < EUN * 64) {
        g_ef16[k] = pack2(edge_feat[2 * (size_t)k], edge_feat[2 * (size_t)k + 1]);
        return;
    }
    int m = k - EUN * 64;
    if (m < NN * 64) {
        g_nf16[m] = pack2(node_feat[2 * (size_t)m], node_feat[2 * (size_t)m + 1]);
        return;
    }
    int z = m - NN * 64;
    if (z < NN) g_csr_cnt[z] = 0;
}
#define PREPA_ITEMS (12 * 256 * 16 + 6 * 8192 + EUN * 64 + NN * 64 + NN)

// ---------------- k_pre1: GEMM1 partials (fp16 out) ----------
#define PE_BLKS ((EUN + 127) / 128)
#define PN_BLKS ((NN + 127) / 128)
#define PRE1_DYN ((2 * 2560 + 2 * 5120) * 4)
__global__ __launch_bounds__(512) void k_pre1()
{
    extern __shared__ __align__(16) unsigned dyn[];
    const int tid = threadIdx.x;
    const unsigned sbase = sptr(dyn);

    int bid = blockIdx.x;
    int rBase, rowsMax, ktbase;
    const unsigned* feat;
    unsigned* out;
    if (bid < PE_BLKS)                { rBase = bid * 128;                       rowsMax = EUN; ktbase = 0; feat = g_ef16; out = g_pe16; }
    else if (bid < PE_BLKS + PN_BLKS) { rBase = (bid - PE_BLKS) * 128;           rowsMax = NN;  ktbase = 4; feat = g_nf16; out = g_pt16; }
    else                              { rBase = (bid - PE_BLKS - PN_BLKS) * 128; rowsMax = NN;  ktbase = 8; feat = g_nf16; out = g_ps16; }

    const int w = tid >> 5, lane = tid & 31;
    const int wm = w & 3, wn = w >> 2;
    const int grp = lane >> 2, qid = lane & 3;

    const int afm = tid >> 2, afc = tid & 3;
    int arow = rBase + afm;
    if (arow >= rowsMax) arow = rowsMax - 1;
    const unsigned* arowp = feat + (size_t)arow * 64 + afc * 4;

#define P1_FILL_A(kt, nb) \
    cpa16(sbase + ((nb) * 2560 + afm * 20 + afc * 4) * 4, arowp + (kt) * 16)
#define P1_FILL_B(kt, nb) do { \
    _Pragma("unroll") \
    for (int l = 0; l < 2; l++) { \
        int i4 = tid + l * 512; \
        int n_ = i4 >> 2, q_ = i4 & 3; \
        cpa16(sbase + (5120 + (nb) * 5120 + n_ * 20 + q_ * 4) * 4, \
              &g_w1t[(ktbase + (kt)) * 4096 + n_ * 16 + q_ * 4]); \
    } } while (0)

    P1_FILL_A(0, 0); P1_FILL_B(0, 0); cpcommit();

    const unsigned aOff = ((wm * 32 + (lane & 7) + ((lane >> 3) & 1) * 8) * 20 + ((lane >> 4) & 1) * 4) * 4;
    const unsigned bOff = ((wn * 64 + (lane & 7)) * 20 + ((lane >> 3) & 1) * 4) * 4;

    float acc[2][8][4];
#pragma unroll
    for (int mi = 0; mi < 2; mi++)
#pragma unroll
        for (int ni = 0; ni < 8; ni++)
#pragma unroll
            for (int q = 0; q < 4; q++) acc[mi][ni][q] = 0.f;

    for (int kt = 0; kt < 4; kt++) {
        if (kt < 3) {
            P1_FILL_A(kt + 1, (kt + 1) & 1);
            P1_FILL_B(kt + 1, (kt + 1) & 1);
            cpcommit();
            cpwait1();
        } else {
            cpwait0();
        }
        __syncthreads();
        const unsigned aB = sbase + ((kt & 1) * 2560) * 4 + aOff;
        const unsigned bB = sbase + (5120 + (kt & 1) * 5120) * 4 + bOff;
#pragma unroll
        for (int k16 = 0; k16 < 2; k16++) {
            unsigned a[2][4], b[8][2];
#pragma unroll
            for (int mi = 0; mi < 2; mi++) ldsm4(a[mi], aB + (mi * 16 * 20 + k16 * 8) * 4);
#pragma unroll
            for (int ni = 0; ni < 8; ni++) ldsm2(b[ni], bB + (ni * 8 * 20 + k16 * 8) * 4);
#pragma unroll
            for (int mi = 0; mi < 2; mi++)
#pragma unroll
                for (int ni = 0; ni < 8; ni++) mma16(acc[mi][ni], a[mi], b[ni]);
        }
        __syncthreads();
    }

#pragma unroll
    for (int mi = 0; mi < 2; mi++)
#pragma unroll
        for (int h = 0; h < 2; h++) {
            int grow = rBase + wm * 32 + mi * 16 + grp + 8 * h;
            if (grow >= rowsMax) continue;
            unsigned* op = out + (size_t)grow * 128;
#pragma unroll
            for (int ni = 0; ni < 8; ni++) {
                int c = wn * 64 + ni * 8 + qid * 2;
                op[c >> 1] = pack2(acc[mi][ni][2 * h], acc[mi][ni][2 * h + 1]);
            }
        }
}

// ---------------- k_h: high-occupancy streaming  h = silu(pe[u]+pt[tgt]+ps[src]) ------
__device__ __forceinline__ unsigned hss(unsigned a, unsigned b, unsigned c) {
    float2 fa = unpack2(a), fb = unpack2(b), fc = unpack2(c);
    return pack2(siluf_(fa.x + fb.x + fc.x), siluf_(fa.y + fb.y + fc.y));
}
__global__ __launch_bounds__(256) void k_h(
    const int* __restrict__ tgt_i, const int* __restrict__ src_i, const int* __restrict__ d2u)
{
    size_t i = (size_t)blockIdx.x * 256 + threadIdx.x;
    if (i >= (size_t)EDN * 32) return;
    int e = (int)(i >> 5), ch = (int)(i & 31);
    int u = __ldg(&d2u[e]);
    int t = __ldg(&tgt_i[e]);
    int s = __ldg(&src_i[e]);
    uint4 A = *(const uint4*)&g_pe16[(size_t)u * 128 + ch * 4];
    uint4 B = *(const uint4*)&g_pt16[(size_t)t * 128 + ch * 4];
    uint4 C = *(const uint4*)&g_ps16[(size_t)s * 128 + ch * 4];
    uint4 O;
    O.x = hss(A.x, B.x, C.x);
    O.y = hss(A.y, B.y, C.y);
    O.z = hss(A.z, B.z, C.z);
    O.w = hss(A.w, B.w, C.w);
    *(uint4*)&g_h16[i * 4] = O;
}

// ---------------- CSR build ----------------
__global__ void k_hist(const int* __restrict__ tgt_i) {
    int i = blockIdx.x * blockDim.x + threadIdx.x;
    if (i < EDN) atomicAdd(&g_csr_cnt[tgt_i[i]], 1);
}
__global__ void k_scan_part() {
    __shared__ int sm[256];
    int t = threadIdx.x;
    int i = blockIdx.x * 256 + t;
    sm[t] = (i < NN) ? g_csr_cnt[i] : 0;
    __syncthreads();
#pragma unroll
    for (int off = 128; off > 0; off >>= 1) {
        if (t < off) sm[t] += sm[t + off];
        __syncthreads();
    }
    if (t == 0) g_part[blockIdx.x] = sm[0];
}
__global__ void k_scan_top(int nparts) {
    __shared__ int sm[256];
    int t = threadIdx.x;
    sm[t] = (t < nparts) ? g_part[t] : 0;
    __syncthreads();
#pragma unroll
    for (int off = 1; off < 256; off <<= 1) {
        int v = (t >= off) ? sm[t - off] : 0;
        __syncthreads();
        sm[t] += v;
        __syncthreads();
    }
    if (t < nparts) g_pbase[t] = (t == 0) ? 0 : sm[t - 1];
    if (t == 0) g_csr_off[NN] = EDN;
}
__global__ void k_scan_apply() {
    __shared__ int sm[256];
    int t = threadIdx.x;
    int i = blockIdx.x * 256 + t;
    int v = (i < NN) ? g_csr_cnt[i] : 0;
    sm[t] = v;
    __syncthreads();
#pragma unroll
    for (int off = 1; off < 256; off <<= 1) {
        int u = (t >= off) ? sm[t - off] : 0;
        __syncthreads();
        sm[t] += u;
        __syncthreads();
    }
    if (i < NN) {
        int excl = sm[t] - v + g_pbase[blockIdx.x];
        g_csr_off[i] = excl;
        g_csr_cur[i] = excl;
    }
}
__global__ void k_scatter(const int* __restrict__ tgt_i) {
    int i = blockIdx.x * blockDim.x + threadIdx.x;
    if (i < EDN) {
        int pos = atomicAdd(&g_csr_cur[tgt_i[i]], 1);
        g_csr_edges[pos] = i;
    }
}

// ============ k_mega: stages A-C, M=64/block, 256 threads, 2 blocks/SM ============
#define FP 68
#define AcO 0                     // 64*68 = 4352 w
#define AgO 4352
#define BcO 8704                  // 128*68 = 8704 w
#define BgO 17408
#define MEGA_DYN ((BgO + 128 * FP) * 4)   // 26112 w = 104448 B
__global__ __launch_bounds__(256, 2) void k_mega(
    const int* __restrict__ d2u,
    const float* __restrict__ lncg, const float* __restrict__ lncb,
    const float* __restrict__ lngg, const float* __restrict__ lngb,
    const float* __restrict__ smooth_weight, const float* __restrict__ W_env)
{
    extern __shared__ __align__(16) unsigned dyn[];
    __shared__ float Wenv_s[7][128];
    __shared__ float sw7[64][8];
    __shared__ float4 red[64][4];

    const int tid = threadIdx.x;
    const int eBase = blockIdx.x * 64;
    const int w = tid >> 5, lane = tid & 31;
    const int wm = w & 1, wn = w >> 1;
    const int grp = lane >> 2, qid = lane & 3;
    const unsigned sbase = sptr(dyn);

    // async fill: h rows (contiguous) -> Ac/Ag, plus Wc2/Wg2 -> Bc/Bg
#pragma unroll
    for (int l = 0; l < 8; l++) {
        int i4 = tid + l * 256;              // 0..2047
        int m = i4 >> 5, ch = i4 & 31;
        unsigned dst = (ch < 16) ? (AcO + m * FP + ch * 4)
                                 : (AgO + m * FP + (ch - 16) * 4);
        cpa16(sbase + dst * 4, &g_h16[((size_t)(eBase + m)) * 128 + ch * 4]);
    }
#pragma unroll
    for (int l = 0; l < 8; l++) {
        int i4 = tid + l * 256;              // 0..2047
        int n_ = i4 >> 4, q_ = i4 & 15;
        int off = (q_ >> 2) * 2048 + n_ * 16 + (q_ & 3) * 4;
        unsigned d = (n_ * FP + (q_ >> 2) * 16 + (q_ & 3) * 4) * 4;
        cpa16(sbase + BcO * 4 + d, &g_w2ct[off]);
        cpa16(sbase + BgO * 4 + d, &g_w2gt[off]);
    }
    cpcommit();

    for (int f = tid; f < 448; f += 256) {
        int mm = f / 7, j = f % 7;
        sw7[mm][j] = smooth_weight[(size_t)d2u[eBase + mm] * 7 + j];
    }
    for (int f = tid; f < 896; f += 256) Wenv_s[f >> 7][f & 127] = W_env[f];

    cpwait0();
    __syncthreads();

    const unsigned aFragOff = ((lane & 7) + ((lane >> 3) & 1) * 8) * FP + ((lane >> 4) & 1) * 4;
    const unsigned bRow2 = ((wn * 32 + (lane & 7)) * FP + ((lane >> 3) & 1) * 4) * 4;

    // ---- stage A: core & gate GEMM, K=128 ----
    float accc[2][4][4], accg[2][4][4];
#pragma unroll
    for (int mi = 0; mi < 2; mi++)
#pragma unroll
        for (int ni = 0; ni < 4; ni++)
#pragma unroll
            for (int q = 0; q < 4; q++) { accc[mi][ni][q] = 0.f; accg[mi][ni][q] = 0.f; }
    {
        const unsigned aC = sbase + (AcO + wm * 32 * FP + aFragOff) * 4;
        const unsigned aG = sbase + (AgO + wm * 32 * FP + aFragOff) * 4;
        const unsigned bC = sbase + BcO * 4 + bRow2;
        const unsigned bG = sbase + BgO * 4 + bRow2;
#pragma unroll
        for (int k16 = 0; k16 < 8; k16++) {
            unsigned ac[2][4], ag[2][4], bc[4][2], bg[4][2];
#pragma unroll
            for (int mi = 0; mi < 2; mi++) {
                ldsm4(ac[mi], aC + (mi * 16 * FP + k16 * 8) * 4);
                ldsm4(ag[mi], aG + (mi * 16 * FP + k16 * 8) * 4);
            }
#pragma unroll
            for (int ni = 0; ni < 4; ni++) {
                ldsm2(bc[ni], bC + (ni * 8 * FP + k16 * 8) * 4);
                ldsm2(bg[ni], bG + (ni * 8 * FP + k16 * 8) * 4);
            }
#pragma unroll
            for (int mi = 0; mi < 2; mi++)
#pragma unroll
                for (int ni = 0; ni < 4; ni++) {
                    mma16(accc[mi][ni], ac[mi], bc[ni]);
                    mma16(accg[mi][ni], ag[mi], bg[ni]);
                }
        }
    }

    // ---- LN partial sums ----
#pragma unroll
    for (int mi = 0; mi < 2; mi++)
#pragma unroll
        for (int h = 0; h < 2; h++) {
            float sc = 0.f, sc2 = 0.f, sg = 0.f, sg2 = 0.f;
#pragma unroll
            for (int ni = 0; ni < 4; ni++) {
                float c0 = accc[mi][ni][2 * h], c1 = accc[mi][ni][2 * h + 1];
                float g0 = accg[mi][ni][2 * h], g1 = accg[mi][ni][2 * h + 1];
                sc += c0 + c1; sc2 += c0 * c0 + c1 * c1;
                sg += g0 + g1; sg2 += g0 * g0 + g1 * g1;
            }
#pragma unroll
            for (int off = 1; off < 4; off <<= 1) {
                sc  += __shfl_xor_sync(0xffffffffu, sc,  off, 4);
                sc2 += __shfl_xor_sync(0xffffffffu, sc2, off, 4);
                sg  += __shfl_xor_sync(0xffffffffu, sg,  off, 4);
                sg2 += __shfl_xor_sync(0xffffffffu, sg2, off, 4);
            }
            if (qid == 0) red[wm * 32 + mi * 16 + grp + 8 * h][wn] = make_float4(sc, sc2, sg, sg2);
        }
    __syncthreads();

    // prefetch We1 / We2 into Bc/Bg regions
#pragma unroll
    for (int l = 0; l < 8; l++) {
        int i4 = tid + l * 256;
        int n_ = i4 >> 4, q_ = i4 & 15;
        int off = (q_ >> 2) * 2048 + n_ * 16 + (q_ & 3) * 4;
        unsigned d = (n_ * FP + (q_ >> 2) * 16 + (q_ & 3) * 4) * 4;
        cpa16(sbase + BcO * 4 + d, &g_we1t[off]);
        cpa16(sbase + BgO * 4 + d, &g_we2t[off]);
    }
    cpcommit();

    // ---- LN epilogue: nl -> t1 (Ac region), msg -> g_msg16 ----
#pragma unroll
    for (int mi = 0; mi < 2; mi++)
#pragma unroll
        for (int h = 0; h < 2; h++) {
            int rloc = wm * 32 + mi * 16 + grp + 8 * h;
            float4 p0 = red[rloc][0], p1 = red[rloc][1], p2 = red[rloc][2], p3 = red[rloc][3];
            float sc = p0.x + p1.x + p2.x + p3.x;
            float sc2 = p0.y + p1.y + p2.y + p3.y;
            float sg = p0.z + p1.z + p2.z + p3.z;
            float sg2 = p0.w + p1.w + p2.w + p3.w;
            float mc = sc * (1.f / 128.f);
            float vc = fmaxf(sc2 * (1.f / 128.f) - mc * mc, 0.f);
            float rc = rsqrtf(vc + 1e-5f);
            float mg = sg * (1.f / 128.f);
            float vg = fmaxf(sg2 * (1.f / 128.f) - mg * mg, 0.f);
            float rg = rsqrtf(vg + 1e-5f);

            float s0 = sw7[rloc][0], s1 = sw7[rloc][1], s2 = sw7[rloc][2], s3 = sw7[rloc][3];
            float s4 = sw7[rloc][4], s5 = sw7[rloc][5], s6 = sw7[rloc][6];
            unsigned* mp = g_msg16 + (size_t)(eBase + rloc) * 64;
#pragma unroll
            for (int ni = 0; ni < 4; ni++) {
                int c = wn * 32 + ni * 8 + qid * 2;
                float hc0 = (accc[mi][ni][2 * h] - mc) * rc * __ldg(&lncg[c]) + __ldg(&lncb[c]);
                float hg0 = (accg[mi][ni][2 * h] - mg) * rg * __ldg(&lngg[c]) + __ldg(&lngb[c]);
                float nl0 = siluf_(hc0) * sigmoidf_(hg0);
                float hc1 = (accc[mi][ni][2 * h + 1] - mc) * rc * __ldg(&lncg[c + 1]) + __ldg(&lncb[c + 1]);
                float hg1 = (accg[mi][ni][2 * h + 1] - mg) * rg * __ldg(&lngg[c + 1]) + __ldg(&lngb[c + 1]);
                float nl1 = siluf_(hc1) * sigmoidf_(hg1);
                dyn[AcO + rloc * FP + (c >> 1)] = pack2(nl0, nl1);
                float sw0 = s0 * Wenv_s[0][c] + s1 * Wenv_s[1][c] + s2 * Wenv_s[2][c]
                          + s3 * Wenv_s[3][c] + s4 * Wenv_s[4][c] + s5 * Wenv_s[5][c]
                          + s6 * Wenv_s[6][c];
                float sw1 = s0 * Wenv_s[0][c + 1] + s1 * Wenv_s[1][c + 1] + s2 * Wenv_s[2][c + 1]
                          + s3 * Wenv_s[3][c + 1] + s4 * Wenv_s[4][c + 1] + s5 * Wenv_s[5][c + 1]
                          + s6 * Wenv_s[6][c + 1];
                mp[c >> 1] = pack2(nl0 * sw0, nl1 * sw1);
            }
        }
    cpwait0();
    __syncthreads();

    // ---- stage B: silu(t1 @ We1) -> t2 (Ag region) ----
    float acc1[2][4][4];
#pragma unroll
    for (int mi = 0; mi < 2; mi++)
#pragma unroll
        for (int ni = 0; ni < 4; ni++)
#pragma unroll
            for (int q = 0; q < 4; q++) acc1[mi][ni][q] = 0.f;
    {
        const unsigned aT = sbase + (AcO + wm * 32 * FP + aFragOff) * 4;
        const unsigned bW = sbase + BcO * 4 + bRow2;
#pragma unroll
        for (int k16 = 0; k16 < 8; k16++) {
            unsigned a[2][4], b[4][2];
#pragma unroll
            for (int mi = 0; mi < 2; mi++) ldsm4(a[mi], aT + (mi * 16 * FP + k16 * 8) * 4);
#pragma unroll
            for (int ni = 0; ni < 4; ni++) ldsm2(b[ni], bW + (ni * 8 * FP + k16 * 8) * 4);
#pragma unroll
            for (int mi = 0; mi < 2; mi++)
#pragma unroll
                for (int ni = 0; ni < 4; ni++) mma16(acc1[mi][ni], a[mi], b[ni]);
        }
    }
#pragma unroll
    for (int mi = 0; mi < 2; mi++)
#pragma unroll
        for (int h = 0; h < 2; h++) {
            int rloc = wm * 32 + mi * 16 + grp + 8 * h;
#pragma unroll
            for (int ni = 0; ni < 4; ni++) {
                int c = wn * 32 + ni * 8 + qid * 2;
                dyn[AgO + rloc * FP + (c >> 1)] =
                    pack2(siluf_(acc1[mi][ni][2 * h]), siluf_(acc1[mi][ni][2 * h + 1]));
            }
        }
    __syncthreads();

    // ---- stage C: t2 @ We2 -> g_ded16 ----
    float acc2[2][4][4];
#pragma unroll
    for (int mi = 0; mi < 2; mi++)
#pragma unroll
        for (int ni = 0; ni < 4; ni++)
#pragma unroll
            for (int q = 0; q < 4; q++) acc2[mi][ni][q] = 0.f;
    {
        const unsigned aT = sbase + (AgO + wm * 32 * FP + aFragOff) * 4;
        const unsigned bW = sbase + BgO * 4 + bRow2;
#pragma unroll
        for (int k16 = 0; k16 < 8; k16++) {
            unsigned a[2][4], b[4][2];
#pragma unroll
            for (int mi = 0; mi < 2; mi++) ldsm4(a[mi], aT + (mi * 16 * FP + k16 * 8) * 4);
#pragma unroll
            for (int ni = 0; ni < 4; ni++) ldsm2(b[ni], bW + (ni * 8 * FP + k16 * 8) * 4);
#pragma unroll
            for (int mi = 0; mi < 2; mi++)
#pragma unroll
                for (int ni = 0; ni < 4; ni++) mma16(acc2[mi][ni], a[mi], b[ni]);
        }
    }
#pragma unroll
    for (int mi = 0; mi < 2; mi++)
#pragma unroll
        for (int h = 0; h < 2; h++) {
            int rloc = wm * 32 + mi * 16 + grp + 8 * h;
            unsigned* dp = g_ded16 + (size_t)(eBase + rloc) * 64;
#pragma unroll
            for (int ni = 0; ni < 4; ni++) {
                int c = wn * 32 + ni * 8 + qid * 2;
                dp[c >> 1] = pack2(acc2[mi][ni][2 * h], acc2[mi][ni][2 * h + 1]);
            }
        }
}

// ============ k_node_fused: CSR gather (smem) + 2-stage node FFN + residual ============
__global__ __launch_bounds__(256) void k_node_fused(
    const float* __restrict__ node_feat, const float* __restrict__ node_res_w,
    float* __restrict__ out_node)
{
    __shared__ __align__(16) unsigned As[64 * 68];
    __shared__ __align__(16) unsigned Bs[128 * 20];
    __shared__ __align__(16) unsigned t1[64 * 68];

    const int tid = threadIdx.x;
    const int nBase = blockIdx.x * 64;
    const int w = tid >> 5, lane = tid & 31;
    const int wm = w & 1, wn = w >> 1;
    const int grp = lane >> 2, qid = lane & 3;

    for (int s = 0; s < 8; s++) {
        int m = w * 8 + s;
        int node = nBase + m;
        float4 acc = make_float4(0.f, 0.f, 0.f, 0.f);
        if (node < NN) {
            int b = g_csr_off[node], e2 = g_csr_off[node + 1];
            int j = b;
            for (; j + 1 < e2; j += 2) {
                int ed0 = g_csr_edges[j], ed1 = g_csr_edges[j + 1];
                uint2 v0 = *(const uint2*)&g_msg16[(size_t)ed0 * 64 + lane * 2];
                uint2 v1 = *(const uint2*)&g_msg16[(size_t)ed1 * 64 + lane * 2];
                float2 a0 = unpack2(v0.x), b0 = unpack2(v0.y);
                float2 a1 = unpack2(v1.x), b1 = unpack2(v1.y);
                acc.x += a0.x + a1.x; acc.y += a0.y + a1.y;
                acc.z += b0.x + b1.x; acc.w += b0.y + b1.y;
            }
            if (j < e2) {
                int ed = g_csr_edges[j];
                uint2 v = *(const uint2*)&g_msg16[(size_t)ed * 64 + lane * 2];
                float2 a = unpack2(v.x), bb = unpack2(v.y);
                acc.x += a.x; acc.y += a.y; acc.z += bb.x; acc.w += bb.y;
            }
        }
        *(uint2*)&As[m * 68 + lane * 2] = make_uint2(pack2(acc.x, acc.y), pack2(acc.z, acc.w));
    }
    __syncthreads();

    const int aRow = wm * 32 + (lane & 7) + ((lane >> 3) & 1) * 8;
    const int aCol = ((lane >> 4) & 1) * 4;
    const unsigned aBase = sptr(As) + (aRow * 68 + aCol) * 4;
    const unsigned tBase = sptr(t1) + (aRow * 68 + aCol) * 4;
    const unsigned bBase = sptr(Bs) + ((wn * 32 + (lane & 7)) * 20 + ((lane >> 3) & 1) * 4) * 4;

    float acc[2][4][4];
#pragma unroll
    for (int mi = 0; mi < 2; mi++)
#pragma unroll
        for (int ni = 0; ni < 4; ni++)
#pragma unroll
            for (int q = 0; q < 4; q++) acc[mi][ni][q] = 0.f;

    for (int kt = 0; kt < 4; kt++) {
        {
            const uint4* src = (const uint4*)&g_wn1t[kt * 2048];
#pragma unroll
            for (int l = 0; l < 2; l++) {
                int i4 = tid + l * 256;
                int n = i4 >> 2, wq = (i4 & 3) * 4;
                *(uint4*)&Bs[n * 20 + wq] = src[i4];
            }
        }
        __syncthreads();
#pragma unroll
        for (int k16 = 0; k16 < 2; k16++) {
            unsigned a[2][4], b[4][2];
#pragma unroll
            for (int mi = 0; mi < 2; mi++)
                ldsm4(a[mi], aBase + (mi * 16 * 68 + kt * 16 + k16 * 8) * 4);
#pragma unroll
            for (int ni = 0; ni < 4; ni++) ldsm2(b[ni], bBase + (ni * 8 * 20 + k16 * 8) * 4);
#pragma unroll
            for (int mi = 0; mi < 2; mi++)
#pragma unroll
                for (int ni = 0; ni < 4; ni++) mma16(acc[mi][ni], a[mi], b[ni]);
        }
        __syncthreads();
    }
#pragma unroll
    for (int mi = 0; mi < 2; mi++)
#pragma unroll
        for (int h = 0; h < 2; h++) {
            int r = wm * 32 + mi * 16 + grp + 8 * h;
#pragma unroll
            for (int ni = 0; ni < 4; ni++) {
                int c = wn * 32 + ni * 8 + qid * 2;
                t1[r * 68 + (c >> 1)] = pack2(siluf_(acc[mi][ni][2 * h]), siluf_(acc[mi][ni][2 * h + 1]));
            }
        }
    __syncthreads();

    float acc2[2][4][4];
#pragma unroll
    for (int mi = 0; mi < 2; mi++)
#pragma unroll
        for (int ni = 0; ni < 4; ni++)
#pragma unroll
            for (int q = 0; q < 4; q++) acc2[mi][ni][q] = 0.f;

    for (int kt = 0; kt < 4; kt++) {
        {
            const uint4* src = (const uint4*)&g_wn2t[kt * 2048];
#pragma unroll
            for (int l = 0; l < 2; l++) {
                int i4 = tid + l * 256;
                int n = i4 >> 2, wq = (i4 & 3) * 4;
                *(uint4*)&Bs[n * 20 + wq] = src[i4];
            }
        }
        __syncthreads();
#pragma unroll
        for (int k16 = 0; k16 < 2; k16++) {
            unsigned a[2][4], b[4][2];
#pragma unroll
            for (int mi = 0; mi < 2; mi++)
                ldsm4(a[mi], tBase + (mi * 16 * 68 + kt * 16 + k16 * 8) * 4);
#pragma unroll
            for (int ni = 0; ni < 4; ni++) ldsm2(b[ni], bBase + (ni * 8 * 20 + k16 * 8) * 4);
#pragma unroll
            for (int mi = 0; mi < 2; mi++)
#pragma unroll
                for (int ni = 0; ni < 4; ni++) mma16(acc2[mi][ni], a[mi], b[ni]);
        }
        __syncthreads();
    }

#pragma unroll
    for (int mi = 0; mi < 2; mi++)
#pragma unroll
        for (int h = 0; h < 2; h++) {
            int row = nBase + wm * 32 + mi * 16 + grp + 8 * h;
            if (row >= NN) continue;
            const float* nf = node_feat + ((size_t)row << 7);
            float* op = out_node + ((size_t)row << 7);
#pragma unroll
            for (int ni = 0; ni < 4; ni++) {
                int c = wn * 32 + ni * 8 + qid * 2;
                float o0 = acc2[mi][ni][2 * h]     + __ldg(&node_res_w[c])     * nf[c];
                float o1 = acc2[mi][ni][2 * h + 1] + __ldg(&node_res_w[c + 1]) * nf[c + 1];
                *(float2*)(op + c) = make_float2(o0, o1);
            }
        }
}

// ============ edge output = (ded[u]+ded[u+EU])/2 + res*edge_feat ============
__global__ void k_edge_final(const float* __restrict__ edge_feat,
                             const float* __restrict__ edge_res_w,
                             float* __restrict__ out_edge)
{
    size_t i = (size_t)blockIdx.x * blockDim.x + threadIdx.x;
    const size_t total = (size_t)EUN * 32;
    if (i >= total) return;
    size_t u = i >> 5;
    int cw = (int)(i & 31);
    uint2 da = *(const uint2*)&g_ded16[u * 64 + cw * 2];
    uint2 db = *(const uint2*)&g_ded16[(u + EUN) * 64 + cw * 2];
    float2 a0 = unpack2(da.x), a1 = unpack2(da.y);
    float2 b0 = unpack2(db.x), b1 = unpack2(db.y);
    float4 ef = *(const float4*)&edge_feat[u * 128 + cw * 4];
    float4 rw = *(const float4*)&edge_res_w[cw * 4];
    float4 o;
    o.x = (a0.x + b0.x) * 0.5f + rw.x * ef.x;
    o.y = (a0.y + b0.y) * 0.5f + rw.y * ef.y;
    o.z = (a1.x + b1.x) * 0.5f + rw.z * ef.z;
    o.w = (a1.y + b1.y) * 0.5f + rw.w * ef.w;
    *(float4*)&out_edge[u * 128 + cw * 4] = o;
}

// ---------------- launch ----------------
extern "C" void kernel_launch(void* const* d_in, const int* in_sizes, int n_in,
                              void* d_out, int out_size)
{
    (void)in_sizes; (void)n_in; (void)out_size;
    const float* node_feat     = (const float*)d_in[0];
    const float* edge_feat     = (const float*)d_in[1];
    const float* smooth_weight = (const float*)d_in[2];
    const int*   source_index  = (const int*)d_in[3];
    const int*   target_index  = (const int*)d_in[4];
    const int*   d2u           = (const int*)d_in[5];
    const float* W_env         = (const float*)d_in[6];
    const float* Wc1           = (const float*)d_in[7];
    const float* Wc2           = (const float*)d_in[8];
    const float* Wg1           = (const float*)d_in[9];
    const float* Wg2           = (const float*)d_in[10];
    const float* ln_c_g        = (const float*)d_in[11];
    const float* ln_c_b        = (const float*)d_in[12];
    const float* ln_g_g        = (const float*)d_in[13];
    const float* ln_g_b        = (const float*)d_in[14];
    const float* Wn1           = (const float*)d_in[15];
    const float* Wn2           = (const float*)d_in[16];
    const float* We1           = (const float*)d_in[17];
    const float* We2           = (const float*)d_in[18];
    const float* node_res_w    = (const float*)d_in[19];
    const float* edge_res_w    = (const float*)d_in[20];

    float* out_node = (float*)d_out;
    float* out_edge = out_node + (size_t)NN * 128;

    cudaFuncSetAttribute(k_mega, cudaFuncAttributeMaxDynamicSharedMemorySize, MEGA_DYN);
    cudaFuncSetAttribute(k_pre1, cudaFuncAttributeMaxDynamicSharedMemorySize, PRE1_DYN);

    const int NPART = (NN + 255) / 256;

    k_prepA<<<(PREPA_ITEMS + 255) / 256, 256>>>(Wc1, Wg1, Wc2, Wg2, We1, We2, Wn1, Wn2,
                                                edge_feat, node_feat);
    k_pre1<<<PE_BLKS + 2 * PN_BLKS, 512, PRE1_DYN>>>();
    k_h<<<(int)(((size_t)EDN * 32 + 255) / 256), 256>>>(target_index, source_index, d2u);

    k_mega<<<EDN / 64, 256, MEGA_DYN>>>(d2u, ln_c_g, ln_c_b, ln_g_g, ln_g_b,
                                        smooth_weight, W_env);

    k_hist<<<(EDN + 255) / 256, 256>>>(target_index);
    k_scan_part<<<NPART, 256>>>();
    k_scan_top<<<1, 256>>>(NPART);
    k_scan_apply<<<NPART, 256>>>();
    k_scatter<<<(EDN + 255) / 256, 256>>>(target_index);

    k_node_fused<<<(NN + 63) / 64, 256>>>(node_feat, node_res_w, out_node);

    k_edge_final<<<((int)((size_t)EUN * 32) + 255) / 256, 256>>>(edge_feat, edge_res_w, out_edge);
}

// round 13
// speedup vs baseline: 1.7500x; 1.0825x over previous
#include <cuda_runtime.h>
#include <cuda_fp16.h>

#define NN  50000
#define EUN 200000
#define EDN 400000

// ---------------- scratch (device globals; no allocation) ----------------
__device__ __align__(16) unsigned g_ef16[EUN * 64];   // edge_feat fp16
__device__ __align__(16) unsigned g_nf16[NN * 64];    // node_feat fp16
__device__ __align__(16) unsigned g_msg16[EDN * 64];  // envelope-scaled messages fp16
// GEMM1 partials, fp16 packed: [row][128 words] (256 halves)
__device__ __align__(16) unsigned g_pe16[(size_t)EUN * 128];
__device__ __align__(16) unsigned g_pt16[(size_t)NN * 128];
__device__ __align__(16) unsigned g_ps16[(size_t)NN * 128];
// h = silu(pe+pt+ps) per directed edge, fp16 packed [e][128 words]
__device__ __align__(16) unsigned g_h16[(size_t)EDN * 128];
// CSR over target_index
__device__ int g_csr_cnt[NN];
__device__ int g_csr_off[NN + 1];
__device__ int g_csr_cur[NN];
__device__ int g_csr_edges[EDN];
__device__ int g_part[256];
__device__ int g_pbase[256];

// pre-transposed fp16 weights, tile-blocked: [ktile32][n][16 words]
__device__ __align__(16) unsigned g_w1t[12 * 256 * 16];
__device__ __align__(16) unsigned g_w2ct[4 * 128 * 16];
__device__ __align__(16) unsigned g_w2gt[4 * 128 * 16];
__device__ __align__(16) unsigned g_we1t[4 * 128 * 16];
__device__ __align__(16) unsigned g_we2t[4 * 128 * 16];
__device__ __align__(16) unsigned g_wn1t[4 * 128 * 16];
__device__ __align__(16) unsigned g_wn2t[4 * 128 * 16];

__device__ __forceinline__ float tanhf_(float x) {
    float y;
    asm("tanh.approx.f32 %0, %1;" : "=f"(y) : "f"(x));
    return y;
}
__device__ __forceinline__ float sigmoidf_(float x) {
    return 0.5f * tanhf_(0.5f * x) + 0.5f;
}
__device__ __forceinline__ float siluf_(float x) { return x * sigmoidf_(x); }

__device__ __forceinline__ unsigned pack2(float x, float y) {
    __half2 h = __floats2half2_rn(x, y);
    return *reinterpret_cast<unsigned*>(&h);
}
__device__ __forceinline__ float2 unpack2(unsigned u) {
    __half2 h = *reinterpret_cast<__half2*>(&u);
    return __half22float2(h);
}
__device__ __forceinline__ unsigned sptr(const void* p) {
    return (unsigned)__cvta_generic_to_shared(p);
}
__device__ __forceinline__ void ldsm4(unsigned* r, unsigned a) {
    asm volatile("ldmatrix.sync.aligned.m8n8.x4.shared.b16 {%0,%1,%2,%3}, [%4];"
        : "=r"(r[0]), "=r"(r[1]), "=r"(r[2]), "=r"(r[3]) : "r"(a));
}
__device__ __forceinline__ void ldsm2(unsigned* r, unsigned a) {
    asm volatile("ldmatrix.sync.aligned.m8n8.x2.shared.b16 {%0,%1}, [%2];"
        : "=r"(r[0]), "=r"(r[1]) : "r"(a));
}
__device__ __forceinline__ void mma16(float* d, const unsigned* a, const unsigned* b) {
    asm volatile(
        "mma.sync.aligned.m16n8k16.row.col.f32.f16.f16.f32 "
        "{%0,%1,%2,%3}, {%4,%5,%6,%7}, {%8,%9}, {%0,%1,%2,%3};"
        : "+f"(d[0]), "+f"(d[1]), "+f"(d[2]), "+f"(d[3])
        : "r"(a[0]), "r"(a[1]), "r"(a[2]), "r"(a[3]), "r"(b[0]), "r"(b[1]));
}
__device__ __forceinline__ void cpa16(unsigned dst, const void* src) {
    asm volatile("cp.async.cg.shared.global [%0], [%1], 16;"
        :: "r"(dst), "l"(__cvta_generic_to_global(src)));
}
__device__ __forceinline__ void cpcommit() { asm volatile("cp.async.commit_group;"); }
__device__ __forceinline__ void cpwait0() { asm volatile("cp.async.wait_group 0;"); }
__device__ __forceinline__ void cpwait1() { asm volatile("cp.async.wait_group 1;"); }

// ---------------- k_prepA: weights + features fp16 + csr zero (merged) ----------------
__global__ void k_prepA(const float* __restrict__ Wc1, const float* __restrict__ Wg1,
                        const float* __restrict__ Wc2, const float* __restrict__ Wg2,
                        const float* __restrict__ We1, const float* __restrict__ We2,
                        const float* __restrict__ Wn1, const float* __restrict__ Wn2,
                        const float* __restrict__ edge_feat, const float* __restrict__ node_feat)
{
    int i = blockIdx.x * blockDim.x + threadIdx.x;
    if (i < 12 * 256 * 16) {
        int kt = i >> 12;
        int r = i & 4095;
        int n = r >> 4, kpl = r & 15;
        int kp = kt * 16 + kpl;
        const float* W = (n < 128) ? Wc1 : Wg1;
        int c = n & 127;
        g_w1t[i] = pack2(W[(size_t)(2 * kp) * 128 + c], W[(size_t)(2 * kp + 1) * 128 + c]);
        return;
    }
    int j = i - 12 * 256 * 16;
    if (j < 6 * 8192) {
        int mtx = j >> 13;
        int r = j & 8191;
        int kt = r >> 11, rr = r & 2047;
        int n = rr >> 4, kpl = rr & 15;
        int kp = kt * 16 + kpl;
        const float* W; unsigned* O;
        switch (mtx) {
            case 0: W = Wc2; O = g_w2ct; break;
            case 1: W = Wg2; O = g_w2gt; break;
            case 2: W = We1; O = g_we1t; break;
            case 3: W = We2; O = g_we2t; break;
            case 4: W = Wn1; O = g_wn1t; break;
            default: W = Wn2; O = g_wn2t; break;
        }
        O[r] = pack2(W[(size_t)(2 * kp) * 128 + n], W[(size_t)(2 * kp + 1) * 128 + n]);
        return;
    }
    int k = j - 6 * 8192;
    if (k < EUN * 64) {
        g_ef16[k] = pack2(edge_feat[2 * (size_t)k], edge_feat[2 * (size_t)k + 1]);
        return;
    }
    int m = k - EUN * 64;
    if (m < NN * 64) {
        g_nf16[m] = pack2(node_feat[2 * (size_t)m], node_feat[2 * (size_t)m + 1]);
        return;
    }
    int z = m - NN * 64;
    if (z < NN) g_csr_cnt[z] = 0;
}
#define PREPA_ITEMS (12 * 256 * 16 + 6 * 8192 + EUN * 64 + NN * 64 + NN)

// ---------------- k_pre1: GEMM1 partials (fp16 out) ----------
#define PE_BLKS ((EUN + 127) / 128)
#define PN_BLKS ((NN + 127) / 128)
#define PRE1_DYN ((2 * 2560 + 2 * 5120) * 4)
__global__ __launch_bounds__(512) void k_pre1()
{
    extern __shared__ __align__(16) unsigned dyn[];
    const int tid = threadIdx.x;
    const unsigned sbase = sptr(dyn);

    int bid = blockIdx.x;
    int rBase, rowsMax, ktbase;
    const unsigned* feat;
    unsigned* out;
    if (bid < PE_BLKS)                { rBase = bid * 128;                       rowsMax = EUN; ktbase = 0; feat = g_ef16; out = g_pe16; }
    else if (bid < PE_BLKS + PN_BLKS) { rBase = (bid - PE_BLKS) * 128;           rowsMax = NN;  ktbase = 4; feat = g_nf16; out = g_pt16; }
    else                              { rBase = (bid - PE_BLKS - PN_BLKS) * 128; rowsMax = NN;  ktbase = 8; feat = g_nf16; out = g_ps16; }

    const int w = tid >> 5, lane = tid & 31;
    const int wm = w & 3, wn = w >> 2;
    const int grp = lane >> 2, qid = lane & 3;

    const int afm = tid >> 2, afc = tid & 3;
    int arow = rBase + afm;
    if (arow >= rowsMax) arow = rowsMax - 1;
    const unsigned* arowp = feat + (size_t)arow * 64 + afc * 4;

#define P1_FILL_A(kt, nb) \
    cpa16(sbase + ((nb) * 2560 + afm * 20 + afc * 4) * 4, arowp + (kt) * 16)
#define P1_FILL_B(kt, nb) do { \
    _Pragma("unroll") \
    for (int l = 0; l < 2; l++) { \
        int i4 = tid + l * 512; \
        int n_ = i4 >> 2, q_ = i4 & 3; \
        cpa16(sbase + (5120 + (nb) * 5120 + n_ * 20 + q_ * 4) * 4, \
              &g_w1t[(ktbase + (kt)) * 4096 + n_ * 16 + q_ * 4]); \
    } } while (0)

    P1_FILL_A(0, 0); P1_FILL_B(0, 0); cpcommit();

    const unsigned aOff = ((wm * 32 + (lane & 7) + ((lane >> 3) & 1) * 8) * 20 + ((lane >> 4) & 1) * 4) * 4;
    const unsigned bOff = ((wn * 64 + (lane & 7)) * 20 + ((lane >> 3) & 1) * 4) * 4;

    float acc[2][8][4];
#pragma unroll
    for (int mi = 0; mi < 2; mi++)
#pragma unroll
        for (int ni = 0; ni < 8; ni++)
#pragma unroll
            for (int q = 0; q < 4; q++) acc[mi][ni][q] = 0.f;

    for (int kt = 0; kt < 4; kt++) {
        if (kt < 3) {
            P1_FILL_A(kt + 1, (kt + 1) & 1);
            P1_FILL_B(kt + 1, (kt + 1) & 1);
            cpcommit();
            cpwait1();
        } else {
            cpwait0();
        }
        __syncthreads();
        const unsigned aB = sbase + ((kt & 1) * 2560) * 4 + aOff;
        const unsigned bB = sbase + (5120 + (kt & 1) * 5120) * 4 + bOff;
#pragma unroll
        for (int k16 = 0; k16 < 2; k16++) {
            unsigned a[2][4], b[8][2];
#pragma unroll
            for (int mi = 0; mi < 2; mi++) ldsm4(a[mi], aB + (mi * 16 * 20 + k16 * 8) * 4);
#pragma unroll
            for (int ni = 0; ni < 8; ni++) ldsm2(b[ni], bB + (ni * 8 * 20 + k16 * 8) * 4);
#pragma unroll
            for (int mi = 0; mi < 2; mi++)
#pragma unroll
                for (int ni = 0; ni < 8; ni++) mma16(acc[mi][ni], a[mi], b[ni]);
        }
        __syncthreads();
    }

#pragma unroll
    for (int mi = 0; mi < 2; mi++)
#pragma unroll
        for (int h = 0; h < 2; h++) {
            int grow = rBase + wm * 32 + mi * 16 + grp + 8 * h;
            if (grow >= rowsMax) continue;
            unsigned* op = out + (size_t)grow * 128;
#pragma unroll
            for (int ni = 0; ni < 8; ni++) {
                int c = wn * 64 + ni * 8 + qid * 2;
                op[c >> 1] = pack2(acc[mi][ni][2 * h], acc[mi][ni][2 * h + 1]);
            }
        }
}

// ---------------- k_h: high-occupancy streaming  h = silu(pe[u]+pt[tgt]+ps[src]) ------
__device__ __forceinline__ unsigned hss(unsigned a, unsigned b, unsigned c) {
    float2 fa = unpack2(a), fb = unpack2(b), fc = unpack2(c);
    return pack2(siluf_(fa.x + fb.x + fc.x), siluf_(fa.y + fb.y + fc.y));
}
__global__ __launch_bounds__(256) void k_h(
    const int* __restrict__ tgt_i, const int* __restrict__ src_i, const int* __restrict__ d2u)
{
    size_t i = (size_t)blockIdx.x * 256 + threadIdx.x;
    if (i >= (size_t)EDN * 32) return;
    int e = (int)(i >> 5), ch = (int)(i & 31);
    int u = __ldg(&d2u[e]);
    int t = __ldg(&tgt_i[e]);
    int s = __ldg(&src_i[e]);
    uint4 A = *(const uint4*)&g_pe16[(size_t)u * 128 + ch * 4];
    uint4 B = *(const uint4*)&g_pt16[(size_t)t * 128 + ch * 4];
    uint4 C = *(const uint4*)&g_ps16[(size_t)s * 128 + ch * 4];
    uint4 O;
    O.x = hss(A.x, B.x, C.x);
    O.y = hss(A.y, B.y, C.y);
    O.z = hss(A.z, B.z, C.z);
    O.w = hss(A.w, B.w, C.w);
    *(uint4*)&g_h16[i * 4] = O;
}

// ---------------- CSR build ----------------
__global__ void k_hist(const int* __restrict__ tgt_i) {
    int i = blockIdx.x * blockDim.x + threadIdx.x;
    if (i < EDN) atomicAdd(&g_csr_cnt[tgt_i[i]], 1);
}
__global__ void k_scan_part() {
    __shared__ int sm[256];
    int t = threadIdx.x;
    int i = blockIdx.x * 256 + t;
    sm[t] = (i < NN) ? g_csr_cnt[i] : 0;
    __syncthreads();
#pragma unroll
    for (int off = 128; off > 0; off >>= 1) {
        if (t < off) sm[t] += sm[t + off];
        __syncthreads();
    }
    if (t == 0) g_part[blockIdx.x] = sm[0];
}
__global__ void k_scan_top(int nparts) {
    __shared__ int sm[256];
    int t = threadIdx.x;
    sm[t] = (t < nparts) ? g_part[t] : 0;
    __syncthreads();
#pragma unroll
    for (int off = 1; off < 256; off <<= 1) {
        int v = (t >= off) ? sm[t - off] : 0;
        __syncthreads();
        sm[t] += v;
        __syncthreads();
    }
    if (t < nparts) g_pbase[t] = (t == 0) ? 0 : sm[t - 1];
    if (t == 0) g_csr_off[NN] = EDN;
}
__global__ void k_scan_apply() {
    __shared__ int sm[256];
    int t = threadIdx.x;
    int i = blockIdx.x * 256 + t;
    int v = (i < NN) ? g_csr_cnt[i] : 0;
    sm[t] = v;
    __syncthreads();
#pragma unroll
    for (int off = 1; off < 256; off <<= 1) {
        int u = (t >= off) ? sm[t - off] : 0;
        __syncthreads();
        sm[t] += u;
        __syncthreads();
    }
    if (i < NN) {
        int excl = sm[t] - v + g_pbase[blockIdx.x];
        g_csr_off[i] = excl;
        g_csr_cur[i] = excl;
    }
}
__global__ void k_scatter(const int* __restrict__ tgt_i) {
    int i = blockIdx.x * blockDim.x + threadIdx.x;
    if (i < EDN) {
        int pos = atomicAdd(&g_csr_cur[tgt_i[i]], 1);
        g_csr_edges[pos] = i;
    }
}

// ============ k_mega: stages A-C + fused edge output. Pair-edge blocks. ============
// block b owns 32 undirected edges: rows 0-31 = directed [32b,32b+32),
// rows 32-63 = directed [EUN+32b, EUN+32b+32). u = 32b + (row&31).
// stage C epilogue: ded -> smem, average halves, + residual -> out_edge. No g_ded16.
#define FP 68
#define AcO 0
#define AgO 4352
#define BcO 8704
#define BgO 17408
#define MEGA_DYN ((BgO + 128 * FP) * 4)   // 104448 B
__global__ __launch_bounds__(256, 2) void k_mega(
    const float* __restrict__ lncg, const float* __restrict__ lncb,
    const float* __restrict__ lngg, const float* __restrict__ lngb,
    const float* __restrict__ smooth_weight, const float* __restrict__ W_env,
    const float* __restrict__ edge_feat, const float* __restrict__ edge_res_w,
    float* __restrict__ out_edge)
{
    extern __shared__ __align__(16) unsigned dyn[];
    __shared__ float Wenv_s[7][128];
    __shared__ float sw7[32][8];
    __shared__ float4 red[64][4];

    const int tid = threadIdx.x;
    const int uBase = blockIdx.x * 32;
    const int w = tid >> 5, lane = tid & 31;
    const int wm = w & 1, wn = w >> 1;
    const int grp = lane >> 2, qid = lane & 3;
    const unsigned sbase = sptr(dyn);

    // async fill: h rows -> Ac/Ag (rows 0-31 fwd edges, 32-63 rev edges), Wc2/Wg2 -> Bc/Bg
#pragma unroll
    for (int l = 0; l < 8; l++) {
        int i4 = tid + l * 256;              // 0..2047
        int m = i4 >> 5, ch = i4 & 31;
        size_t e = (m < 32) ? (size_t)(uBase + m) : (size_t)(EUN + uBase + m - 32);
        unsigned dst = (ch < 16) ? (AcO + m * FP + ch * 4)
                                 : (AgO + m * FP + (ch - 16) * 4);
        cpa16(sbase + dst * 4, &g_h16[e * 128 + ch * 4]);
    }
#pragma unroll
    for (int l = 0; l < 8; l++) {
        int i4 = tid + l * 256;
        int n_ = i4 >> 4, q_ = i4 & 15;
        int off = (q_ >> 2) * 2048 + n_ * 16 + (q_ & 3) * 4;
        unsigned d = (n_ * FP + (q_ >> 2) * 16 + (q_ & 3) * 4) * 4;
        cpa16(sbase + BcO * 4 + d, &g_w2ct[off]);
        cpa16(sbase + BgO * 4 + d, &g_w2gt[off]);
    }
    cpcommit();

    for (int f = tid; f < 224; f += 256) {
        int mm = f / 7, j = f % 7;
        sw7[mm][j] = smooth_weight[(size_t)(uBase + mm) * 7 + j];
    }
    for (int f = tid; f < 896; f += 256) Wenv_s[f >> 7][f & 127] = W_env[f];

    cpwait0();
    __syncthreads();

    const unsigned aFragOff = ((lane & 7) + ((lane >> 3) & 1) * 8) * FP + ((lane >> 4) & 1) * 4;
    const unsigned bRow2 = ((wn * 32 + (lane & 7)) * FP + ((lane >> 3) & 1) * 4) * 4;

    // ---- stage A: core & gate GEMM, K=128 ----
    float accc[2][4][4], accg[2][4][4];
#pragma unroll
    for (int mi = 0; mi < 2; mi++)
#pragma unroll
        for (int ni = 0; ni < 4; ni++)
#pragma unroll
            for (int q = 0; q < 4; q++) { accc[mi][ni][q] = 0.f; accg[mi][ni][q] = 0.f; }
    {
        const unsigned aC = sbase + (AcO + wm * 32 * FP + aFragOff) * 4;
        const unsigned aG = sbase + (AgO + wm * 32 * FP + aFragOff) * 4;
        const unsigned bC = sbase + BcO * 4 + bRow2;
        const unsigned bG = sbase + BgO * 4 + bRow2;
#pragma unroll
        for (int k16 = 0; k16 < 8; k16++) {
            unsigned ac[2][4], ag[2][4], bc[4][2], bg[4][2];
#pragma unroll
            for (int mi = 0; mi < 2; mi++) {
                ldsm4(ac[mi], aC + (mi * 16 * FP + k16 * 8) * 4);
                ldsm4(ag[mi], aG + (mi * 16 * FP + k16 * 8) * 4);
            }
#pragma unroll
            for (int ni = 0; ni < 4; ni++) {
                ldsm2(bc[ni], bC + (ni * 8 * FP + k16 * 8) * 4);
                ldsm2(bg[ni], bG + (ni * 8 * FP + k16 * 8) * 4);
            }
#pragma unroll
            for (int mi = 0; mi < 2; mi++)
#pragma unroll
                for (int ni = 0; ni < 4; ni++) {
                    mma16(accc[mi][ni], ac[mi], bc[ni]);
                    mma16(accg[mi][ni], ag[mi], bg[ni]);
                }
        }
    }

    // ---- LN partial sums ----
#pragma unroll
    for (int mi = 0; mi < 2; mi++)
#pragma unroll
        for (int h = 0; h < 2; h++) {
            float sc = 0.f, sc2 = 0.f, sg = 0.f, sg2 = 0.f;
#pragma unroll
            for (int ni = 0; ni < 4; ni++) {
                float c0 = accc[mi][ni][2 * h], c1 = accc[mi][ni][2 * h + 1];
                float g0 = accg[mi][ni][2 * h], g1 = accg[mi][ni][2 * h + 1];
                sc += c0 + c1; sc2 += c0 * c0 + c1 * c1;
                sg += g0 + g1; sg2 += g0 * g0 + g1 * g1;
            }
#pragma unroll
            for (int off = 1; off < 4; off <<= 1) {
                sc  += __shfl_xor_sync(0xffffffffu, sc,  off, 4);
                sc2 += __shfl_xor_sync(0xffffffffu, sc2, off, 4);
                sg  += __shfl_xor_sync(0xffffffffu, sg,  off, 4);
                sg2 += __shfl_xor_sync(0xffffffffu, sg2, off, 4);
            }
            if (qid == 0) red[wm * 32 + mi * 16 + grp + 8 * h][wn] = make_float4(sc, sc2, sg, sg2);
        }
    __syncthreads();

    // prefetch We1 / We2 into Bc/Bg regions
#pragma unroll
    for (int l = 0; l < 8; l++) {
        int i4 = tid + l * 256;
        int n_ = i4 >> 4, q_ = i4 & 15;
        int off = (q_ >> 2) * 2048 + n_ * 16 + (q_ & 3) * 4;
        unsigned d = (n_ * FP + (q_ >> 2) * 16 + (q_ & 3) * 4) * 4;
        cpa16(sbase + BcO * 4 + d, &g_we1t[off]);
        cpa16(sbase + BgO * 4 + d, &g_we2t[off]);
    }
    cpcommit();

    // ---- LN epilogue: nl -> t1 (Ac region), msg -> g_msg16 ----
#pragma unroll
    for (int mi = 0; mi < 2; mi++)
#pragma unroll
        for (int h = 0; h < 2; h++) {
            int rloc = wm * 32 + mi * 16 + grp + 8 * h;
            float4 p0 = red[rloc][0], p1 = red[rloc][1], p2 = red[rloc][2], p3 = red[rloc][3];
            float sc = p0.x + p1.x + p2.x + p3.x;
            float sc2 = p0.y + p1.y + p2.y + p3.y;
            float sg = p0.z + p1.z + p2.z + p3.z;
            float sg2 = p0.w + p1.w + p2.w + p3.w;
            float mc = sc * (1.f / 128.f);
            float vc = fmaxf(sc2 * (1.f / 128.f) - mc * mc, 0.f);
            float rc = rsqrtf(vc + 1e-5f);
            float mg = sg * (1.f / 128.f);
            float vg = fmaxf(sg2 * (1.f / 128.f) - mg * mg, 0.f);
            float rg = rsqrtf(vg + 1e-5f);

            int rr = rloc & 31;
            float s0 = sw7[rr][0], s1 = sw7[rr][1], s2 = sw7[rr][2], s3 = sw7[rr][3];
            float s4 = sw7[rr][4], s5 = sw7[rr][5], s6 = sw7[rr][6];
            size_t e = (rloc < 32) ? (size_t)(uBase + rloc) : (size_t)(EUN + uBase + rloc - 32);
            unsigned* mp = g_msg16 + e * 64;
#pragma unroll
            for (int ni = 0; ni < 4; ni++) {
                int c = wn * 32 + ni * 8 + qid * 2;
                float hc0 = (accc[mi][ni][2 * h] - mc) * rc * __ldg(&lncg[c]) + __ldg(&lncb[c]);
                float hg0 = (accg[mi][ni][2 * h] - mg) * rg * __ldg(&lngg[c]) + __ldg(&lngb[c]);
                float nl0 = siluf_(hc0) * sigmoidf_(hg0);
                float hc1 = (accc[mi][ni][2 * h + 1] - mc) * rc * __ldg(&lncg[c + 1]) + __ldg(&lncb[c + 1]);
                float hg1 = (accg[mi][ni][2 * h + 1] - mg) * rg * __ldg(&lngg[c + 1]) + __ldg(&lngb[c + 1]);
                float nl1 = siluf_(hc1) * sigmoidf_(hg1);
                dyn[AcO + rloc * FP + (c >> 1)] = pack2(nl0, nl1);
                float sw0 = s0 * Wenv_s[0][c] + s1 * Wenv_s[1][c] + s2 * Wenv_s[2][c]
                          + s3 * Wenv_s[3][c] + s4 * Wenv_s[4][c] + s5 * Wenv_s[5][c]
                          + s6 * Wenv_s[6][c];
                float sw1 = s0 * Wenv_s[0][c + 1] + s1 * Wenv_s[1][c + 1] + s2 * Wenv_s[2][c + 1]
                          + s3 * Wenv_s[3][c + 1] + s4 * Wenv_s[4][c + 1] + s5 * Wenv_s[5][c + 1]
                          + s6 * Wenv_s[6][c + 1];
                mp[c >> 1] = pack2(nl0 * sw0, nl1 * sw1);
            }
        }
    cpwait0();
    __syncthreads();

    // ---- stage B: silu(t1 @ We1) -> t2 (Ag region) ----
    float acc1[2][4][4];
#pragma unroll
    for (int mi = 0; mi < 2; mi++)
#pragma unroll
        for (int ni = 0; ni < 4; ni++)
#pragma unroll
            for (int q = 0; q < 4; q++) acc1[mi][ni][q] = 0.f;
    {
        const unsigned aT = sbase + (AcO + wm * 32 * FP + aFragOff) * 4;
        const unsigned bW = sbase + BcO * 4 + bRow2;
#pragma unroll
        for (int k16 = 0; k16 < 8; k16++) {
            unsigned a[2][4], b[4][2];
#pragma unroll
            for (int mi = 0; mi < 2; mi++) ldsm4(a[mi], aT + (mi * 16 * FP + k16 * 8) * 4);
#pragma unroll
            for (int ni = 0; ni < 4; ni++) ldsm2(b[ni], bW + (ni * 8 * FP + k16 * 8) * 4);
#pragma unroll
            for (int mi = 0; mi < 2; mi++)
#pragma unroll
                for (int ni = 0; ni < 4; ni++) mma16(acc1[mi][ni], a[mi], b[ni]);
        }
    }
#pragma unroll
    for (int mi = 0; mi < 2; mi++)
#pragma unroll
        for (int h = 0; h < 2; h++) {
            int rloc = wm * 32 + mi * 16 + grp + 8 * h;
#pragma unroll
            for (int ni = 0; ni < 4; ni++) {
                int c = wn * 32 + ni * 8 + qid * 2;
                dyn[AgO + rloc * FP + (c >> 1)] =
                    pack2(siluf_(acc1[mi][ni][2 * h]), siluf_(acc1[mi][ni][2 * h + 1]));
            }
        }
    __syncthreads();

    // ---- stage C: t2 @ We2 -> ded (smem, Ac region) ----
    float acc2[2][4][4];
#pragma unroll
    for (int mi = 0; mi < 2; mi++)
#pragma unroll
        for (int ni = 0; ni < 4; ni++)
#pragma unroll
            for (int q = 0; q < 4; q++) acc2[mi][ni][q] = 0.f;
    {
        const unsigned aT = sbase + (AgO + wm * 32 * FP + aFragOff) * 4;
        const unsigned bW = sbase + BgO * 4 + bRow2;
#pragma unroll
        for (int k16 = 0; k16 < 8; k16++) {
            unsigned a[2][4], b[4][2];
#pragma unroll
            for (int mi = 0; mi < 2; mi++) ldsm4(a[mi], aT + (mi * 16 * FP + k16 * 8) * 4);
#pragma unroll
            for (int ni = 0; ni < 4; ni++) ldsm2(b[ni], bW + (ni * 8 * FP + k16 * 8) * 4);
#pragma unroll
            for (int mi = 0; mi < 2; mi++)
#pragma unroll
                for (int ni = 0; ni < 4; ni++) mma16(acc2[mi][ni], a[mi], b[ni]);
        }
    }
#pragma unroll
    for (int mi = 0; mi < 2; mi++)
#pragma unroll
        for (int h = 0; h < 2; h++) {
            int rloc = wm * 32 + mi * 16 + grp + 8 * h;
#pragma unroll
            for (int ni = 0; ni < 4; ni++) {
                int c = wn * 32 + ni * 8 + qid * 2;
                dyn[AcO + rloc * FP + (c >> 1)] = pack2(acc2[mi][ni][2 * h], acc2[mi][ni][2 * h + 1]);
            }
        }
    __syncthreads();

    // ---- fused edge output: out_edge[u] = (ded_fwd + ded_rev)/2 + rw*ef ----
#pragma unroll
    for (int it = 0; it < 4; it++) {
        int f = tid + it * 256;        // 0..1023
        int row = f >> 5, cw = f & 31; // row 0..31, cw*4 = col
        uint2 da = *(uint2*)&dyn[AcO + row * FP + cw * 2];
        uint2 db = *(uint2*)&dyn[AcO + (row + 32) * FP + cw * 2];
        float2 a0 = unpack2(da.x), a1 = unpack2(da.y);
        float2 b0 = unpack2(db.x), b1 = unpack2(db.y);
        size_t u = (size_t)(uBase + row);
        float4 ef = *(const float4*)&edge_feat[u * 128 + cw * 4];
        float4 rw = *(const float4*)&edge_res_w[cw * 4];
        float4 o;
        o.x = (a0.x + b0.x) * 0.5f + rw.x * ef.x;
        o.y = (a0.y + b0.y) * 0.5f + rw.y * ef.y;
        o.z = (a1.x + b1.x) * 0.5f + rw.z * ef.z;
        o.w = (a1.y + b1.y) * 0.5f + rw.w * ef.w;
        *(float4*)&out_edge[u * 128 + cw * 4] = o;
    }
}

// ============ k_node_fused: CSR gather (smem) + 2-stage node FFN + residual ============
__global__ __launch_bounds__(256) void k_node_fused(
    const float* __restrict__ node_feat, const float* __restrict__ node_res_w,
    float* __restrict__ out_node)
{
    __shared__ __align__(16) unsigned As[64 * 68];
    __shared__ __align__(16) unsigned Bs[128 * 20];
    __shared__ __align__(16) unsigned t1[64 * 68];

    const int tid = threadIdx.x;
    const int nBase = blockIdx.x * 64;
    const int w = tid >> 5, lane = tid & 31;
    const int wm = w & 1, wn = w >> 1;
    const int grp = lane >> 2, qid = lane & 3;

    for (int s = 0; s < 8; s++) {
        int m = w * 8 + s;
        int node = nBase + m;
        float4 acc = make_float4(0.f, 0.f, 0.f, 0.f);
        if (node < NN) {
            int b = g_csr_off[node], e2 = g_csr_off[node + 1];
            int j = b;
            for (; j + 1 < e2; j += 2) {
                int ed0 = g_csr_edges[j], ed1 = g_csr_edges[j + 1];
                uint2 v0 = *(const uint2*)&g_msg16[(size_t)ed0 * 64 + lane * 2];
                uint2 v1 = *(const uint2*)&g_msg16[(size_t)ed1 * 64 + lane * 2];
                float2 a0 = unpack2(v0.x), b0 = unpack2(v0.y);
                float2 a1 = unpack2(v1.x), b1 = unpack2(v1.y);
                acc.x += a0.x + a1.x; acc.y += a0.y + a1.y;
                acc.z += b0.x + b1.x; acc.w += b0.y + b1.y;
            }
            if (j < e2) {
                int ed = g_csr_edges[j];
                uint2 v = *(const uint2*)&g_msg16[(size_t)ed * 64 + lane * 2];
                float2 a = unpack2(v.x), bb = unpack2(v.y);
                acc.x += a.x; acc.y += a.y; acc.z += bb.x; acc.w += bb.y;
            }
        }
        *(uint2*)&As[m * 68 + lane * 2] = make_uint2(pack2(acc.x, acc.y), pack2(acc.z, acc.w));
    }
    __syncthreads();

    const int aRow = wm * 32 + (lane & 7) + ((lane >> 3) & 1) * 8;
    const int aCol = ((lane >> 4) & 1) * 4;
    const unsigned aBase = sptr(As) + (aRow * 68 + aCol) * 4;
    const unsigned tBase = sptr(t1) + (aRow * 68 + aCol) * 4;
    const unsigned bBase = sptr(Bs) + ((wn * 32 + (lane & 7)) * 20 + ((lane >> 3) & 1) * 4) * 4;

    float acc[2][4][4];
#pragma unroll
    for (int mi = 0; mi < 2; mi++)
#pragma unroll
        for (int ni = 0; ni < 4; ni++)
#pragma unroll
            for (int q = 0; q < 4; q++) acc[mi][ni][q] = 0.f;

    for (int kt = 0; kt < 4; kt++) {
        {
            const uint4* src = (const uint4*)&g_wn1t[kt * 2048];
#pragma unroll
            for (int l = 0; l < 2; l++) {
                int i4 = tid + l * 256;
                int n = i4 >> 2, wq = (i4 & 3) * 4;
                *(uint4*)&Bs[n * 20 + wq] = src[i4];
            }
        }
        __syncthreads();
#pragma unroll
        for (int k16 = 0; k16 < 2; k16++) {
            unsigned a[2][4], b[4][2];
#pragma unroll
            for (int mi = 0; mi < 2; mi++)
                ldsm4(a[mi], aBase + (mi * 16 * 68 + kt * 16 + k16 * 8) * 4);
#pragma unroll
            for (int ni = 0; ni < 4; ni++) ldsm2(b[ni], bBase + (ni * 8 * 20 + k16 * 8) * 4);
#pragma unroll
            for (int mi = 0; mi < 2; mi++)
#pragma unroll
                for (int ni = 0; ni < 4; ni++) mma16(acc[mi][ni], a[mi], b[ni]);
        }
        __syncthreads();
    }
#pragma unroll
    for (int mi = 0; mi < 2; mi++)
#pragma unroll
        for (int h = 0; h < 2; h++) {
            int r = wm * 32 + mi * 16 + grp + 8 * h;
#pragma unroll
            for (int ni = 0; ni < 4; ni++) {
                int c = wn * 32 + ni * 8 + qid * 2;
                t1[r * 68 + (c >> 1)] = pack2(siluf_(acc[mi][ni][2 * h]), siluf_(acc[mi][ni][2 * h + 1]));
            }
        }
    __syncthreads();

    float acc2[2][4][4];
#pragma unroll
    for (int mi = 0; mi < 2; mi++)
#pragma unroll
        for (int ni = 0; ni < 4; ni++)
#pragma unroll
            for (int q = 0; q < 4; q++) acc2[mi][ni][q] = 0.f;

    for (int kt = 0; kt < 4; kt++) {
        {
            const uint4* src = (const uint4*)&g_wn2t[kt * 2048];
#pragma unroll
            for (int l = 0; l < 2; l++) {
                int i4 = tid + l * 256;
                int n = i4 >> 2, wq = (i4 & 3) * 4;
                *(uint4*)&Bs[n * 20 + wq] = src[i4];
            }
        }
        __syncthreads();
#pragma unroll
        for (int k16 = 0; k16 < 2; k16++) {
            unsigned a[2][4], b[4][2];
#pragma unroll
            for (int mi = 0; mi < 2; mi++)
                ldsm4(a[mi], tBase + (mi * 16 * 68 + kt * 16 + k16 * 8) * 4);
#pragma unroll
            for (int ni = 0; ni < 4; ni++) ldsm2(b[ni], bBase + (ni * 8 * 20 + k16 * 8) * 4);
#pragma unroll
            for (int mi = 0; mi < 2; mi++)
#pragma unroll
                for (int ni = 0; ni < 4; ni++) mma16(acc2[mi][ni], a[mi], b[ni]);
        }
        __syncthreads();
    }

#pragma unroll
    for (int mi = 0; mi < 2; mi++)
#pragma unroll
        for (int h = 0; h < 2; h++) {
            int row = nBase + wm * 32 + mi * 16 + grp + 8 * h;
            if (row >= NN) continue;
            const float* nf = node_feat + ((size_t)row << 7);
            float* op = out_node + ((size_t)row << 7);
#pragma unroll
            for (int ni = 0; ni < 4; ni++) {
                int c = wn * 32 + ni * 8 + qid * 2;
                float o0 = acc2[mi][ni][2 * h]     + __ldg(&node_res_w[c])     * nf[c];
                float o1 = acc2[mi][ni][2 * h + 1] + __ldg(&node_res_w[c + 1]) * nf[c + 1];
                *(float2*)(op + c) = make_float2(o0, o1);
            }
        }
}

// ---------------- launch ----------------
extern "C" void kernel_launch(void* const* d_in, const int* in_sizes, int n_in,
                              void* d_out, int out_size)
{
    (void)in_sizes; (void)n_in; (void)out_size;
    const float* node_feat     = (const float*)d_in[0];
    const float* edge_feat     = (const float*)d_in[1];
    const float* smooth_weight = (const float*)d_in[2];
    const int*   source_index  = (const int*)d_in[3];
    const int*   target_index  = (const int*)d_in[4];
    const int*   d2u           = (const int*)d_in[5];
    const float* W_env         = (const float*)d_in[6];
    const float* Wc1           = (const float*)d_in[7];
    const float* Wc2           = (const float*)d_in[8];
    const float* Wg1           = (const float*)d_in[9];
    const float* Wg2           = (const float*)d_in[10];
    const float* ln_c_g        = (const float*)d_in[11];
    const float* ln_c_b        = (const float*)d_in[12];
    const float* ln_g_g        = (const float*)d_in[13];
    const float* ln_g_b        = (const float*)d_in[14];
    const float* Wn1           = (const float*)d_in[15];
    const float* Wn2           = (const float*)d_in[16];
    const float* We1           = (const float*)d_in[17];
    const float* We2           = (const float*)d_in[18];
    const float* node_res_w    = (const float*)d_in[19];
    const float* edge_res_w    = (const float*)d_in[20];

    float* out_node = (float*)d_out;
    float* out_edge = out_node + (size_t)NN * 128;

    cudaFuncSetAttribute(k_mega, cudaFuncAttributeMaxDynamicSharedMemorySize, MEGA_DYN);
    cudaFuncSetAttribute(k_pre1, cudaFuncAttributeMaxDynamicSharedMemorySize, PRE1_DYN);

    const int NPART = (NN + 255) / 256;

    k_prepA<<<(PREPA_ITEMS + 255) / 256, 256>>>(Wc1, Wg1, Wc2, Wg2, We1, We2, Wn1, Wn2,
                                                edge_feat, node_feat);
    k_pre1<<<PE_BLKS + 2 * PN_BLKS, 512, PRE1_DYN>>>();
    k_h<<<(int)(((size_t)EDN * 32 + 255) / 256), 256>>>(target_index, source_index, d2u);

    k_mega<<<EUN / 32, 256, MEGA_DYN>>>(ln_c_g, ln_c_b, ln_g_g, ln_g_b,
                                        smooth_weight, W_env,
                                        edge_feat, edge_res_w, out_edge);

    k_hist<<<(EDN + 255) / 256, 256>>>(target_index);
    k_scan_part<<<NPART, 256>>>();
    k_scan_top<<<1, 256>>>(NPART);
    k_scan_apply<<<NPART, 256>>>();
    k_scatter<<<(EDN + 255) / 256, 256>>>(target_index);

    k_node_fused<<<(NN + 63) / 64, 256>>>(node_feat, node_res_w, out_node);
}

// round 14
// speedup vs baseline: 1.8242x; 1.0424x over previous
#include <cuda_runtime.h>
#include <cuda_fp16.h>

#define NN  50000
#define EUN 200000
#define EDN 400000

// ---------------- scratch (device globals; no allocation) ----------------
__device__ __align__(16) unsigned g_ef16[EUN * 64];   // edge_feat fp16
__device__ __align__(16) unsigned g_nf16[NN * 64];    // node_feat fp16
__device__ __align__(16) unsigned g_msg16[EDN * 64];  // envelope-scaled messages fp16
// GEMM1 partials, fp16 packed: [row][128 words] (256 halves)
__device__ __align__(16) unsigned g_pe16[(size_t)EUN * 128];
__device__ __align__(16) unsigned g_pt16[(size_t)NN * 128];
__device__ __align__(16) unsigned g_ps16[(size_t)NN * 128];
// CSR over target_index
__device__ int g_csr_cnt[NN];
__device__ int g_csr_off[NN + 1];
__device__ int g_csr_cur[NN];
__device__ int g_csr_edges[EDN];
__device__ int g_part[256];
__device__ int g_pbase[256];

// pre-transposed fp16 weights, tile-blocked: [ktile32][n][16 words]
__device__ __align__(16) unsigned g_w1t[12 * 256 * 16];
__device__ __align__(16) unsigned g_w2ct[4 * 128 * 16];
__device__ __align__(16) unsigned g_w2gt[4 * 128 * 16];
__device__ __align__(16) unsigned g_we1t[4 * 128 * 16];
__device__ __align__(16) unsigned g_we2t[4 * 128 * 16];
__device__ __align__(16) unsigned g_wn1t[4 * 128 * 16];
__device__ __align__(16) unsigned g_wn2t[4 * 128 * 16];

__device__ __forceinline__ float tanhf_(float x) {
    float y;
    asm("tanh.approx.f32 %0, %1;" : "=f"(y) : "f"(x));
    return y;
}
__device__ __forceinline__ float sigmoidf_(float x) {
    return 0.5f * tanhf_(0.5f * x) + 0.5f;
}
__device__ __forceinline__ float siluf_(float x) { return x * sigmoidf_(x); }

__device__ __forceinline__ unsigned pack2(float x, float y) {
    __half2 h = __floats2half2_rn(x, y);
    return *reinterpret_cast<unsigned*>(&h);
}
__device__ __forceinline__ float2 unpack2(unsigned u) {
    __half2 h = *reinterpret_cast<__half2*>(&u);
    return __half22float2(h);
}
__device__ __forceinline__ unsigned sptr(const void* p) {
    return (unsigned)__cvta_generic_to_shared(p);
}
__device__ __forceinline__ void ldsm4(unsigned* r, unsigned a) {
    asm volatile("ldmatrix.sync.aligned.m8n8.x4.shared.b16 {%0,%1,%2,%3}, [%4];"
        : "=r"(r[0]), "=r"(r[1]), "=r"(r[2]), "=r"(r[3]) : "r"(a));
}
__device__ __forceinline__ void ldsm2(unsigned* r, unsigned a) {
    asm volatile("ldmatrix.sync.aligned.m8n8.x2.shared.b16 {%0,%1}, [%2];"
        : "=r"(r[0]), "=r"(r[1]) : "r"(a));
}
__device__ __forceinline__ void mma16(float* d, const unsigned* a, const unsigned* b) {
    asm volatile(
        "mma.sync.aligned.m16n8k16.row.col.f32.f16.f16.f32 "
        "{%0,%1,%2,%3}, {%4,%5,%6,%7}, {%8,%9}, {%0,%1,%2,%3};"
        : "+f"(d[0]), "+f"(d[1]), "+f"(d[2]), "+f"(d[3])
        : "r"(a[0]), "r"(a[1]), "r"(a[2]), "r"(a[3]), "r"(b[0]), "r"(b[1]));
}
__device__ __forceinline__ void cpa16(unsigned dst, const void* src) {
    asm volatile("cp.async.cg.shared.global [%0], [%1], 16;"
        :: "r"(dst), "l"(__cvta_generic_to_global(src)));
}
__device__ __forceinline__ void cpcommit() { asm volatile("cp.async.commit_group;"); }
__device__ __forceinline__ void cpwait0() { asm volatile("cp.async.wait_group 0;"); }
__device__ __forceinline__ void cpwait1() { asm volatile("cp.async.wait_group 1;"); }

__device__ __forceinline__ unsigned hss(unsigned a, unsigned b, unsigned c) {
    float2 fa = unpack2(a), fb = unpack2(b), fc = unpack2(c);
    return pack2(siluf_(fa.x + fb.x + fc.x), siluf_(fa.y + fb.y + fc.y));
}

// ---------------- k_prepA: weights + features fp16 + csr zero (merged) ----------------
__global__ void k_prepA(const float* __restrict__ Wc1, const float* __restrict__ Wg1,
                        const float* __restrict__ Wc2, const float* __restrict__ Wg2,
                        const float* __restrict__ We1, const float* __restrict__ We2,
                        const float* __restrict__ Wn1, const float* __restrict__ Wn2,
                        const float* __restrict__ edge_feat, const float* __restrict__ node_feat)
{
    int i = blockIdx.x * blockDim.x + threadIdx.x;
    if (i < 12 * 256 * 16) {
        int kt = i >> 12;
        int r = i & 4095;
        int n = r >> 4, kpl = r & 15;
        int kp = kt * 16 + kpl;
        const float* W = (n < 128) ? Wc1 : Wg1;
        int c = n & 127;
        g_w1t[i] = pack2(W[(size_t)(2 * kp) * 128 + c], W[(size_t)(2 * kp + 1) * 128 + c]);
        return;
    }
    int j = i - 12 * 256 * 16;
    if (j < 6 * 8192) {
        int mtx = j >> 13;
        int r = j & 8191;
        int kt = r >> 11, rr = r & 2047;
        int n = rr >> 4, kpl = rr & 15;
        int kp = kt * 16 + kpl;
        const float* W; unsigned* O;
        switch (mtx) {
            case 0: W = Wc2; O = g_w2ct; break;
            case 1: W = Wg2; O = g_w2gt; break;
            case 2: W = We1; O = g_we1t; break;
            case 3: W = We2; O = g_we2t; break;
            case 4: W = Wn1; O = g_wn1t; break;
            default: W = Wn2; O = g_wn2t; break;
        }
        O[r] = pack2(W[(size_t)(2 * kp) * 128 + n], W[(size_t)(2 * kp + 1) * 128 + n]);
        return;
    }
    int k = j - 6 * 8192;
    if (k < EUN * 64) {
        g_ef16[k] = pack2(edge_feat[2 * (size_t)k], edge_feat[2 * (size_t)k + 1]);
        return;
    }
    int m = k - EUN * 64;
    if (m < NN * 64) {
        g_nf16[m] = pack2(node_feat[2 * (size_t)m], node_feat[2 * (size_t)m + 1]);
        return;
    }
    int z = m - NN * 64;
    if (z < NN) g_csr_cnt[z] = 0;
}
#define PREPA_ITEMS (12 * 256 * 16 + 6 * 8192 + EUN * 64 + NN * 64 + NN)

// ---------------- k_pre1: GEMM1 partials (fp16 out) ----------
#define PE_BLKS ((EUN + 127) / 128)
#define PN_BLKS ((NN + 127) / 128)
#define PRE1_DYN ((2 * 2560 + 2 * 5120) * 4)
__global__ __launch_bounds__(512) void k_pre1()
{
    extern __shared__ __align__(16) unsigned dyn[];
    const int tid = threadIdx.x;
    const unsigned sbase = sptr(dyn);

    int bid = blockIdx.x;
    int rBase, rowsMax, ktbase;
    const unsigned* feat;
    unsigned* out;
    if (bid < PE_BLKS)                { rBase = bid * 128;                       rowsMax = EUN; ktbase = 0; feat = g_ef16; out = g_pe16; }
    else if (bid < PE_BLKS + PN_BLKS) { rBase = (bid - PE_BLKS) * 128;           rowsMax = NN;  ktbase = 4; feat = g_nf16; out = g_pt16; }
    else                              { rBase = (bid - PE_BLKS - PN_BLKS) * 128; rowsMax = NN;  ktbase = 8; feat = g_nf16; out = g_ps16; }

    const int w = tid >> 5, lane = tid & 31;
    const int wm = w & 3, wn = w >> 2;
    const int grp = lane >> 2, qid = lane & 3;

    const int afm = tid >> 2, afc = tid & 3;
    int arow = rBase + afm;
    if (arow >= rowsMax) arow = rowsMax - 1;
    const unsigned* arowp = feat + (size_t)arow * 64 + afc * 4;

#define P1_FILL_A(kt, nb) \
    cpa16(sbase + ((nb) * 2560 + afm * 20 + afc * 4) * 4, arowp + (kt) * 16)
#define P1_FILL_B(kt, nb) do { \
    _Pragma("unroll") \
    for (int l = 0; l < 2; l++) { \
        int i4 = tid + l * 512; \
        int n_ = i4 >> 2, q_ = i4 & 3; \
        cpa16(sbase + (5120 + (nb) * 5120 + n_ * 20 + q_ * 4) * 4, \
              &g_w1t[(ktbase + (kt)) * 4096 + n_ * 16 + q_ * 4]); \
    } } while (0)

    P1_FILL_A(0, 0); P1_FILL_B(0, 0); cpcommit();

    const unsigned aOff = ((wm * 32 + (lane & 7) + ((lane >> 3) & 1) * 8) * 20 + ((lane >> 4) & 1) * 4) * 4;
    const unsigned bOff = ((wn * 64 + (lane & 7)) * 20 + ((lane >> 3) & 1) * 4) * 4;

    float acc[2][8][4];
#pragma unroll
    for (int mi = 0; mi < 2; mi++)
#pragma unroll
        for (int ni = 0; ni < 8; ni++)
#pragma unroll
            for (int q = 0; q < 4; q++) acc[mi][ni][q] = 0.f;

    for (int kt = 0; kt < 4; kt++) {
        if (kt < 3) {
            P1_FILL_A(kt + 1, (kt + 1) & 1);
            P1_FILL_B(kt + 1, (kt + 1) & 1);
            cpcommit();
            cpwait1();
        } else {
            cpwait0();
        }
        __syncthreads();
        const unsigned aB = sbase + ((kt & 1) * 2560) * 4 + aOff;
        const unsigned bB = sbase + (5120 + (kt & 1) * 5120) * 4 + bOff;
#pragma unroll
        for (int k16 = 0; k16 < 2; k16++) {
            unsigned a[2][4], b[8][2];
#pragma unroll
            for (int mi = 0; mi < 2; mi++) ldsm4(a[mi], aB + (mi * 16 * 20 + k16 * 8) * 4);
#pragma unroll
            for (int ni = 0; ni < 8; ni++) ldsm2(b[ni], bB + (ni * 8 * 20 + k16 * 8) * 4);
#pragma unroll
            for (int mi = 0; mi < 2; mi++)
#pragma unroll
                for (int ni = 0; ni < 8; ni++) mma16(acc[mi][ni], a[mi], b[ni]);
        }
        __syncthreads();
    }

#pragma unroll
    for (int mi = 0; mi < 2; mi++)
#pragma unroll
        for (int h = 0; h < 2; h++) {
            int grow = rBase + wm * 32 + mi * 16 + grp + 8 * h;
            if (grow >= rowsMax) continue;
            unsigned* op = out + (size_t)grow * 128;
#pragma unroll
            for (int ni = 0; ni < 8; ni++) {
                int c = wn * 64 + ni * 8 + qid * 2;
                op[c >> 1] = pack2(acc[mi][ni][2 * h], acc[mi][ni][2 * h + 1]);
            }
        }
}

// ---------------- CSR build ----------------
__global__ void k_hist(const int* __restrict__ tgt_i) {
    int i = blockIdx.x * blockDim.x + threadIdx.x;
    if (i < EDN) atomicAdd(&g_csr_cnt[tgt_i[i]], 1);
}
__global__ void k_scan_part() {
    __shared__ int sm[256];
    int t = threadIdx.x;
    int i = blockIdx.x * 256 + t;
    sm[t] = (i < NN) ? g_csr_cnt[i] : 0;
    __syncthreads();
#pragma unroll
    for (int off = 128; off > 0; off >>= 1) {
        if (t < off) sm[t] += sm[t + off];
        __syncthreads();
    }
    if (t == 0) g_part[blockIdx.x] = sm[0];
}
__global__ void k_scan_top(int nparts) {
    __shared__ int sm[256];
    int t = threadIdx.x;
    sm[t] = (t < nparts) ? g_part[t] : 0;
    __syncthreads();
#pragma unroll
    for (int off = 1; off < 256; off <<= 1) {
        int v = (t >= off) ? sm[t - off] : 0;
        __syncthreads();
        sm[t] += v;
        __syncthreads();
    }
    if (t < nparts) g_pbase[t] = (t == 0) ? 0 : sm[t - 1];
    if (t == 0) g_csr_off[NN] = EDN;
}
__global__ void k_scan_apply() {
    __shared__ int sm[256];
    int t = threadIdx.x;
    int i = blockIdx.x * 256 + t;
    int v = (i < NN) ? g_csr_cnt[i] : 0;
    sm[t] = v;
    __syncthreads();
#pragma unroll
    for (int off = 1; off < 256; off <<= 1) {
        int u = (t >= off) ? sm[t - off] : 0;
        __syncthreads();
        sm[t] += u;
        __syncthreads();
    }
    if (i < NN) {
        int excl = sm[t] - v + g_pbase[blockIdx.x];
        g_csr_off[i] = excl;
        g_csr_cur[i] = excl;
    }
}
__global__ void k_scatter(const int* __restrict__ tgt_i) {
    int i = blockIdx.x * blockDim.x + threadIdx.x;
    if (i < EDN) {
        int pos = atomicAdd(&g_csr_cur[tgt_i[i]], 1);
        g_csr_edges[pos] = i;
    }
}

// ============ k_mega: h-construction + stages A-C + fused edge output ============
// block b owns 32 undirected edges; rows 0-31 = fwd directed, 32-63 = rev directed.
// prologue: pt/ps rows cp.async-gathered into Bc/Bg; pe rows (contiguous, shared by
// both halves) via LDG; h = silu(pe+pt+ps) -> Ac/Ag. Then weights -> Bc/Bg.
#define FP 68
#define AcO 0
#define AgO 4352
#define BcO 8704
#define BgO 17408
#define MEGA_DYN ((BgO + 128 * FP) * 4)   // 104448 B
__global__ __launch_bounds__(256, 2) void k_mega(
    const int* __restrict__ tgt_i, const int* __restrict__ src_i,
    const float* __restrict__ lncg, const float* __restrict__ lncb,
    const float* __restrict__ lngg, const float* __restrict__ lngb,
    const float* __restrict__ smooth_weight, const float* __restrict__ W_env,
    const float* __restrict__ edge_feat, const float* __restrict__ edge_res_w,
    float* __restrict__ out_edge)
{
    extern __shared__ __align__(16) unsigned dyn[];
    __shared__ float Wenv_s[7][128];
    __shared__ float sw7[32][8];
    __shared__ float4 red[64][4];
    __shared__ int idxT[64], idxS[64];

    const int tid = threadIdx.x;
    const int uBase = blockIdx.x * 32;
    const int w = tid >> 5, lane = tid & 31;
    const int wm = w & 1, wn = w >> 1;
    const int grp = lane >> 2, qid = lane & 3;
    const unsigned sbase = sptr(dyn);

    if (tid < 64) {
        int m = tid;
        int e = (m < 32) ? (uBase + m) : (EUN + uBase + m - 32);
        idxT[m] = tgt_i[e];
    } else if (tid < 128) {
        int m = tid - 64;
        int e = (m < 32) ? (uBase + m) : (EUN + uBase + m - 32);
        idxS[m] = src_i[e];
    }
    __syncthreads();

    // cp.async gather: pt rows -> Bc (pitch 128 words), ps rows -> Bg
#pragma unroll
    for (int l = 0; l < 8; l++) {
        int i4 = tid + l * 256;        // 0..2047
        int m = i4 >> 5, q = i4 & 31;  // row, uint4 chunk
        cpa16(sbase + (BcO + m * 128 + q * 4) * 4, &g_pt16[(size_t)idxT[m] * 128 + q * 4]);
        cpa16(sbase + (BgO + m * 128 + q * 4) * 4, &g_ps16[(size_t)idxS[m] * 128 + q * 4]);
    }
    cpcommit();

    for (int f = tid; f < 224; f += 256) {
        int mm = f / 7, j = f % 7;
        sw7[mm][j] = smooth_weight[(size_t)(uBase + mm) * 7 + j];
    }
    for (int f = tid; f < 896; f += 256) Wenv_s[f >> 7][f & 127] = W_env[f];

    cpwait0();
    __syncthreads();

    // ---- h = silu(pe + pt + ps) -> Ac (core cols) / Ag (gate cols) ----
#pragma unroll
    for (int l = 0; l < 8; l++) {
        int i4 = tid + l * 256;
        int m = i4 >> 5, q = i4 & 31;
        uint4 A = *(const uint4*)&g_pe16[(size_t)(uBase + (m & 31)) * 128 + q * 4];
        uint4 B = *(uint4*)&dyn[BcO + m * 128 + q * 4];
        uint4 C = *(uint4*)&dyn[BgO + m * 128 + q * 4];
        uint4 O;
        O.x = hss(A.x, B.x, C.x);
        O.y = hss(A.y, B.y, C.y);
        O.z = hss(A.z, B.z, C.z);
        O.w = hss(A.w, B.w, C.w);
        if (q < 16) *(uint4*)&dyn[AcO + m * FP + q * 4] = O;
        else        *(uint4*)&dyn[AgO + m * FP + (q - 16) * 4] = O;
    }
    __syncthreads();   // Bc/Bg reads done; safe to overwrite with weights

    // weights Wc2/Wg2 -> Bc/Bg
#pragma unroll
    for (int l = 0; l < 8; l++) {
        int i4 = tid + l * 256;
        int n_ = i4 >> 4, q_ = i4 & 15;
        int off = (q_ >> 2) * 2048 + n_ * 16 + (q_ & 3) * 4;
        unsigned d = (n_ * FP + (q_ >> 2) * 16 + (q_ & 3) * 4) * 4;
        cpa16(sbase + BcO * 4 + d, &g_w2ct[off]);
        cpa16(sbase + BgO * 4 + d, &g_w2gt[off]);
    }
    cpcommit();
    cpwait0();
    __syncthreads();

    const unsigned aFragOff = ((lane & 7) + ((lane >> 3) & 1) * 8) * FP + ((lane >> 4) & 1) * 4;
    const unsigned bRow2 = ((wn * 32 + (lane & 7)) * FP + ((lane >> 3) & 1) * 4) * 4;

    // ---- stage A: core & gate GEMM, K=128 ----
    float accc[2][4][4], accg[2][4][4];
#pragma unroll
    for (int mi = 0; mi < 2; mi++)
#pragma unroll
        for (int ni = 0; ni < 4; ni++)
#pragma unroll
            for (int q = 0; q < 4; q++) { accc[mi][ni][q] = 0.f; accg[mi][ni][q] = 0.f; }
    {
        const unsigned aC = sbase + (AcO + wm * 32 * FP + aFragOff) * 4;
        const unsigned aG = sbase + (AgO + wm * 32 * FP + aFragOff) * 4;
        const unsigned bC = sbase + BcO * 4 + bRow2;
        const unsigned bG = sbase + BgO * 4 + bRow2;
#pragma unroll
        for (int k16 = 0; k16 < 8; k16++) {
            unsigned ac[2][4], ag[2][4], bc[4][2], bg[4][2];
#pragma unroll
            for (int mi = 0; mi < 2; mi++) {
                ldsm4(ac[mi], aC + (mi * 16 * FP + k16 * 8) * 4);
                ldsm4(ag[mi], aG + (mi * 16 * FP + k16 * 8) * 4);
            }
#pragma unroll
            for (int ni = 0; ni < 4; ni++) {
                ldsm2(bc[ni], bC + (ni * 8 * FP + k16 * 8) * 4);
                ldsm2(bg[ni], bG + (ni * 8 * FP + k16 * 8) * 4);
            }
#pragma unroll
            for (int mi = 0; mi < 2; mi++)
#pragma unroll
                for (int ni = 0; ni < 4; ni++) {
                    mma16(accc[mi][ni], ac[mi], bc[ni]);
                    mma16(accg[mi][ni], ag[mi], bg[ni]);
                }
        }
    }

    // ---- LN partial sums ----
#pragma unroll
    for (int mi = 0; mi < 2; mi++)
#pragma unroll
        for (int h = 0; h < 2; h++) {
            float sc = 0.f, sc2 = 0.f, sg = 0.f, sg2 = 0.f;
#pragma unroll
            for (int ni = 0; ni < 4; ni++) {
                float c0 = accc[mi][ni][2 * h], c1 = accc[mi][ni][2 * h + 1];
                float g0 = accg[mi][ni][2 * h], g1 = accg[mi][ni][2 * h + 1];
                sc += c0 + c1; sc2 += c0 * c0 + c1 * c1;
                sg += g0 + g1; sg2 += g0 * g0 + g1 * g1;
            }
#pragma unroll
            for (int off = 1; off < 4; off <<= 1) {
                sc  += __shfl_xor_sync(0xffffffffu, sc,  off, 4);
                sc2 += __shfl_xor_sync(0xffffffffu, sc2, off, 4);
                sg  += __shfl_xor_sync(0xffffffffu, sg,  off, 4);
                sg2 += __shfl_xor_sync(0xffffffffu, sg2, off, 4);
            }
            if (qid == 0) red[wm * 32 + mi * 16 + grp + 8 * h][wn] = make_float4(sc, sc2, sg, sg2);
        }
    __syncthreads();

    // prefetch We1 / We2 into Bc/Bg regions
#pragma unroll
    for (int l = 0; l < 8; l++) {
        int i4 = tid + l * 256;
        int n_ = i4 >> 4, q_ = i4 & 15;
        int off = (q_ >> 2) * 2048 + n_ * 16 + (q_ & 3) * 4;
        unsigned d = (n_ * FP + (q_ >> 2) * 16 + (q_ & 3) * 4) * 4;
        cpa16(sbase + BcO * 4 + d, &g_we1t[off]);
        cpa16(sbase + BgO * 4 + d, &g_we2t[off]);
    }
    cpcommit();

    // ---- LN epilogue: nl -> t1 (Ac region), msg -> g_msg16 ----
#pragma unroll
    for (int mi = 0; mi < 2; mi++)
#pragma unroll
        for (int h = 0; h < 2; h++) {
            int rloc = wm * 32 + mi * 16 + grp + 8 * h;
            float4 p0 = red[rloc][0], p1 = red[rloc][1], p2 = red[rloc][2], p3 = red[rloc][3];
            float sc = p0.x + p1.x + p2.x + p3.x;
            float sc2 = p0.y + p1.y + p2.y + p3.y;
            float sg = p0.z + p1.z + p2.z + p3.z;
            float sg2 = p0.w + p1.w + p2.w + p3.w;
            float mc = sc * (1.f / 128.f);
            float vc = fmaxf(sc2 * (1.f / 128.f) - mc * mc, 0.f);
            float rc = rsqrtf(vc + 1e-5f);
            float mg = sg * (1.f / 128.f);
            float vg = fmaxf(sg2 * (1.f / 128.f) - mg * mg, 0.f);
            float rg = rsqrtf(vg + 1e-5f);

            int rr = rloc & 31;
            float s0 = sw7[rr][0], s1 = sw7[rr][1], s2 = sw7[rr][2], s3 = sw7[rr][3];
            float s4 = sw7[rr][4], s5 = sw7[rr][5], s6 = sw7[rr][6];
            size_t e = (rloc < 32) ? (size_t)(uBase + rloc) : (size_t)(EUN + uBase + rloc - 32);
            unsigned* mp = g_msg16 + e * 64;
#pragma unroll
            for (int ni = 0; ni < 4; ni++) {
                int c = wn * 32 + ni * 8 + qid * 2;
                float hc0 = (accc[mi][ni][2 * h] - mc) * rc * __ldg(&lncg[c]) + __ldg(&lncb[c]);
                float hg0 = (accg[mi][ni][2 * h] - mg) * rg * __ldg(&lngg[c]) + __ldg(&lngb[c]);
                float nl0 = siluf_(hc0) * sigmoidf_(hg0);
                float hc1 = (accc[mi][ni][2 * h + 1] - mc) * rc * __ldg(&lncg[c + 1]) + __ldg(&lncb[c + 1]);
                float hg1 = (accg[mi][ni][2 * h + 1] - mg) * rg * __ldg(&lngg[c + 1]) + __ldg(&lngb[c + 1]);
                float nl1 = siluf_(hc1) * sigmoidf_(hg1);
                dyn[AcO + rloc * FP + (c >> 1)] = pack2(nl0, nl1);
                float sw0 = s0 * Wenv_s[0][c] + s1 * Wenv_s[1][c] + s2 * Wenv_s[2][c]
                          + s3 * Wenv_s[3][c] + s4 * Wenv_s[4][c] + s5 * Wenv_s[5][c]
                          + s6 * Wenv_s[6][c];
                float sw1 = s0 * Wenv_s[0][c + 1] + s1 * Wenv_s[1][c + 1] + s2 * Wenv_s[2][c + 1]
                          + s3 * Wenv_s[3][c + 1] + s4 * Wenv_s[4][c + 1] + s5 * Wenv_s[5][c + 1]
                          + s6 * Wenv_s[6][c + 1];
                mp[c >> 1] = pack2(nl0 * sw0, nl1 * sw1);
            }
        }
    cpwait0();
    __syncthreads();

    // ---- stage B: silu(t1 @ We1) -> t2 (Ag region) ----
    float acc1[2][4][4];
#pragma unroll
    for (int mi = 0; mi < 2; mi++)
#pragma unroll
        for (int ni = 0; ni < 4; ni++)
#pragma unroll
            for (int q = 0; q < 4; q++) acc1[mi][ni][q] = 0.f;
    {
        const unsigned aT = sbase + (AcO + wm * 32 * FP + aFragOff) * 4;
        const unsigned bW = sbase + BcO * 4 + bRow2;
#pragma unroll
        for (int k16 = 0; k16 < 8; k16++) {
            unsigned a[2][4], b[4][2];
#pragma unroll
            for (int mi = 0; mi < 2; mi++) ldsm4(a[mi], aT + (mi * 16 * FP + k16 * 8) * 4);
#pragma unroll
            for (int ni = 0; ni < 4; ni++) ldsm2(b[ni], bW + (ni * 8 * FP + k16 * 8) * 4);
#pragma unroll
            for (int mi = 0; mi < 2; mi++)
#pragma unroll
                for (int ni = 0; ni < 4; ni++) mma16(acc1[mi][ni], a[mi], b[ni]);
        }
    }
#pragma unroll
    for (int mi = 0; mi < 2; mi++)
#pragma unroll
        for (int h = 0; h < 2; h++) {
            int rloc = wm * 32 + mi * 16 + grp + 8 * h;
#pragma unroll
            for (int ni = 0; ni < 4; ni++) {
                int c = wn * 32 + ni * 8 + qid * 2;
                dyn[AgO + rloc * FP + (c >> 1)] =
                    pack2(siluf_(acc1[mi][ni][2 * h]), siluf_(acc1[mi][ni][2 * h + 1]));
            }
        }
    __syncthreads();

    // ---- stage C: t2 @ We2 -> ded (smem, Ac region) ----
    float acc2[2][4][4];
#pragma unroll
    for (int mi = 0; mi < 2; mi++)
#pragma unroll
        for (int ni = 0; ni < 4; ni++)
#pragma unroll
            for (int q = 0; q < 4; q++) acc2[mi][ni][q] = 0.f;
    {
        const unsigned aT = sbase + (AgO + wm * 32 * FP + aFragOff) * 4;
        const unsigned bW = sbase + BgO * 4 + bRow2;
#pragma unroll
        for (int k16 = 0; k16 < 8; k16++) {
            unsigned a[2][4], b[4][2];
#pragma unroll
            for (int mi = 0; mi < 2; mi++) ldsm4(a[mi], aT + (mi * 16 * FP + k16 * 8) * 4);
#pragma unroll
            for (int ni = 0; ni < 4; ni++) ldsm2(b[ni], bW + (ni * 8 * FP + k16 * 8) * 4);
#pragma unroll
            for (int mi = 0; mi < 2; mi++)
#pragma unroll
                for (int ni = 0; ni < 4; ni++) mma16(acc2[mi][ni], a[mi], b[ni]);
        }
    }
#pragma unroll
    for (int mi = 0; mi < 2; mi++)
#pragma unroll
        for (int h = 0; h < 2; h++) {
            int rloc = wm * 32 + mi * 16 + grp + 8 * h;
#pragma unroll
            for (int ni = 0; ni < 4; ni++) {
                int c = wn * 32 + ni * 8 + qid * 2;
                dyn[AcO + rloc * FP + (c >> 1)] = pack2(acc2[mi][ni][2 * h], acc2[mi][ni][2 * h + 1]);
            }
        }
    __syncthreads();

    // ---- fused edge output: out_edge[u] = (ded_fwd + ded_rev)/2 + rw*ef ----
#pragma unroll
    for (int it = 0; it < 4; it++) {
        int f = tid + it * 256;
        int row = f >> 5, cw = f & 31;
        uint2 da = *(uint2*)&dyn[AcO + row * FP + cw * 2];
        uint2 db = *(uint2*)&dyn[AcO + (row + 32) * FP + cw * 2];
        float2 a0 = unpack2(da.x), a1 = unpack2(da.y);
        float2 b0 = unpack2(db.x), b1 = unpack2(db.y);
        size_t u = (size_t)(uBase + row);
        float4 ef = *(const float4*)&edge_feat[u * 128 + cw * 4];
        float4 rw = *(const float4*)&edge_res_w[cw * 4];
        float4 o;
        o.x = (a0.x + b0.x) * 0.5f + rw.x * ef.x;
        o.y = (a0.y + b0.y) * 0.5f + rw.y * ef.y;
        o.z = (a1.x + b1.x) * 0.5f + rw.z * ef.z;
        o.w = (a1.y + b1.y) * 0.5f + rw.w * ef.w;
        *(float4*)&out_edge[u * 128 + cw * 4] = o;
    }
}

// ============ k_node_fused: CSR gather (smem) + 2-stage node FFN + residual ============
__global__ __launch_bounds__(256) void k_node_fused(
    const float* __restrict__ node_feat, const float* __restrict__ node_res_w,
    float* __restrict__ out_node)
{
    __shared__ __align__(16) unsigned As[64 * 68];
    __shared__ __align__(16) unsigned Bs[128 * 20];
    __shared__ __align__(16) unsigned t1[64 * 68];

    const int tid = threadIdx.x;
    const int nBase = blockIdx.x * 64;
    const int w = tid >> 5, lane = tid & 31;
    const int wm = w & 1, wn = w >> 1;
    const int grp = lane >> 2, qid = lane & 3;

    for (int s = 0; s < 8; s++) {
        int m = w * 8 + s;
        int node = nBase + m;
        float4 acc = make_float4(0.f, 0.f, 0.f, 0.f);
        if (node < NN) {
            int b = g_csr_off[node], e2 = g_csr_off[node + 1];
            int j = b;
            for (; j + 1 < e2; j += 2) {
                int ed0 = g_csr_edges[j], ed1 = g_csr_edges[j + 1];
                uint2 v0 = *(const uint2*)&g_msg16[(size_t)ed0 * 64 + lane * 2];
                uint2 v1 = *(const uint2*)&g_msg16[(size_t)ed1 * 64 + lane * 2];
                float2 a0 = unpack2(v0.x), b0 = unpack2(v0.y);
                float2 a1 = unpack2(v1.x), b1 = unpack2(v1.y);
                acc.x += a0.x + a1.x; acc.y += a0.y + a1.y;
                acc.z += b0.x + b1.x; acc.w += b0.y + b1.y;
            }
            if (j < e2) {
                int ed = g_csr_edges[j];
                uint2 v = *(const uint2*)&g_msg16[(size_t)ed * 64 + lane * 2];
                float2 a = unpack2(v.x), bb = unpack2(v.y);
                acc.x += a.x; acc.y += a.y; acc.z += bb.x; acc.w += bb.y;
            }
        }
        *(uint2*)&As[m * 68 + lane * 2] = make_uint2(pack2(acc.x, acc.y), pack2(acc.z, acc.w));
    }
    __syncthreads();

    const int aRow = wm * 32 + (lane & 7) + ((lane >> 3) & 1) * 8;
    const int aCol = ((lane >> 4) & 1) * 4;
    const unsigned aBase = sptr(As) + (aRow * 68 + aCol) * 4;
    const unsigned tBase = sptr(t1) + (aRow * 68 + aCol) * 4;
    const unsigned bBase = sptr(Bs) + ((wn * 32 + (lane & 7)) * 20 + ((lane >> 3) & 1) * 4) * 4;

    float acc[2][4][4];
#pragma unroll
    for (int mi = 0; mi < 2; mi++)
#pragma unroll
        for (int ni = 0; ni < 4; ni++)
#pragma unroll
            for (int q = 0; q < 4; q++) acc[mi][ni][q] = 0.f;

    for (int kt = 0; kt < 4; kt++) {
        {
            const uint4* src = (const uint4*)&g_wn1t[kt * 2048];
#pragma unroll
            for (int l = 0; l < 2; l++) {
                int i4 = tid + l * 256;
                int n = i4 >> 2, wq = (i4 & 3) * 4;
                *(uint4*)&Bs[n * 20 + wq] = src[i4];
            }
        }
        __syncthreads();
#pragma unroll
        for (int k16 = 0; k16 < 2; k16++) {
            unsigned a[2][4], b[4][2];
#pragma unroll
            for (int mi = 0; mi < 2; mi++)
                ldsm4(a[mi], aBase + (mi * 16 * 68 + kt * 16 + k16 * 8) * 4);
#pragma unroll
            for (int ni = 0; ni < 4; ni++) ldsm2(b[ni], bBase + (ni * 8 * 20 + k16 * 8) * 4);
#pragma unroll
            for (int mi = 0; mi < 2; mi++)
#pragma unroll
                for (int ni = 0; ni < 4; ni++) mma16(acc[mi][ni], a[mi], b[ni]);
        }
        __syncthreads();
    }
#pragma unroll
    for (int mi = 0; mi < 2; mi++)
#pragma unroll
        for (int h = 0; h < 2; h++) {
            int r = wm * 32 + mi * 16 + grp + 8 * h;
#pragma unroll
            for (int ni = 0; ni < 4; ni++) {
                int c = wn * 32 + ni * 8 + qid * 2;
                t1[r * 68 + (c >> 1)] = pack2(siluf_(acc[mi][ni][2 * h]), siluf_(acc[mi][ni][2 * h + 1]));
            }
        }
    __syncthreads();

    float acc2[2][4][4];
#pragma unroll
    for (int mi = 0; mi < 2; mi++)
#pragma unroll
        for (int ni = 0; ni < 4; ni++)
#pragma unroll
            for (int q = 0; q < 4; q++) acc2[mi][ni][q] = 0.f;

    for (int kt = 0; kt < 4; kt++) {
        {
            const uint4* src = (const uint4*)&g_wn2t[kt * 2048];
#pragma unroll
            for (int l = 0; l < 2; l++) {
                int i4 = tid + l * 256;
                int n = i4 >> 2, wq = (i4 & 3) * 4;
                *(uint4*)&Bs[n * 20 + wq] = src[i4];
            }
        }
        __syncthreads();
#pragma unroll
        for (int k16 = 0; k16 < 2; k16++) {
            unsigned a[2][4], b[4][2];
#pragma unroll
            for (int mi = 0; mi < 2; mi++)
                ldsm4(a[mi], tBase + (mi * 16 * 68 + kt * 16 + k16 * 8) * 4);
#pragma unroll
            for (int ni = 0; ni < 4; ni++) ldsm2(b[ni], bBase + (ni * 8 * 20 + k16 * 8) * 4);
#pragma unroll
            for (int mi = 0; mi < 2; mi++)
#pragma unroll
                for (int ni = 0; ni < 4; ni++) mma16(acc2[mi][ni], a[mi], b[ni]);
        }
        __syncthreads();
    }

#pragma unroll
    for (int mi = 0; mi < 2; mi++)
#pragma unroll
        for (int h = 0; h < 2; h++) {
            int row = nBase + wm * 32 + mi * 16 + grp + 8 * h;
            if (row >= NN) continue;
            const float* nf = node_feat + ((size_t)row << 7);
            float* op = out_node + ((size_t)row << 7);
#pragma unroll
            for (int ni = 0; ni < 4; ni++) {
                int c = wn * 32 + ni * 8 + qid * 2;
                float o0 = acc2[mi][ni][2 * h]     + __ldg(&node_res_w[c])     * nf[c];
                float o1 = acc2[mi][ni][2 * h + 1] + __ldg(&node_res_w[c + 1]) * nf[c + 1];
                *(float2*)(op + c) = make_float2(o0, o1);
            }
        }
}

// ---------------- launch ----------------
extern "C" void kernel_launch(void* const* d_in, const int* in_sizes, int n_in,
                              void* d_out, int out_size)
{
    (void)in_sizes; (void)n_in; (void)out_size;
    const float* node_feat     = (const float*)d_in[0];
    const float* edge_feat     = (const float*)d_in[1];
    const float* smooth_weight = (const float*)d_in[2];
    const int*   source_index  = (const int*)d_in[3];
    const int*   target_index  = (const int*)d_in[4];
    const int*   d2u           = (const int*)d_in[5];
    const float* W_env         = (const float*)d_in[6];
    const float* Wc1           = (const float*)d_in[7];
    const float* Wc2           = (const float*)d_in[8];
    const float* Wg1           = (const float*)d_in[9];
    const float* Wg2           = (const float*)d_in[10];
    const float* ln_c_g        = (const float*)d_in[11];
    const float* ln_c_b        = (const float*)d_in[12];
    const float* ln_g_g        = (const float*)d_in[13];
    const float* ln_g_b        = (const float*)d_in[14];
    const float* Wn1           = (const float*)d_in[15];
    const float* Wn2           = (const float*)d_in[16];
    const float* We1           = (const float*)d_in[17];
    const float* We2           = (const float*)d_in[18];
    const float* node_res_w    = (const float*)d_in[19];
    const float* edge_res_w    = (const float*)d_in[20];
    (void)d2u;

    float* out_node = (float*)d_out;
    float* out_edge = out_node + (size_t)NN * 128;

    cudaFuncSetAttribute(k_mega, cudaFuncAttributeMaxDynamicSharedMemorySize, MEGA_DYN);
    cudaFuncSetAttribute(k_pre1, cudaFuncAttributeMaxDynamicSharedMemorySize, PRE1_DYN);

    const int NPART = (NN + 255) / 256;

    k_prepA<<<(PREPA_ITEMS + 255) / 256, 256>>>(Wc1, Wg1, Wc2, Wg2, We1, We2, Wn1, Wn2,
                                                edge_feat, node_feat);
    k_pre1<<<PE_BLKS + 2 * PN_BLKS, 512, PRE1_DYN>>>();

    k_mega<<<EUN / 32, 256, MEGA_DYN>>>(target_index, source_index,
                                        ln_c_g, ln_c_b, ln_g_g, ln_g_b,
                                        smooth_weight, W_env,
                                        edge_feat, edge_res_w, out_edge);

    k_hist<<<(EDN + 255) / 256, 256>>>(target_index);
    k_scan_part<<<NPART, 256>>>();
    k_scan_top<<<1, 256>>>(NPART);
    k_scan_apply<<<NPART, 256>>>();
    k_scatter<<<(EDN + 255) / 256, 256>>>(target_index);

    k_node_fused<<<(NN + 63) / 64, 256>>>(node_feat, node_res_w, out_node);
}

// round 15
// speedup vs baseline: 1.8500x; 1.0142x over previous
#include <cuda_runtime.h>
#include <cuda_fp16.h>

#define NN  50000
#define EUN 200000
#define EDN 400000

// ---------------- scratch (device globals; no allocation) ----------------
__device__ __align__(16) unsigned g_ef16[EUN * 64];   // edge_feat fp16
__device__ __align__(16) unsigned g_nf16[NN * 64];    // node_feat fp16
__device__ __align__(16) unsigned g_msg16[EDN * 64];  // envelope-scaled messages fp16
// GEMM1 partials, fp16 packed: [row][128 words] (256 halves)
__device__ __align__(16) unsigned g_pe16[(size_t)EUN * 128];
__device__ __align__(16) unsigned g_pt16[(size_t)NN * 128];
__device__ __align__(16) unsigned g_ps16[(size_t)NN * 128];
// CSR over target_index
__device__ int g_csr_cnt[NN];
__device__ int g_csr_off[NN + 1];
__device__ int g_csr_cur[NN];
__device__ int g_csr_edges[EDN];
__device__ int g_part[256];
__device__ int g_pbase[256];

// pre-transposed fp16 weights, tile-blocked: [ktile32][n][16 words]
__device__ __align__(16) unsigned g_w1t[12 * 256 * 16];
__device__ __align__(16) unsigned g_w2ct[4 * 128 * 16];
__device__ __align__(16) unsigned g_w2gt[4 * 128 * 16];
__device__ __align__(16) unsigned g_we1t[4 * 128 * 16];
__device__ __align__(16) unsigned g_we2t[4 * 128 * 16];
__device__ __align__(16) unsigned g_wn1t[4 * 128 * 16];
__device__ __align__(16) unsigned g_wn2t[4 * 128 * 16];

__device__ __forceinline__ float tanhf_(float x) {
    float y;
    asm("tanh.approx.f32 %0, %1;" : "=f"(y) : "f"(x));
    return y;
}
__device__ __forceinline__ float sigmoidf_(float x) {
    return 0.5f * tanhf_(0.5f * x) + 0.5f;
}
__device__ __forceinline__ float siluf_(float x) { return x * sigmoidf_(x); }

__device__ __forceinline__ unsigned pack2(float x, float y) {
    __half2 h = __floats2half2_rn(x, y);
    return *reinterpret_cast<unsigned*>(&h);
}
__device__ __forceinline__ float2 unpack2(unsigned u) {
    __half2 h = *reinterpret_cast<__half2*>(&u);
    return __half22float2(h);
}
__device__ __forceinline__ unsigned sptr(const void* p) {
    return (unsigned)__cvta_generic_to_shared(p);
}
__device__ __forceinline__ void ldsm4(unsigned* r, unsigned a) {
    asm volatile("ldmatrix.sync.aligned.m8n8.x4.shared.b16 {%0,%1,%2,%3}, [%4];"
        : "=r"(r[0]), "=r"(r[1]), "=r"(r[2]), "=r"(r[3]) : "r"(a));
}
__device__ __forceinline__ void ldsm2(unsigned* r, unsigned a) {
    asm volatile("ldmatrix.sync.aligned.m8n8.x2.shared.b16 {%0,%1}, [%2];"
        : "=r"(r[0]), "=r"(r[1]) : "r"(a));
}
__device__ __forceinline__ void mma16(float* d, const unsigned* a, const unsigned* b) {
    asm volatile(
        "mma.sync.aligned.m16n8k16.row.col.f32.f16.f16.f32 "
        "{%0,%1,%2,%3}, {%4,%5,%6,%7}, {%8,%9}, {%0,%1,%2,%3};"
        : "+f"(d[0]), "+f"(d[1]), "+f"(d[2]), "+f"(d[3])
        : "r"(a[0]), "r"(a[1]), "r"(a[2]), "r"(a[3]), "r"(b[0]), "r"(b[1]));
}
__device__ __forceinline__ void cpa16(unsigned dst, const void* src) {
    asm volatile("cp.async.cg.shared.global [%0], [%1], 16;"
        :: "r"(dst), "l"(__cvta_generic_to_global(src)));
}
__device__ __forceinline__ void cpcommit() { asm volatile("cp.async.commit_group;"); }
__device__ __forceinline__ void cpwait0() { asm volatile("cp.async.wait_group 0;"); }
__device__ __forceinline__ void cpwait1() { asm volatile("cp.async.wait_group 1;"); }

__device__ __forceinline__ unsigned hss(unsigned a, unsigned b, unsigned c) {
    float2 fa = unpack2(a), fb = unpack2(b), fc = unpack2(c);
    return pack2(siluf_(fa.x + fb.x + fc.x), siluf_(fa.y + fb.y + fc.y));
}

// ---------------- k_prepA: weights + features fp16 (csr zero moved to side stream) ----
__global__ void k_prepA(const float* __restrict__ Wc1, const float* __restrict__ Wg1,
                        const float* __restrict__ Wc2, const float* __restrict__ Wg2,
                        const float* __restrict__ We1, const float* __restrict__ We2,
                        const float* __restrict__ Wn1, const float* __restrict__ Wn2,
                        const float* __restrict__ edge_feat, const float* __restrict__ node_feat)
{
    int i = blockIdx.x * blockDim.x + threadIdx.x;
    if (i < 12 * 256 * 16) {
        int kt = i >> 12;
        int r = i & 4095;
        int n = r >> 4, kpl = r & 15;
        int kp = kt * 16 + kpl;
        const float* W = (n < 128) ? Wc1 : Wg1;
        int c = n & 127;
        g_w1t[i] = pack2(W[(size_t)(2 * kp) * 128 + c], W[(size_t)(2 * kp + 1) * 128 + c]);
        return;
    }
    int j = i - 12 * 256 * 16;
    if (j < 6 * 8192) {
        int mtx = j >> 13;
        int r = j & 8191;
        int kt = r >> 11, rr = r & 2047;
        int n = rr >> 4, kpl = rr & 15;
        int kp = kt * 16 + kpl;
        const float* W; unsigned* O;
        switch (mtx) {
            case 0: W = Wc2; O = g_w2ct; break;
            case 1: W = Wg2; O = g_w2gt; break;
            case 2: W = We1; O = g_we1t; break;
            case 3: W = We2; O = g_we2t; break;
            case 4: W = Wn1; O = g_wn1t; break;
            default: W = Wn2; O = g_wn2t; break;
        }
        O[r] = pack2(W[(size_t)(2 * kp) * 128 + n], W[(size_t)(2 * kp + 1) * 128 + n]);
        return;
    }
    int k = j - 6 * 8192;
    if (k < EUN * 64) {
        g_ef16[k] = pack2(edge_feat[2 * (size_t)k], edge_feat[2 * (size_t)k + 1]);
        return;
    }
    int m = k - EUN * 64;
    if (m < NN * 64) {
        g_nf16[m] = pack2(node_feat[2 * (size_t)m], node_feat[2 * (size_t)m + 1]);
    }
}
#define PREPA_ITEMS (12 * 256 * 16 + 6 * 8192 + EUN * 64 + NN * 64)

// ---------------- k_pre1: GEMM1 partials (fp16 out) ----------
#define PE_BLKS ((EUN + 127) / 128)
#define PN_BLKS ((NN + 127) / 128)
#define PRE1_DYN ((2 * 2560 + 2 * 5120) * 4)
__global__ __launch_bounds__(512) void k_pre1()
{
    extern __shared__ __align__(16) unsigned dyn[];
    const int tid = threadIdx.x;
    const unsigned sbase = sptr(dyn);

    int bid = blockIdx.x;
    int rBase, rowsMax, ktbase;
    const unsigned* feat;
    unsigned* out;
    if (bid < PE_BLKS)                { rBase = bid * 128;                       rowsMax = EUN; ktbase = 0; feat = g_ef16; out = g_pe16; }
    else if (bid < PE_BLKS + PN_BLKS) { rBase = (bid - PE_BLKS) * 128;           rowsMax = NN;  ktbase = 4; feat = g_nf16; out = g_pt16; }
    else                              { rBase = (bid - PE_BLKS - PN_BLKS) * 128; rowsMax = NN;  ktbase = 8; feat = g_nf16; out = g_ps16; }

    const int w = tid >> 5, lane = tid & 31;
    const int wm = w & 3, wn = w >> 2;
    const int grp = lane >> 2, qid = lane & 3;

    const int afm = tid >> 2, afc = tid & 3;
    int arow = rBase + afm;
    if (arow >= rowsMax) arow = rowsMax - 1;
    const unsigned* arowp = feat + (size_t)arow * 64 + afc * 4;

#define P1_FILL_A(kt, nb) \
    cpa16(sbase + ((nb) * 2560 + afm * 20 + afc * 4) * 4, arowp + (kt) * 16)
#define P1_FILL_B(kt, nb) do { \
    _Pragma("unroll") \
    for (int l = 0; l < 2; l++) { \
        int i4 = tid + l * 512; \
        int n_ = i4 >> 2, q_ = i4 & 3; \
        cpa16(sbase + (5120 + (nb) * 5120 + n_ * 20 + q_ * 4) * 4, \
              &g_w1t[(ktbase + (kt)) * 4096 + n_ * 16 + q_ * 4]); \
    } } while (0)

    P1_FILL_A(0, 0); P1_FILL_B(0, 0); cpcommit();

    const unsigned aOff = ((wm * 32 + (lane & 7) + ((lane >> 3) & 1) * 8) * 20 + ((lane >> 4) & 1) * 4) * 4;
    const unsigned bOff = ((wn * 64 + (lane & 7)) * 20 + ((lane >> 3) & 1) * 4) * 4;

    float acc[2][8][4];
#pragma unroll
    for (int mi = 0; mi < 2; mi++)
#pragma unroll
        for (int ni = 0; ni < 8; ni++)
#pragma unroll
            for (int q = 0; q < 4; q++) acc[mi][ni][q] = 0.f;

    for (int kt = 0; kt < 4; kt++) {
        if (kt < 3) {
            P1_FILL_A(kt + 1, (kt + 1) & 1);
            P1_FILL_B(kt + 1, (kt + 1) & 1);
            cpcommit();
            cpwait1();
        } else {
            cpwait0();
        }
        __syncthreads();
        const unsigned aB = sbase + ((kt & 1) * 2560) * 4 + aOff;
        const unsigned bB = sbase + (5120 + (kt & 1) * 5120) * 4 + bOff;
#pragma unroll
        for (int k16 = 0; k16 < 2; k16++) {
            unsigned a[2][4], b[8][2];
#pragma unroll
            for (int mi = 0; mi < 2; mi++) ldsm4(a[mi], aB + (mi * 16 * 20 + k16 * 8) * 4);
#pragma unroll
            for (int ni = 0; ni < 8; ni++) ldsm2(b[ni], bB + (ni * 8 * 20 + k16 * 8) * 4);
#pragma unroll
            for (int mi = 0; mi < 2; mi++)
#pragma unroll
                for (int ni = 0; ni < 8; ni++) mma16(acc[mi][ni], a[mi], b[ni]);
        }
        __syncthreads();
    }

#pragma unroll
    for (int mi = 0; mi < 2; mi++)
#pragma unroll
        for (int h = 0; h < 2; h++) {
            int grow = rBase + wm * 32 + mi * 16 + grp + 8 * h;
            if (grow >= rowsMax) continue;
            unsigned* op = out + (size_t)grow * 128;
#pragma unroll
            for (int ni = 0; ni < 8; ni++) {
                int c = wn * 64 + ni * 8 + qid * 2;
                op[c >> 1] = pack2(acc[mi][ni][2 * h], acc[mi][ni][2 * h + 1]);
            }
        }
}

// ---------------- CSR build (side stream) ----------------
__global__ void k_zero_cnt() {
    int i = blockIdx.x * blockDim.x + threadIdx.x;
    if (i < NN) g_csr_cnt[i] = 0;
}
__global__ void k_hist(const int* __restrict__ tgt_i) {
    int i = blockIdx.x * blockDim.x + threadIdx.x;
    if (i < EDN) atomicAdd(&g_csr_cnt[tgt_i[i]], 1);
}
__global__ void k_scan_part() {
    __shared__ int sm[256];
    int t = threadIdx.x;
    int i = blockIdx.x * 256 + t;
    sm[t] = (i < NN) ? g_csr_cnt[i] : 0;
    __syncthreads();
#pragma unroll
    for (int off = 128; off > 0; off >>= 1) {
        if (t < off) sm[t] += sm[t + off];
        __syncthreads();
    }
    if (t == 0) g_part[blockIdx.x] = sm[0];
}
__global__ void k_scan_top(int nparts) {
    __shared__ int sm[256];
    int t = threadIdx.x;
    sm[t] = (t < nparts) ? g_part[t] : 0;
    __syncthreads();
#pragma unroll
    for (int off = 1; off < 256; off <<= 1) {
        int v = (t >= off) ? sm[t - off] : 0;
        __syncthreads();
        sm[t] += v;
        __syncthreads();
    }
    if (t < nparts) g_pbase[t] = (t == 0) ? 0 : sm[t - 1];
    if (t == 0) g_csr_off[NN] = EDN;
}
__global__ void k_scan_apply() {
    __shared__ int sm[256];
    int t = threadIdx.x;
    int i = blockIdx.x * 256 + t;
    int v = (i < NN) ? g_csr_cnt[i] : 0;
    sm[t] = v;
    __syncthreads();
#pragma unroll
    for (int off = 1; off < 256; off <<= 1) {
        int u = (t >= off) ? sm[t - off] : 0;
        __syncthreads();
        sm[t] += u;
        __syncthreads();
    }
    if (i < NN) {
        int excl = sm[t] - v + g_pbase[blockIdx.x];
        g_csr_off[i] = excl;
        g_csr_cur[i] = excl;
    }
}
__global__ void k_scatter(const int* __restrict__ tgt_i) {
    int i = blockIdx.x * blockDim.x + threadIdx.x;
    if (i < EDN) {
        int pos = atomicAdd(&g_csr_cur[tgt_i[i]], 1);
        g_csr_edges[pos] = i;
    }
}

// ============ k_mega: h-construction + stages A-C + fused edge output ============
#define FP 68
#define AcO 0
#define AgO 4352
#define BcO 8704
#define BgO 17408
#define MEGA_DYN ((BgO + 128 * FP) * 4)   // 104448 B
__global__ __launch_bounds__(256, 2) void k_mega(
    const int* __restrict__ tgt_i, const int* __restrict__ src_i,
    const float* __restrict__ lncg, const float* __restrict__ lncb,
    const float* __restrict__ lngg, const float* __restrict__ lngb,
    const float* __restrict__ smooth_weight, const float* __restrict__ W_env,
    const float* __restrict__ edge_feat, const float* __restrict__ edge_res_w,
    float* __restrict__ out_edge)
{
    extern __shared__ __align__(16) unsigned dyn[];
    __shared__ float Wenv_s[7][128];
    __shared__ float sw7[32][8];
    __shared__ float4 red[64][4];
    __shared__ int idxT[64], idxS[64];

    const int tid = threadIdx.x;
    const int uBase = blockIdx.x * 32;
    const int w = tid >> 5, lane = tid & 31;
    const int wm = w & 1, wn = w >> 1;
    const int grp = lane >> 2, qid = lane & 3;
    const unsigned sbase = sptr(dyn);

    if (tid < 64) {
        int m = tid;
        int e = (m < 32) ? (uBase + m) : (EUN + uBase + m - 32);
        idxT[m] = tgt_i[e];
    } else if (tid < 128) {
        int m = tid - 64;
        int e = (m < 32) ? (uBase + m) : (EUN + uBase + m - 32);
        idxS[m] = src_i[e];
    }
    __syncthreads();

    // cp.async gather: pt rows -> Bc, ps rows -> Bg
#pragma unroll
    for (int l = 0; l < 8; l++) {
        int i4 = tid + l * 256;
        int m = i4 >> 5, q = i4 & 31;
        cpa16(sbase + (BcO + m * 128 + q * 4) * 4, &g_pt16[(size_t)idxT[m] * 128 + q * 4]);
        cpa16(sbase + (BgO + m * 128 + q * 4) * 4, &g_ps16[(size_t)idxS[m] * 128 + q * 4]);
    }
    cpcommit();

    for (int f = tid; f < 224; f += 256) {
        int mm = f / 7, j = f % 7;
        sw7[mm][j] = smooth_weight[(size_t)(uBase + mm) * 7 + j];
    }
    for (int f = tid; f < 896; f += 256) Wenv_s[f >> 7][f & 127] = W_env[f];

    cpwait0();
    __syncthreads();

    // ---- h = silu(pe + pt + ps) -> Ac / Ag ----
#pragma unroll
    for (int l = 0; l < 8; l++) {
        int i4 = tid + l * 256;
        int m = i4 >> 5, q = i4 & 31;
        uint4 A = *(const uint4*)&g_pe16[(size_t)(uBase + (m & 31)) * 128 + q * 4];
        uint4 B = *(uint4*)&dyn[BcO + m * 128 + q * 4];
        uint4 C = *(uint4*)&dyn[BgO + m * 128 + q * 4];
        uint4 O;
        O.x = hss(A.x, B.x, C.x);
        O.y = hss(A.y, B.y, C.y);
        O.z = hss(A.z, B.z, C.z);
        O.w = hss(A.w, B.w, C.w);
        if (q < 16) *(uint4*)&dyn[AcO + m * FP + q * 4] = O;
        else        *(uint4*)&dyn[AgO + m * FP + (q - 16) * 4] = O;
    }
    __syncthreads();

    // weights Wc2/Wg2 -> Bc/Bg
#pragma unroll
    for (int l = 0; l < 8; l++) {
        int i4 = tid + l * 256;
        int n_ = i4 >> 4, q_ = i4 & 15;
        int off = (q_ >> 2) * 2048 + n_ * 16 + (q_ & 3) * 4;
        unsigned d = (n_ * FP + (q_ >> 2) * 16 + (q_ & 3) * 4) * 4;
        cpa16(sbase + BcO * 4 + d, &g_w2ct[off]);
        cpa16(sbase + BgO * 4 + d, &g_w2gt[off]);
    }
    cpcommit();
    cpwait0();
    __syncthreads();

    const unsigned aFragOff = ((lane & 7) + ((lane >> 3) & 1) * 8) * FP + ((lane >> 4) & 1) * 4;
    const unsigned bRow2 = ((wn * 32 + (lane & 7)) * FP + ((lane >> 3) & 1) * 4) * 4;

    // ---- stage A ----
    float accc[2][4][4], accg[2][4][4];
#pragma unroll
    for (int mi = 0; mi < 2; mi++)
#pragma unroll
        for (int ni = 0; ni < 4; ni++)
#pragma unroll
            for (int q = 0; q < 4; q++) { accc[mi][ni][q] = 0.f; accg[mi][ni][q] = 0.f; }
    {
        const unsigned aC = sbase + (AcO + wm * 32 * FP + aFragOff) * 4;
        const unsigned aG = sbase + (AgO + wm * 32 * FP + aFragOff) * 4;
        const unsigned bC = sbase + BcO * 4 + bRow2;
        const unsigned bG = sbase + BgO * 4 + bRow2;
#pragma unroll
        for (int k16 = 0; k16 < 8; k16++) {
            unsigned ac[2][4], ag[2][4], bc[4][2], bg[4][2];
#pragma unroll
            for (int mi = 0; mi < 2; mi++) {
                ldsm4(ac[mi], aC + (mi * 16 * FP + k16 * 8) * 4);
                ldsm4(ag[mi], aG + (mi * 16 * FP + k16 * 8) * 4);
            }
#pragma unroll
            for (int ni = 0; ni < 4; ni++) {
                ldsm2(bc[ni], bC + (ni * 8 * FP + k16 * 8) * 4);
                ldsm2(bg[ni], bG + (ni * 8 * FP + k16 * 8) * 4);
            }
#pragma unroll
            for (int mi = 0; mi < 2; mi++)
#pragma unroll
                for (int ni = 0; ni < 4; ni++) {
                    mma16(accc[mi][ni], ac[mi], bc[ni]);
                    mma16(accg[mi][ni], ag[mi], bg[ni]);
                }
        }
    }

    // ---- LN partial sums ----
#pragma unroll
    for (int mi = 0; mi < 2; mi++)
#pragma unroll
        for (int h = 0; h < 2; h++) {
            float sc = 0.f, sc2 = 0.f, sg = 0.f, sg2 = 0.f;
#pragma unroll
            for (int ni = 0; ni < 4; ni++) {
                float c0 = accc[mi][ni][2 * h], c1 = accc[mi][ni][2 * h + 1];
                float g0 = accg[mi][ni][2 * h], g1 = accg[mi][ni][2 * h + 1];
                sc += c0 + c1; sc2 += c0 * c0 + c1 * c1;
                sg += g0 + g1; sg2 += g0 * g0 + g1 * g1;
            }
#pragma unroll
            for (int off = 1; off < 4; off <<= 1) {
                sc  += __shfl_xor_sync(0xffffffffu, sc,  off, 4);
                sc2 += __shfl_xor_sync(0xffffffffu, sc2, off, 4);
                sg  += __shfl_xor_sync(0xffffffffu, sg,  off, 4);
                sg2 += __shfl_xor_sync(0xffffffffu, sg2, off, 4);
            }
            if (qid == 0) red[wm * 32 + mi * 16 + grp + 8 * h][wn] = make_float4(sc, sc2, sg, sg2);
        }
    __syncthreads();

    // prefetch We1 / We2 into Bc/Bg
#pragma unroll
    for (int l = 0; l < 8; l++) {
        int i4 = tid + l * 256;
        int n_ = i4 >> 4, q_ = i4 & 15;
        int off = (q_ >> 2) * 2048 + n_ * 16 + (q_ & 3) * 4;
        unsigned d = (n_ * FP + (q_ >> 2) * 16 + (q_ & 3) * 4) * 4;
        cpa16(sbase + BcO * 4 + d, &g_we1t[off]);
        cpa16(sbase + BgO * 4 + d, &g_we2t[off]);
    }
    cpcommit();

    // ---- LN epilogue: nl -> t1, msg -> g_msg16 ----
#pragma unroll
    for (int mi = 0; mi < 2; mi++)
#pragma unroll
        for (int h = 0; h < 2; h++) {
            int rloc = wm * 32 + mi * 16 + grp + 8 * h;
            float4 p0 = red[rloc][0], p1 = red[rloc][1], p2 = red[rloc][2], p3 = red[rloc][3];
            float sc = p0.x + p1.x + p2.x + p3.x;
            float sc2 = p0.y + p1.y + p2.y + p3.y;
            float sg = p0.z + p1.z + p2.z + p3.z;
            float sg2 = p0.w + p1.w + p2.w + p3.w;
            float mc = sc * (1.f / 128.f);
            float vc = fmaxf(sc2 * (1.f / 128.f) - mc * mc, 0.f);
            float rc = rsqrtf(vc + 1e-5f);
            float mg = sg * (1.f / 128.f);
            float vg = fmaxf(sg2 * (1.f / 128.f) - mg * mg, 0.f);
            float rg = rsqrtf(vg + 1e-5f);

            int rr = rloc & 31;
            float s0 = sw7[rr][0], s1 = sw7[rr][1], s2 = sw7[rr][2], s3 = sw7[rr][3];
            float s4 = sw7[rr][4], s5 = sw7[rr][5], s6 = sw7[rr][6];
            size_t e = (rloc < 32) ? (size_t)(uBase + rloc) : (size_t)(EUN + uBase + rloc - 32);
            unsigned* mp = g_msg16 + e * 64;
#pragma unroll
            for (int ni = 0; ni < 4; ni++) {
                int c = wn * 32 + ni * 8 + qid * 2;
                float hc0 = (accc[mi][ni][2 * h] - mc) * rc * __ldg(&lncg[c]) + __ldg(&lncb[c]);
                float hg0 = (accg[mi][ni][2 * h] - mg) * rg * __ldg(&lngg[c]) + __ldg(&lngb[c]);
                float nl0 = siluf_(hc0) * sigmoidf_(hg0);
                float hc1 = (accc[mi][ni][2 * h + 1] - mc) * rc * __ldg(&lncg[c + 1]) + __ldg(&lncb[c + 1]);
                float hg1 = (accg[mi][ni][2 * h + 1] - mg) * rg * __ldg(&lngg[c + 1]) + __ldg(&lngb[c + 1]);
                float nl1 = siluf_(hc1) * sigmoidf_(hg1);
                dyn[AcO + rloc * FP + (c >> 1)] = pack2(nl0, nl1);
                float sw0 = s0 * Wenv_s[0][c] + s1 * Wenv_s[1][c] + s2 * Wenv_s[2][c]
                          + s3 * Wenv_s[3][c] + s4 * Wenv_s[4][c] + s5 * Wenv_s[5][c]
                          + s6 * Wenv_s[6][c];
                float sw1 = s0 * Wenv_s[0][c + 1] + s1 * Wenv_s[1][c + 1] + s2 * Wenv_s[2][c + 1]
                          + s3 * Wenv_s[3][c + 1] + s4 * Wenv_s[4][c + 1] + s5 * Wenv_s[5][c + 1]
                          + s6 * Wenv_s[6][c + 1];
                mp[c >> 1] = pack2(nl0 * sw0, nl1 * sw1);
            }
        }
    cpwait0();
    __syncthreads();

    // ---- stage B ----
    float acc1[2][4][4];
#pragma unroll
    for (int mi = 0; mi < 2; mi++)
#pragma unroll
        for (int ni = 0; ni < 4; ni++)
#pragma unroll
            for (int q = 0; q < 4; q++) acc1[mi][ni][q] = 0.f;
    {
        const unsigned aT = sbase + (AcO + wm * 32 * FP + aFragOff) * 4;
        const unsigned bW = sbase + BcO * 4 + bRow2;
#pragma unroll
        for (int k16 = 0; k16 < 8; k16++) {
            unsigned a[2][4], b[4][2];
#pragma unroll
            for (int mi = 0; mi < 2; mi++) ldsm4(a[mi], aT + (mi * 16 * FP + k16 * 8) * 4);
#pragma unroll
            for (int ni = 0; ni < 4; ni++) ldsm2(b[ni], bW + (ni * 8 * FP + k16 * 8) * 4);
#pragma unroll
            for (int mi = 0; mi < 2; mi++)
#pragma unroll
                for (int ni = 0; ni < 4; ni++) mma16(acc1[mi][ni], a[mi], b[ni]);
        }
    }
#pragma unroll
    for (int mi = 0; mi < 2; mi++)
#pragma unroll
        for (int h = 0; h < 2; h++) {
            int rloc = wm * 32 + mi * 16 + grp + 8 * h;
#pragma unroll
            for (int ni = 0; ni < 4; ni++) {
                int c = wn * 32 + ni * 8 + qid * 2;
                dyn[AgO + rloc * FP + (c >> 1)] =
                    pack2(siluf_(acc1[mi][ni][2 * h]), siluf_(acc1[mi][ni][2 * h + 1]));
            }
        }
    __syncthreads();

    // ---- stage C ----
    float acc2[2][4][4];
#pragma unroll
    for (int mi = 0; mi < 2; mi++)
#pragma unroll
        for (int ni = 0; ni < 4; ni++)
#pragma unroll
            for (int q = 0; q < 4; q++) acc2[mi][ni][q] = 0.f;
    {
        const unsigned aT = sbase + (AgO + wm * 32 * FP + aFragOff) * 4;
        const unsigned bW = sbase + BgO * 4 + bRow2;
#pragma unroll
        for (int k16 = 0; k16 < 8; k16++) {
            unsigned a[2][4], b[4][2];
#pragma unroll
            for (int mi = 0; mi < 2; mi++) ldsm4(a[mi], aT + (mi * 16 * FP + k16 * 8) * 4);
#pragma unroll
            for (int ni = 0; ni < 4; ni++) ldsm2(b[ni], bW + (ni * 8 * FP + k16 * 8) * 4);
#pragma unroll
            for (int mi = 0; mi < 2; mi++)
#pragma unroll
                for (int ni = 0; ni < 4; ni++) mma16(acc2[mi][ni], a[mi], b[ni]);
        }
    }
#pragma unroll
    for (int mi = 0; mi < 2; mi++)
#pragma unroll
        for (int h = 0; h < 2; h++) {
            int rloc = wm * 32 + mi * 16 + grp + 8 * h;
#pragma unroll
            for (int ni = 0; ni < 4; ni++) {
                int c = wn * 32 + ni * 8 + qid * 2;
                dyn[AcO + rloc * FP + (c >> 1)] = pack2(acc2[mi][ni][2 * h], acc2[mi][ni][2 * h + 1]);
            }
        }
    __syncthreads();

    // ---- fused edge output ----
#pragma unroll
    for (int it = 0; it < 4; it++) {
        int f = tid + it * 256;
        int row = f >> 5, cw = f & 31;
        uint2 da = *(uint2*)&dyn[AcO + row * FP + cw * 2];
        uint2 db = *(uint2*)&dyn[AcO + (row + 32) * FP + cw * 2];
        float2 a0 = unpack2(da.x), a1 = unpack2(da.y);
        float2 b0 = unpack2(db.x), b1 = unpack2(db.y);
        size_t u = (size_t)(uBase + row);
        float4 ef = *(const float4*)&edge_feat[u * 128 + cw * 4];
        float4 rw = *(const float4*)&edge_res_w[cw * 4];
        float4 o;
        o.x = (a0.x + b0.x) * 0.5f + rw.x * ef.x;
        o.y = (a0.y + b0.y) * 0.5f + rw.y * ef.y;
        o.z = (a1.x + b1.x) * 0.5f + rw.z * ef.z;
        o.w = (a1.y + b1.y) * 0.5f + rw.w * ef.w;
        *(float4*)&out_edge[u * 128 + cw * 4] = o;
    }
}

// ============ k_node_fused ============
__global__ __launch_bounds__(256) void k_node_fused(
    const float* __restrict__ node_feat, const float* __restrict__ node_res_w,
    float* __restrict__ out_node)
{
    __shared__ __align__(16) unsigned As[64 * 68];
    __shared__ __align__(16) unsigned Bs[128 * 20];
    __shared__ __align__(16) unsigned t1[64 * 68];

    const int tid = threadIdx.x;
    const int nBase = blockIdx.x * 64;
    const int w = tid >> 5, lane = tid & 31;
    const int wm = w & 1, wn = w >> 1;
    const int grp = lane >> 2, qid = lane & 3;

    for (int s = 0; s < 8; s++) {
        int m = w * 8 + s;
        int node = nBase + m;
        float4 acc = make_float4(0.f, 0.f, 0.f, 0.f);
        if (node < NN) {
            int b = g_csr_off[node], e2 = g_csr_off[node + 1];
            int j = b;
            for (; j + 1 < e2; j += 2) {
                int ed0 = g_csr_edges[j], ed1 = g_csr_edges[j + 1];
                uint2 v0 = *(const uint2*)&g_msg16[(size_t)ed0 * 64 + lane * 2];
                uint2 v1 = *(const uint2*)&g_msg16[(size_t)ed1 * 64 + lane * 2];
                float2 a0 = unpack2(v0.x), b0 = unpack2(v0.y);
                float2 a1 = unpack2(v1.x), b1 = unpack2(v1.y);
                acc.x += a0.x + a1.x; acc.y += a0.y + a1.y;
                acc.z += b0.x + b1.x; acc.w += b0.y + b1.y;
            }
            if (j < e2) {
                int ed = g_csr_edges[j];
                uint2 v = *(const uint2*)&g_msg16[(size_t)ed * 64 + lane * 2];
                float2 a = unpack2(v.x), bb = unpack2(v.y);
                acc.x += a.x; acc.y += a.y; acc.z += bb.x; acc.w += bb.y;
            }
        }
        *(uint2*)&As[m * 68 + lane * 2] = make_uint2(pack2(acc.x, acc.y), pack2(acc.z, acc.w));
    }
    __syncthreads();

    const int aRow = wm * 32 + (lane & 7) + ((lane >> 3) & 1) * 8;
    const int aCol = ((lane >> 4) & 1) * 4;
    const unsigned aBase = sptr(As) + (aRow * 68 + aCol) * 4;
    const unsigned tBase = sptr(t1) + (aRow * 68 + aCol) * 4;
    const unsigned bBase = sptr(Bs) + ((wn * 32 + (lane & 7)) * 20 + ((lane >> 3) & 1) * 4) * 4;

    float acc[2][4][4];
#pragma unroll
    for (int mi = 0; mi < 2; mi++)
#pragma unroll
        for (int ni = 0; ni < 4; ni++)
#pragma unroll
            for (int q = 0; q < 4; q++) acc[mi][ni][q] = 0.f;

    for (int kt = 0; kt < 4; kt++) {
        {
            const uint4* src = (const uint4*)&g_wn1t[kt * 2048];
#pragma unroll
            for (int l = 0; l < 2; l++) {
                int i4 = tid + l * 256;
                int n = i4 >> 2, wq = (i4 & 3) * 4;
                *(uint4*)&Bs[n * 20 + wq] = src[i4];
            }
        }
        __syncthreads();
#pragma unroll
        for (int k16 = 0; k16 < 2; k16++) {
            unsigned a[2][4], b[4][2];
#pragma unroll
            for (int mi = 0; mi < 2; mi++)
                ldsm4(a[mi], aBase + (mi * 16 * 68 + kt * 16 + k16 * 8) * 4);
#pragma unroll
            for (int ni = 0; ni < 4; ni++) ldsm2(b[ni], bBase + (ni * 8 * 20 + k16 * 8) * 4);
#pragma unroll
            for (int mi = 0; mi < 2; mi++)
#pragma unroll
                for (int ni = 0; ni < 4; ni++) mma16(acc[mi][ni], a[mi], b[ni]);
        }
        __syncthreads();
    }
#pragma unroll
    for (int mi = 0; mi < 2; mi++)
#pragma unroll
        for (int h = 0; h < 2; h++) {
            int r = wm * 32 + mi * 16 + grp + 8 * h;
#pragma unroll
            for (int ni = 0; ni < 4; ni++) {
                int c = wn * 32 + ni * 8 + qid * 2;
                t1[r * 68 + (c >> 1)] = pack2(siluf_(acc[mi][ni][2 * h]), siluf_(acc[mi][ni][2 * h + 1]));
            }
        }
    __syncthreads();

    float acc2[2][4][4];
#pragma unroll
    for (int mi = 0; mi < 2; mi++)
#pragma unroll
        for (int ni = 0; ni < 4; ni++)
#pragma unroll
            for (int q = 0; q < 4; q++) acc2[mi][ni][q] = 0.f;

    for (int kt = 0; kt < 4; kt++) {
        {
            const uint4* src = (const uint4*)&g_wn2t[kt * 2048];
#pragma unroll
            for (int l = 0; l < 2; l++) {
                int i4 = tid + l * 256;
                int n = i4 >> 2, wq = (i4 & 3) * 4;
                *(uint4*)&Bs[n * 20 + wq] = src[i4];
            }
        }
        __syncthreads();
#pragma unroll
        for (int k16 = 0; k16 < 2; k16++) {
            unsigned a[2][4], b[4][2];
#pragma unroll
            for (int mi = 0; mi < 2; mi++)
                ldsm4(a[mi], tBase + (mi * 16 * 68 + kt * 16 + k16 * 8) * 4);
#pragma unroll
            for (int ni = 0; ni < 4; ni++) ldsm2(b[ni], bBase + (ni * 8 * 20 + k16 * 8) * 4);
#pragma unroll
            for (int mi = 0; mi < 2; mi++)
#pragma unroll
                for (int ni = 0; ni < 4; ni++) mma16(acc2[mi][ni], a[mi], b[ni]);
        }
        __syncthreads();
    }

#pragma unroll
    for (int mi = 0; mi < 2; mi++)
#pragma unroll
        for (int h = 0; h < 2; h++) {
            int row = nBase + wm * 32 + mi * 16 + grp + 8 * h;
            if (row >= NN) continue;
            const float* nf = node_feat + ((size_t)row << 7);
            float* op = out_node + ((size_t)row << 7);
#pragma unroll
            for (int ni = 0; ni < 4; ni++) {
                int c = wn * 32 + ni * 8 + qid * 2;
                float o0 = acc2[mi][ni][2 * h]     + __ldg(&node_res_w[c])     * nf[c];
                float o1 = acc2[mi][ni][2 * h + 1] + __ldg(&node_res_w[c + 1]) * nf[c + 1];
                *(float2*)(op + c) = make_float2(o0, o1);
            }
        }
}

// ---------------- launch: fork/join CSR chain on a side stream ----------------
extern "C" void kernel_launch(void* const* d_in, const int* in_sizes, int n_in,
                              void* d_out, int out_size)
{
    (void)in_sizes; (void)n_in; (void)out_size;
    const float* node_feat     = (const float*)d_in[0];
    const float* edge_feat     = (const float*)d_in[1];
    const float* smooth_weight = (const float*)d_in[2];
    const int*   source_index  = (const int*)d_in[3];
    const int*   target_index  = (const int*)d_in[4];
    const float* W_env         = (const float*)d_in[6];
    const float* Wc1           = (const float*)d_in[7];
    const float* Wc2           = (const float*)d_in[8];
    const float* Wg1           = (const float*)d_in[9];
    const float* Wg2           = (const float*)d_in[10];
    const float* ln_c_g        = (const float*)d_in[11];
    const float* ln_c_b        = (const float*)d_in[12];
    const float* ln_g_g        = (const float*)d_in[13];
    const float* ln_g_b        = (const float*)d_in[14];
    const float* Wn1           = (const float*)d_in[15];
    const float* Wn2           = (const float*)d_in[16];
    const float* We1           = (const float*)d_in[17];
    const float* We2           = (const float*)d_in[18];
    const float* node_res_w    = (const float*)d_in[19];
    const float* edge_res_w    = (const float*)d_in[20];

    float* out_node = (float*)d_out;
    float* out_edge = out_node + (size_t)NN * 128;

    static cudaStream_t s2 = nullptr;
    static cudaEvent_t evFork = nullptr, evJoin = nullptr;
    static bool attrsSet = false;
    if (!s2) {
        cudaStreamCreateWithFlags(&s2, cudaStreamNonBlocking);
        cudaEventCreateWithFlags(&evFork, cudaEventDisableTiming);
        cudaEventCreateWithFlags(&evJoin, cudaEventDisableTiming);
    }
    if (!attrsSet) {
        cudaFuncSetAttribute(k_mega, cudaFuncAttributeMaxDynamicSharedMemorySize, MEGA_DYN);
        cudaFuncSetAttribute(k_pre1, cudaFuncAttributeMaxDynamicSharedMemorySize, PRE1_DYN);
        attrsSet = true;
    }

    const int NPART = (NN + 255) / 256;

    // fork: CSR chain on s2, independent of the main compute chain
    cudaEventRecord(evFork, 0);
    cudaStreamWaitEvent(s2, evFork, 0);
    k_zero_cnt<<<(NN + 255) / 256, 256, 0, s2>>>();
    k_hist<<<(EDN + 255) / 256, 256, 0, s2>>>(target_index);
    k_scan_part<<<NPART, 256, 0, s2>>>();
    k_scan_top<<<1, 256, 0, s2>>>(NPART);
    k_scan_apply<<<NPART, 256, 0, s2>>>();
    k_scatter<<<(EDN + 255) / 256, 256, 0, s2>>>(target_index);
    cudaEventRecord(evJoin, s2);

    // main chain
    k_prepA<<<(PREPA_ITEMS + 255) / 256, 256>>>(Wc1, Wg1, Wc2, Wg2, We1, We2, Wn1, Wn2,
                                                edge_feat, node_feat);
    k_pre1<<<PE_BLKS + 2 * PN_BLKS, 512, PRE1_DYN>>>();

    k_mega<<<EUN / 32, 256, MEGA_DYN>>>(target_index, source_index,
                                        ln_c_g, ln_c_b, ln_g_g, ln_g_b,
                                        smooth_weight, W_env,
                                        edge_feat, edge_res_w, out_edge);

    // join: node_fused needs both k_mega (msg) and the CSR chain
    cudaStreamWaitEvent(0, evJoin, 0);
    k_node_fused<<<(NN + 63) / 64, 256>>>(node_feat, node_res_w, out_node);
}

// round 16
// speedup vs baseline: 1.8995x; 1.0268x over previous
#include <cuda_runtime.h>
#include <cuda_fp16.h>

#define NN  50000
#define EUN 200000
#define EDN 400000

// ---------------- scratch (device globals; no allocation) ----------------
__device__ __align__(16) unsigned g_msg16[EDN * 64];  // envelope-scaled messages fp16
// GEMM1 partials, fp16 packed: [row][128 words] (256 halves)
__device__ __align__(16) unsigned g_pe16[(size_t)EUN * 128];
__device__ __align__(16) unsigned g_pt16[(size_t)NN * 128];
__device__ __align__(16) unsigned g_ps16[(size_t)NN * 128];
// CSR over target_index
__device__ int g_csr_cnt[NN];
__device__ int g_csr_off[NN + 1];
__device__ int g_csr_cur[NN];
__device__ int g_csr_edges[EDN];
__device__ int g_part[256];
__device__ int g_pbase[256];

// pre-transposed fp16 weights, tile-blocked: [ktile32][n][16 words]
__device__ __align__(16) unsigned g_w1t[12 * 256 * 16];
__device__ __align__(16) unsigned g_w2ct[4 * 128 * 16];
__device__ __align__(16) unsigned g_w2gt[4 * 128 * 16];
__device__ __align__(16) unsigned g_we1t[4 * 128 * 16];
__device__ __align__(16) unsigned g_we2t[4 * 128 * 16];
__device__ __align__(16) unsigned g_wn1t[4 * 128 * 16];
__device__ __align__(16) unsigned g_wn2t[4 * 128 * 16];

__device__ __forceinline__ float tanhf_(float x) {
    float y;
    asm("tanh.approx.f32 %0, %1;" : "=f"(y) : "f"(x));
    return y;
}
__device__ __forceinline__ float sigmoidf_(float x) {
    return 0.5f * tanhf_(0.5f * x) + 0.5f;
}
__device__ __forceinline__ float siluf_(float x) { return x * sigmoidf_(x); }

__device__ __forceinline__ unsigned pack2(float x, float y) {
    __half2 h = __floats2half2_rn(x, y);
    return *reinterpret_cast<unsigned*>(&h);
}
__device__ __forceinline__ float2 unpack2(unsigned u) {
    __half2 h = *reinterpret_cast<__half2*>(&u);
    return __half22float2(h);
}
__device__ __forceinline__ unsigned sptr(const void* p) {
    return (unsigned)__cvta_generic_to_shared(p);
}
__device__ __forceinline__ void ldsm4(unsigned* r, unsigned a) {
    asm volatile("ldmatrix.sync.aligned.m8n8.x4.shared.b16 {%0,%1,%2,%3}, [%4];"
        : "=r"(r[0]), "=r"(r[1]), "=r"(r[2]), "=r"(r[3]) : "r"(a));
}
__device__ __forceinline__ void ldsm2(unsigned* r, unsigned a) {
    asm volatile("ldmatrix.sync.aligned.m8n8.x2.shared.b16 {%0,%1}, [%2];"
        : "=r"(r[0]), "=r"(r[1]) : "r"(a));
}
__device__ __forceinline__ void mma16(float* d, const unsigned* a, const unsigned* b) {
    asm volatile(
        "mma.sync.aligned.m16n8k16.row.col.f32.f16.f16.f32 "
        "{%0,%1,%2,%3}, {%4,%5,%6,%7}, {%8,%9}, {%0,%1,%2,%3};"
        : "+f"(d[0]), "+f"(d[1]), "+f"(d[2]), "+f"(d[3])
        : "r"(a[0]), "r"(a[1]), "r"(a[2]), "r"(a[3]), "r"(b[0]), "r"(b[1]));
}
__device__ __forceinline__ void cpa16(unsigned dst, const void* src) {
    asm volatile("cp.async.cg.shared.global [%0], [%1], 16;"
        :: "r"(dst), "l"(__cvta_generic_to_global(src)));
}
__device__ __forceinline__ void cpcommit() { asm volatile("cp.async.commit_group;"); }
__device__ __forceinline__ void cpwait0() { asm volatile("cp.async.wait_group 0;"); }
__device__ __forceinline__ void cpwait1() { asm volatile("cp.async.wait_group 1;"); }

__device__ __forceinline__ unsigned hss(unsigned a, unsigned b, unsigned c) {
    float2 fa = unpack2(a), fb = unpack2(b), fc = unpack2(c);
    return pack2(siluf_(fa.x + fb.x + fc.x), siluf_(fa.y + fb.y + fc.y));
}

// ---------------- k_prepA: weights -> fp16 transposed tile-blocked (weights only) ----
__global__ void k_prepA(const float* __restrict__ Wc1, const float* __restrict__ Wg1,
                        const float* __restrict__ Wc2, const float* __restrict__ Wg2,
                        const float* __restrict__ We1, const float* __restrict__ We2,
                        const float* __restrict__ Wn1, const float* __restrict__ Wn2)
{
    int i = blockIdx.x * blockDim.x + threadIdx.x;
    if (i < 12 * 256 * 16) {
        int kt = i >> 12;
        int r = i & 4095;
        int n = r >> 4, kpl = r & 15;
        int kp = kt * 16 + kpl;
        const float* W = (n < 128) ? Wc1 : Wg1;
        int c = n & 127;
        g_w1t[i] = pack2(W[(size_t)(2 * kp) * 128 + c], W[(size_t)(2 * kp + 1) * 128 + c]);
        return;
    }
    int j = i - 12 * 256 * 16;
    if (j < 6 * 8192) {
        int mtx = j >> 13;
        int r = j & 8191;
        int kt = r >> 11, rr = r & 2047;
        int n = rr >> 4, kpl = rr & 15;
        int kp = kt * 16 + kpl;
        const float* W; unsigned* O;
        switch (mtx) {
            case 0: W = Wc2; O = g_w2ct; break;
            case 1: W = Wg2; O = g_w2gt; break;
            case 2: W = We1; O = g_we1t; break;
            case 3: W = We2; O = g_we2t; break;
            case 4: W = Wn1; O = g_wn1t; break;
            default: W = Wn2; O = g_wn2t; break;
        }
        O[r] = pack2(W[(size_t)(2 * kp) * 128 + n], W[(size_t)(2 * kp + 1) * 128 + n]);
    }
}
#define PREPA_ITEMS (12 * 256 * 16 + 6 * 8192)

// ---------------- k_pre1: GEMM1 partials, convert-on-fill from fp32 features --------
// A tile: full K=128, pitch 68 words; B double-buffered per ktile.
#define PE_BLKS ((EUN + 127) / 128)
#define PN_BLKS ((NN + 127) / 128)
#define P1_B0 (128 * 68)                      // B buffers start (words)
#define PRE1_DYN ((P1_B0 + 2 * 5120) * 4)     // 75776 B
__global__ __launch_bounds__(512) void k_pre1(const float* __restrict__ edge_feat,
                                              const float* __restrict__ node_feat)
{
    extern __shared__ __align__(16) unsigned dyn[];
    const int tid = threadIdx.x;
    const unsigned sbase = sptr(dyn);

    int bid = blockIdx.x;
    int rBase, rowsMax, ktbase;
    const float* feat;
    unsigned* out;
    if (bid < PE_BLKS)                { rBase = bid * 128;                       rowsMax = EUN; ktbase = 0; feat = edge_feat; out = g_pe16; }
    else if (bid < PE_BLKS + PN_BLKS) { rBase = (bid - PE_BLKS) * 128;           rowsMax = NN;  ktbase = 4; feat = node_feat; out = g_pt16; }
    else                              { rBase = (bid - PE_BLKS - PN_BLKS) * 128; rowsMax = NN;  ktbase = 8; feat = node_feat; out = g_ps16; }

    const int w = tid >> 5, lane = tid & 31;
    const int wm = w & 3, wn = w >> 2;
    const int grp = lane >> 2, qid = lane & 3;

#define P1_FILL_B(kt, nb) do { \
    _Pragma("unroll") \
    for (int l = 0; l < 2; l++) { \
        int i4 = tid + l * 512; \
        int n_ = i4 >> 2, q_ = i4 & 3; \
        cpa16(sbase + (P1_B0 + (nb) * 5120 + n_ * 20 + q_ * 4) * 4, \
              &g_w1t[(ktbase + (kt)) * 4096 + n_ * 16 + q_ * 4]); \
    } } while (0)

    P1_FILL_B(0, 0); cpcommit();

    // A fill: read fp32 feature rows, convert to fp16, store full K=128 (pitch 68)
    {
        int afm = tid >> 2, afc = tid & 3;
        int row = rBase + afm;
        if (row >= rowsMax) row = rowsMax - 1;
        const float* sp = feat + (size_t)row * 128 + afc * 32;
#pragma unroll
        for (int p = 0; p < 4; p++) {
            float4 v0 = *(const float4*)(sp + p * 8);
            float4 v1 = *(const float4*)(sp + p * 8 + 4);
            *(uint4*)&dyn[afm * 68 + afc * 16 + p * 4] =
                make_uint4(pack2(v0.x, v0.y), pack2(v0.z, v0.w),
                           pack2(v1.x, v1.y), pack2(v1.z, v1.w));
        }
    }

    const unsigned aOff = ((wm * 32 + (lane & 7) + ((lane >> 3) & 1) * 8) * 68 + ((lane >> 4) & 1) * 4) * 4;
    const unsigned bOff = ((wn * 64 + (lane & 7)) * 20 + ((lane >> 3) & 1) * 4) * 4;

    float acc[2][8][4];
#pragma unroll
    for (int mi = 0; mi < 2; mi++)
#pragma unroll
        for (int ni = 0; ni < 8; ni++)
#pragma unroll
            for (int q = 0; q < 4; q++) acc[mi][ni][q] = 0.f;

    for (int kt = 0; kt < 4; kt++) {
        if (kt < 3) {
            P1_FILL_B(kt + 1, (kt + 1) & 1);
            cpcommit();
            cpwait1();
        } else {
            cpwait0();
        }
        __syncthreads();
        const unsigned aB = sbase + aOff + (kt * 16) * 4;
        const unsigned bB = sbase + (P1_B0 + (kt & 1) * 5120) * 4 + bOff;
#pragma unroll
        for (int k16 = 0; k16 < 2; k16++) {
            unsigned a[2][4], b[8][2];
#pragma unroll
            for (int mi = 0; mi < 2; mi++) ldsm4(a[mi], aB + (mi * 16 * 68 + k16 * 8) * 4);
#pragma unroll
            for (int ni = 0; ni < 8; ni++) ldsm2(b[ni], bB + (ni * 8 * 20 + k16 * 8) * 4);
#pragma unroll
            for (int mi = 0; mi < 2; mi++)
#pragma unroll
                for (int ni = 0; ni < 8; ni++) mma16(acc[mi][ni], a[mi], b[ni]);
        }
        __syncthreads();
    }

#pragma unroll
    for (int mi = 0; mi < 2; mi++)
#pragma unroll
        for (int h = 0; h < 2; h++) {
            int grow = rBase + wm * 32 + mi * 16 + grp + 8 * h;
            if (grow >= rowsMax) continue;
            unsigned* op = out + (size_t)grow * 128;
#pragma unroll
            for (int ni = 0; ni < 8; ni++) {
                int c = wn * 64 + ni * 8 + qid * 2;
                op[c >> 1] = pack2(acc[mi][ni][2 * h], acc[mi][ni][2 * h + 1]);
            }
        }
}

// ---------------- CSR build (side stream) ----------------
__global__ void k_zero_cnt() {
    int i = blockIdx.x * blockDim.x + threadIdx.x;
    if (i < NN) g_csr_cnt[i] = 0;
}
__global__ void k_hist(const int* __restrict__ tgt_i) {
    int i = blockIdx.x * blockDim.x + threadIdx.x;
    if (i < EDN) atomicAdd(&g_csr_cnt[tgt_i[i]], 1);
}
__global__ void k_scan_part() {
    __shared__ int sm[256];
    int t = threadIdx.x;
    int i = blockIdx.x * 256 + t;
    sm[t] = (i < NN) ? g_csr_cnt[i] : 0;
    __syncthreads();
#pragma unroll
    for (int off = 128; off > 0; off >>= 1) {
        if (t < off) sm[t] += sm[t + off];
        __syncthreads();
    }
    if (t == 0) g_part[blockIdx.x] = sm[0];
}
__global__ void k_scan_top(int nparts) {
    __shared__ int sm[256];
    int t = threadIdx.x;
    sm[t] = (t < nparts) ? g_part[t] : 0;
    __syncthreads();
#pragma unroll
    for (int off = 1; off < 256; off <<= 1) {
        int v = (t >= off) ? sm[t - off] : 0;
        __syncthreads();
        sm[t] += v;
        __syncthreads();
    }
    if (t < nparts) g_pbase[t] = (t == 0) ? 0 : sm[t - 1];
    if (t == 0) g_csr_off[NN] = EDN;
}
__global__ void k_scan_apply() {
    __shared__ int sm[256];
    int t = threadIdx.x;
    int i = blockIdx.x * 256 + t;
    int v = (i < NN) ? g_csr_cnt[i] : 0;
    sm[t] = v;
    __syncthreads();
#pragma unroll
    for (int off = 1; off < 256; off <<= 1) {
        int u = (t >= off) ? sm[t - off] : 0;
        __syncthreads();
        sm[t] += u;
        __syncthreads();
    }
    if (i < NN) {
        int excl = sm[t] - v + g_pbase[blockIdx.x];
        g_csr_off[i] = excl;
        g_csr_cur[i] = excl;
    }
}
__global__ void k_scatter(const int* __restrict__ tgt_i) {
    int i = blockIdx.x * blockDim.x + threadIdx.x;
    if (i < EDN) {
        int pos = atomicAdd(&g_csr_cur[tgt_i[i]], 1);
        g_csr_edges[pos] = i;
    }
}

// ============ k_mega: h-construction + stages A-C + fused edge output ============
#define FP 68
#define AcO 0
#define AgO 4352
#define BcO 8704
#define BgO 17408
#define MEGA_DYN ((BgO + 128 * FP) * 4)   // 104448 B
__global__ __launch_bounds__(256, 2) void k_mega(
    const int* __restrict__ tgt_i, const int* __restrict__ src_i,
    const float* __restrict__ lncg, const float* __restrict__ lncb,
    const float* __restrict__ lngg, const float* __restrict__ lngb,
    const float* __restrict__ smooth_weight, const float* __restrict__ W_env,
    const float* __restrict__ edge_feat, const float* __restrict__ edge_res_w,
    float* __restrict__ out_edge)
{
    extern __shared__ __align__(16) unsigned dyn[];
    __shared__ float Wenv_s[7][128];
    __shared__ float sw7[32][8];
    __shared__ float4 red[64][4];
    __shared__ int idxT[64], idxS[64];

    const int tid = threadIdx.x;
    const int uBase = blockIdx.x * 32;
    const int w = tid >> 5, lane = tid & 31;
    const int wm = w & 1, wn = w >> 1;
    const int grp = lane >> 2, qid = lane & 3;
    const unsigned sbase = sptr(dyn);

    if (tid < 64) {
        int m = tid;
        int e = (m < 32) ? (uBase + m) : (EUN + uBase + m - 32);
        idxT[m] = tgt_i[e];
    } else if (tid < 128) {
        int m = tid - 64;
        int e = (m < 32) ? (uBase + m) : (EUN + uBase + m - 32);
        idxS[m] = src_i[e];
    }
    __syncthreads();

    // cp.async gather: pt rows -> Bc, ps rows -> Bg
#pragma unroll
    for (int l = 0; l < 8; l++) {
        int i4 = tid + l * 256;
        int m = i4 >> 5, q = i4 & 31;
        cpa16(sbase + (BcO + m * 128 + q * 4) * 4, &g_pt16[(size_t)idxT[m] * 128 + q * 4]);
        cpa16(sbase + (BgO + m * 128 + q * 4) * 4, &g_ps16[(size_t)idxS[m] * 128 + q * 4]);
    }
    cpcommit();

    for (int f = tid; f < 224; f += 256) {
        int mm = f / 7, j = f % 7;
        sw7[mm][j] = smooth_weight[(size_t)(uBase + mm) * 7 + j];
    }
    for (int f = tid; f < 896; f += 256) Wenv_s[f >> 7][f & 127] = W_env[f];

    cpwait0();
    __syncthreads();

    // ---- h = silu(pe + pt + ps) -> Ac / Ag ----
#pragma unroll
    for (int l = 0; l < 8; l++) {
        int i4 = tid + l * 256;
        int m = i4 >> 5, q = i4 & 31;
        uint4 A = *(const uint4*)&g_pe16[(size_t)(uBase + (m & 31)) * 128 + q * 4];
        uint4 B = *(uint4*)&dyn[BcO + m * 128 + q * 4];
        uint4 C = *(uint4*)&dyn[BgO + m * 128 + q * 4];
        uint4 O;
        O.x = hss(A.x, B.x, C.x);
        O.y = hss(A.y, B.y, C.y);
        O.z = hss(A.z, B.z, C.z);
        O.w = hss(A.w, B.w, C.w);
        if (q < 16) *(uint4*)&dyn[AcO + m * FP + q * 4] = O;
        else        *(uint4*)&dyn[AgO + m * FP + (q - 16) * 4] = O;
    }
    __syncthreads();

    // weights Wc2/Wg2 -> Bc/Bg
#pragma unroll
    for (int l = 0; l < 8; l++) {
        int i4 = tid + l * 256;
        int n_ = i4 >> 4, q_ = i4 & 15;
        int off = (q_ >> 2) * 2048 + n_ * 16 + (q_ & 3) * 4;
        unsigned d = (n_ * FP + (q_ >> 2) * 16 + (q_ & 3) * 4) * 4;
        cpa16(sbase + BcO * 4 + d, &g_w2ct[off]);
        cpa16(sbase + BgO * 4 + d, &g_w2gt[off]);
    }
    cpcommit();
    cpwait0();
    __syncthreads();

    const unsigned aFragOff = ((lane & 7) + ((lane >> 3) & 1) * 8) * FP + ((lane >> 4) & 1) * 4;
    const unsigned bRow2 = ((wn * 32 + (lane & 7)) * FP + ((lane >> 3) & 1) * 4) * 4;

    // ---- stage A ----
    float accc[2][4][4], accg[2][4][4];
#pragma unroll
    for (int mi = 0; mi < 2; mi++)
#pragma unroll
        for (int ni = 0; ni < 4; ni++)
#pragma unroll
            for (int q = 0; q < 4; q++) { accc[mi][ni][q] = 0.f; accg[mi][ni][q] = 0.f; }
    {
        const unsigned aC = sbase + (AcO + wm * 32 * FP + aFragOff) * 4;
        const unsigned aG = sbase + (AgO + wm * 32 * FP + aFragOff) * 4;
        const unsigned bC = sbase + BcO * 4 + bRow2;
        const unsigned bG = sbase + BgO * 4 + bRow2;
#pragma unroll
        for (int k16 = 0; k16 < 8; k16++) {
            unsigned ac[2][4], ag[2][4], bc[4][2], bg[4][2];
#pragma unroll
            for (int mi = 0; mi < 2; mi++) {
                ldsm4(ac[mi], aC + (mi * 16 * FP + k16 * 8) * 4);
                ldsm4(ag[mi], aG + (mi * 16 * FP + k16 * 8) * 4);
            }
#pragma unroll
            for (int ni = 0; ni < 4; ni++) {
                ldsm2(bc[ni], bC + (ni * 8 * FP + k16 * 8) * 4);
                ldsm2(bg[ni], bG + (ni * 8 * FP + k16 * 8) * 4);
            }
#pragma unroll
            for (int mi = 0; mi < 2; mi++)
#pragma unroll
                for (int ni = 0; ni < 4; ni++) {
                    mma16(accc[mi][ni], ac[mi], bc[ni]);
                    mma16(accg[mi][ni], ag[mi], bg[ni]);
                }
        }
    }

    // ---- LN partial sums ----
#pragma unroll
    for (int mi = 0; mi < 2; mi++)
#pragma unroll
        for (int h = 0; h < 2; h++) {
            float sc = 0.f, sc2 = 0.f, sg = 0.f, sg2 = 0.f;
#pragma unroll
            for (int ni = 0; ni < 4; ni++) {
                float c0 = accc[mi][ni][2 * h], c1 = accc[mi][ni][2 * h + 1];
                float g0 = accg[mi][ni][2 * h], g1 = accg[mi][ni][2 * h + 1];
                sc += c0 + c1; sc2 += c0 * c0 + c1 * c1;
                sg += g0 + g1; sg2 += g0 * g0 + g1 * g1;
            }
#pragma unroll
            for (int off = 1; off < 4; off <<= 1) {
                sc  += __shfl_xor_sync(0xffffffffu, sc,  off, 4);
                sc2 += __shfl_xor_sync(0xffffffffu, sc2, off, 4);
                sg  += __shfl_xor_sync(0xffffffffu, sg,  off, 4);
                sg2 += __shfl_xor_sync(0xffffffffu, sg2, off, 4);
            }
            if (qid == 0) red[wm * 32 + mi * 16 + grp + 8 * h][wn] = make_float4(sc, sc2, sg, sg2);
        }
    __syncthreads();

    // prefetch We1 / We2 into Bc/Bg
#pragma unroll
    for (int l = 0; l < 8; l++) {
        int i4 = tid + l * 256;
        int n_ = i4 >> 4, q_ = i4 & 15;
        int off = (q_ >> 2) * 2048 + n_ * 16 + (q_ & 3) * 4;
        unsigned d = (n_ * FP + (q_ >> 2) * 16 + (q_ & 3) * 4) * 4;
        cpa16(sbase + BcO * 4 + d, &g_we1t[off]);
        cpa16(sbase + BgO * 4 + d, &g_we2t[off]);
    }
    cpcommit();

    // ---- LN epilogue: nl -> t1, msg -> g_msg16 ----
#pragma unroll
    for (int mi = 0; mi < 2; mi++)
#pragma unroll
        for (int h = 0; h < 2; h++) {
            int rloc = wm * 32 + mi * 16 + grp + 8 * h;
            float4 p0 = red[rloc][0], p1 = red[rloc][1], p2 = red[rloc][2], p3 = red[rloc][3];
            float sc = p0.x + p1.x + p2.x + p3.x;
            float sc2 = p0.y + p1.y + p2.y + p3.y;
            float sg = p0.z + p1.z + p2.z + p3.z;
            float sg2 = p0.w + p1.w + p2.w + p3.w;
            float mc = sc * (1.f / 128.f);
            float vc = fmaxf(sc2 * (1.f / 128.f) - mc * mc, 0.f);
            float rc = rsqrtf(vc + 1e-5f);
            float mg = sg * (1.f / 128.f);
            float vg = fmaxf(sg2 * (1.f / 128.f) - mg * mg, 0.f);
            float rg = rsqrtf(vg + 1e-5f);

            int rr = rloc & 31;
            float s0 = sw7[rr][0], s1 = sw7[rr][1], s2 = sw7[rr][2], s3 = sw7[rr][3];
            float s4 = sw7[rr][4], s5 = sw7[rr][5], s6 = sw7[rr][6];
            size_t e = (rloc < 32) ? (size_t)(uBase + rloc) : (size_t)(EUN + uBase + rloc - 32);
            unsigned* mp = g_msg16 + e * 64;
#pragma unroll
            for (int ni = 0; ni < 4; ni++) {
                int c = wn * 32 + ni * 8 + qid * 2;
                float hc0 = (accc[mi][ni][2 * h] - mc) * rc * __ldg(&lncg[c]) + __ldg(&lncb[c]);
                float hg0 = (accg[mi][ni][2 * h] - mg) * rg * __ldg(&lngg[c]) + __ldg(&lngb[c]);
                float nl0 = siluf_(hc0) * sigmoidf_(hg0);
                float hc1 = (accc[mi][ni][2 * h + 1] - mc) * rc * __ldg(&lncg[c + 1]) + __ldg(&lncb[c + 1]);
                float hg1 = (accg[mi][ni][2 * h + 1] - mg) * rg * __ldg(&lngg[c + 1]) + __ldg(&lngb[c + 1]);
                float nl1 = siluf_(hc1) * sigmoidf_(hg1);
                dyn[AcO + rloc * FP + (c >> 1)] = pack2(nl0, nl1);
                float sw0 = s0 * Wenv_s[0][c] + s1 * Wenv_s[1][c] + s2 * Wenv_s[2][c]
                          + s3 * Wenv_s[3][c] + s4 * Wenv_s[4][c] + s5 * Wenv_s[5][c]
                          + s6 * Wenv_s[6][c];
                float sw1 = s0 * Wenv_s[0][c + 1] + s1 * Wenv_s[1][c + 1] + s2 * Wenv_s[2][c + 1]
                          + s3 * Wenv_s[3][c + 1] + s4 * Wenv_s[4][c + 1] + s5 * Wenv_s[5][c + 1]
                          + s6 * Wenv_s[6][c + 1];
                mp[c >> 1] = pack2(nl0 * sw0, nl1 * sw1);
            }
        }
    cpwait0();
    __syncthreads();

    // ---- stage B ----
    float acc1[2][4][4];
#pragma unroll
    for (int mi = 0; mi < 2; mi++)
#pragma unroll
        for (int ni = 0; ni < 4; ni++)
#pragma unroll
            for (int q = 0; q < 4; q++) acc1[mi][ni][q] = 0.f;
    {
        const unsigned aT = sbase + (AcO + wm * 32 * FP + aFragOff) * 4;
        const unsigned bW = sbase + BcO * 4 + bRow2;
#pragma unroll
        for (int k16 = 0; k16 < 8; k16++) {
            unsigned a[2][4], b[4][2];
#pragma unroll
            for (int mi = 0; mi < 2; mi++) ldsm4(a[mi], aT + (mi * 16 * FP + k16 * 8) * 4);
#pragma unroll
            for (int ni = 0; ni < 4; ni++) ldsm2(b[ni], bW + (ni * 8 * FP + k16 * 8) * 4);
#pragma unroll
            for (int mi = 0; mi < 2; mi++)
#pragma unroll
                for (int ni = 0; ni < 4; ni++) mma16(acc1[mi][ni], a[mi], b[ni]);
        }
    }
#pragma unroll
    for (int mi = 0; mi < 2; mi++)
#pragma unroll
        for (int h = 0; h < 2; h++) {
            int rloc = wm * 32 + mi * 16 + grp + 8 * h;
#pragma unroll
            for (int ni = 0; ni < 4; ni++) {
                int c = wn * 32 + ni * 8 + qid * 2;
                dyn[AgO + rloc * FP + (c >> 1)] =
                    pack2(siluf_(acc1[mi][ni][2 * h]), siluf_(acc1[mi][ni][2 * h + 1]));
            }
        }
    __syncthreads();

    // ---- stage C ----
    float acc2[2][4][4];
#pragma unroll
    for (int mi = 0; mi < 2; mi++)
#pragma unroll
        for (int ni = 0; ni < 4; ni++)
#pragma unroll
            for (int q = 0; q < 4; q++) acc2[mi][ni][q] = 0.f;
    {
        const unsigned aT = sbase + (AgO + wm * 32 * FP + aFragOff) * 4;
        const unsigned bW = sbase + BgO * 4 + bRow2;
#pragma unroll
        for (int k16 = 0; k16 < 8; k16++) {
            unsigned a[2][4], b[4][2];
#pragma unroll
            for (int mi = 0; mi < 2; mi++) ldsm4(a[mi], aT + (mi * 16 * FP + k16 * 8) * 4);
#pragma unroll
            for (int ni = 0; ni < 4; ni++) ldsm2(b[ni], bW + (ni * 8 * FP + k16 * 8) * 4);
#pragma unroll
            for (int mi = 0; mi < 2; mi++)
#pragma unroll
                for (int ni = 0; ni < 4; ni++) mma16(acc2[mi][ni], a[mi], b[ni]);
        }
    }
#pragma unroll
    for (int mi = 0; mi < 2; mi++)
#pragma unroll
        for (int h = 0; h < 2; h++) {
            int rloc = wm * 32 + mi * 16 + grp + 8 * h;
#pragma unroll
            for (int ni = 0; ni < 4; ni++) {
                int c = wn * 32 + ni * 8 + qid * 2;
                dyn[AcO + rloc * FP + (c >> 1)] = pack2(acc2[mi][ni][2 * h], acc2[mi][ni][2 * h + 1]);
            }
        }
    __syncthreads();

    // ---- fused edge output ----
#pragma unroll
    for (int it = 0; it < 4; it++) {
        int f = tid + it * 256;
        int row = f >> 5, cw = f & 31;
        uint2 da = *(uint2*)&dyn[AcO + row * FP + cw * 2];
        uint2 db = *(uint2*)&dyn[AcO + (row + 32) * FP + cw * 2];
        float2 a0 = unpack2(da.x), a1 = unpack2(da.y);
        float2 b0 = unpack2(db.x), b1 = unpack2(db.y);
        size_t u = (size_t)(uBase + row);
        float4 ef = *(const float4*)&edge_feat[u * 128 + cw * 4];
        float4 rw = *(const float4*)&edge_res_w[cw * 4];
        float4 o;
        o.x = (a0.x + b0.x) * 0.5f + rw.x * ef.x;
        o.y = (a0.y + b0.y) * 0.5f + rw.y * ef.y;
        o.z = (a1.x + b1.x) * 0.5f + rw.z * ef.z;
        o.w = (a1.y + b1.y) * 0.5f + rw.w * ef.w;
        *(float4*)&out_edge[u * 128 + cw * 4] = o;
    }
}

// ============ k_node_fused ============
__global__ __launch_bounds__(256) void k_node_fused(
    const float* __restrict__ node_feat, const float* __restrict__ node_res_w,
    float* __restrict__ out_node)
{
    __shared__ __align__(16) unsigned As[64 * 68];
    __shared__ __align__(16) unsigned Bs[128 * 20];
    __shared__ __align__(16) unsigned t1[64 * 68];

    const int tid = threadIdx.x;
    const int nBase = blockIdx.x * 64;
    const int w = tid >> 5, lane = tid & 31;
    const int wm = w & 1, wn = w >> 1;
    const int grp = lane >> 2, qid = lane & 3;

    for (int s = 0; s < 8; s++) {
        int m = w * 8 + s;
        int node = nBase + m;
        float4 acc = make_float4(0.f, 0.f, 0.f, 0.f);
        if (node < NN) {
            int b = g_csr_off[node], e2 = g_csr_off[node + 1];
            int j = b;
            for (; j + 1 < e2; j += 2) {
                int ed0 = g_csr_edges[j], ed1 = g_csr_edges[j + 1];
                uint2 v0 = *(const uint2*)&g_msg16[(size_t)ed0 * 64 + lane * 2];
                uint2 v1 = *(const uint2*)&g_msg16[(size_t)ed1 * 64 + lane * 2];
                float2 a0 = unpack2(v0.x), b0 = unpack2(v0.y);
                float2 a1 = unpack2(v1.x), b1 = unpack2(v1.y);
                acc.x += a0.x + a1.x; acc.y += a0.y + a1.y;
                acc.z += b0.x + b1.x; acc.w += b0.y + b1.y;
            }
            if (j < e2) {
                int ed = g_csr_edges[j];
                uint2 v = *(const uint2*)&g_msg16[(size_t)ed * 64 + lane * 2];
                float2 a = unpack2(v.x), bb = unpack2(v.y);
                acc.x += a.x; acc.y += a.y; acc.z += bb.x; acc.w += bb.y;
            }
        }
        *(uint2*)&As[m * 68 + lane * 2] = make_uint2(pack2(acc.x, acc.y), pack2(acc.z, acc.w));
    }
    __syncthreads();

    const int aRow = wm * 32 + (lane & 7) + ((lane >> 3) & 1) * 8;
    const int aCol = ((lane >> 4) & 1) * 4;
    const unsigned aBase = sptr(As) + (aRow * 68 + aCol) * 4;
    const unsigned tBase = sptr(t1) + (aRow * 68 + aCol) * 4;
    const unsigned bBase = sptr(Bs) + ((wn * 32 + (lane & 7)) * 20 + ((lane >> 3) & 1) * 4) * 4;

    float acc[2][4][4];
#pragma unroll
    for (int mi = 0; mi < 2; mi++)
#pragma unroll
        for (int ni = 0; ni < 4; ni++)
#pragma unroll
            for (int q = 0; q < 4; q++) acc[mi][ni][q] = 0.f;

    for (int kt = 0; kt < 4; kt++) {
        {
            const uint4* src = (const uint4*)&g_wn1t[kt * 2048];
#pragma unroll
            for (int l = 0; l < 2; l++) {
                int i4 = tid + l * 256;
                int n = i4 >> 2, wq = (i4 & 3) * 4;
                *(uint4*)&Bs[n * 20 + wq] = src[i4];
            }
        }
        __syncthreads();
#pragma unroll
        for (int k16 = 0; k16 < 2; k16++) {
            unsigned a[2][4], b[4][2];
#pragma unroll
            for (int mi = 0; mi < 2; mi++)
                ldsm4(a[mi], aBase + (mi * 16 * 68 + kt * 16 + k16 * 8) * 4);
#pragma unroll
            for (int ni = 0; ni < 4; ni++) ldsm2(b[ni], bBase + (ni * 8 * 20 + k16 * 8) * 4);
#pragma unroll
            for (int mi = 0; mi < 2; mi++)
#pragma unroll
                for (int ni = 0; ni < 4; ni++) mma16(acc[mi][ni], a[mi], b[ni]);
        }
        __syncthreads();
    }
#pragma unroll
    for (int mi = 0; mi < 2; mi++)
#pragma unroll
        for (int h = 0; h < 2; h++) {
            int r = wm * 32 + mi * 16 + grp + 8 * h;
#pragma unroll
            for (int ni = 0; ni < 4; ni++) {
                int c = wn * 32 + ni * 8 + qid * 2;
                t1[r * 68 + (c >> 1)] = pack2(siluf_(acc[mi][ni][2 * h]), siluf_(acc[mi][ni][2 * h + 1]));
            }
        }
    __syncthreads();

    float acc2[2][4][4];
#pragma unroll
    for (int mi = 0; mi < 2; mi++)
#pragma unroll
        for (int ni = 0; ni < 4; ni++)
#pragma unroll
            for (int q = 0; q < 4; q++) acc2[mi][ni][q] = 0.f;

    for (int kt = 0; kt < 4; kt++) {
        {
            const uint4* src = (const uint4*)&g_wn2t[kt * 2048];
#pragma unroll
            for (int l = 0; l < 2; l++) {
                int i4 = tid + l * 256;
                int n = i4 >> 2, wq = (i4 & 3) * 4;
                *(uint4*)&Bs[n * 20 + wq] = src[i4];
            }
        }
        __syncthreads();
#pragma unroll
        for (int k16 = 0; k16 < 2; k16++) {
            unsigned a[2][4], b[4][2];
#pragma unroll
            for (int mi = 0; mi < 2; mi++)
                ldsm4(a[mi], tBase + (mi * 16 * 68 + kt * 16 + k16 * 8) * 4);
#pragma unroll
            for (int ni = 0; ni < 4; ni++) ldsm2(b[ni], bBase + (ni * 8 * 20 + k16 * 8) * 4);
#pragma unroll
            for (int mi = 0; mi < 2; mi++)
#pragma unroll
                for (int ni = 0; ni < 4; ni++) mma16(acc2[mi][ni], a[mi], b[ni]);
        }
        __syncthreads();
    }

#pragma unroll
    for (int mi = 0; mi < 2; mi++)
#pragma unroll
        for (int h = 0; h < 2; h++) {
            int row = nBase + wm * 32 + mi * 16 + grp + 8 * h;
            if (row >= NN) continue;
            const float* nf = node_feat + ((size_t)row << 7);
            float* op = out_node + ((size_t)row << 7);
#pragma unroll
            for (int ni = 0; ni < 4; ni++) {
                int c = wn * 32 + ni * 8 + qid * 2;
                float o0 = acc2[mi][ni][2 * h]     + __ldg(&node_res_w[c])     * nf[c];
                float o1 = acc2[mi][ni][2 * h + 1] + __ldg(&node_res_w[c + 1]) * nf[c + 1];
                *(float2*)(op + c) = make_float2(o0, o1);
            }
        }
}

// ---------------- launch: fork/join CSR chain on a side stream ----------------
extern "C" void kernel_launch(void* const* d_in, const int* in_sizes, int n_in,
                              void* d_out, int out_size)
{
    (void)in_sizes; (void)n_in; (void)out_size;
    const float* node_feat     = (const float*)d_in[0];
    const float* edge_feat     = (const float*)d_in[1];
    const float* smooth_weight = (const float*)d_in[2];
    const int*   source_index  = (const int*)d_in[3];
    const int*   target_index  = (const int*)d_in[4];
    const float* W_env         = (const float*)d_in[6];
    const float* Wc1           = (const float*)d_in[7];
    const float* Wc2           = (const float*)d_in[8];
    const float* Wg1           = (const float*)d_in[9];
    const float* Wg2           = (const float*)d_in[10];
    const float* ln_c_g        = (const float*)d_in[11];
    const float* ln_c_b        = (const float*)d_in[12];
    const float* ln_g_g        = (const float*)d_in[13];
    const float* ln_g_b        = (const float*)d_in[14];
    const float* Wn1           = (const float*)d_in[15];
    const float* Wn2           = (const float*)d_in[16];
    const float* We1           = (const float*)d_in[17];
    const float* We2           = (const float*)d_in[18];
    const float* node_res_w    = (const float*)d_in[19];
    const float* edge_res_w    = (const float*)d_in[20];

    float* out_node = (float*)d_out;
    float* out_edge = out_node + (size_t)NN * 128;

    static cudaStream_t s2 = nullptr;
    static cudaEvent_t evFork = nullptr, evJoin = nullptr;
    static bool attrsSet = false;
    if (!s2) {
        cudaStreamCreateWithFlags(&s2, cudaStreamNonBlocking);
        cudaEventCreateWithFlags(&evFork, cudaEventDisableTiming);
        cudaEventCreateWithFlags(&evJoin, cudaEventDisableTiming);
    }
    if (!attrsSet) {
        cudaFuncSetAttribute(k_mega, cudaFuncAttributeMaxDynamicSharedMemorySize, MEGA_DYN);
        cudaFuncSetAttribute(k_pre1, cudaFuncAttributeMaxDynamicSharedMemorySize, PRE1_DYN);
        attrsSet = true;
    }

    const int NPART = (NN + 255) / 256;

    // fork: CSR chain on s2, independent of the main compute chain
    cudaEventRecord(evFork, 0);
    cudaStreamWaitEvent(s2, evFork, 0);
    k_zero_cnt<<<(NN + 255) / 256, 256, 0, s2>>>();
    k_hist<<<(EDN + 255) / 256, 256, 0, s2>>>(target_index);
    k_scan_part<<<NPART, 256, 0, s2>>>();
    k_scan_top<<<1, 256, 0, s2>>>(NPART);
    k_scan_apply<<<NPART, 256, 0, s2>>>();
    k_scatter<<<(EDN + 255) / 256, 256, 0, s2>>>(target_index);
    cudaEventRecord(evJoin, s2);

    // main chain
    k_prepA<<<(PREPA_ITEMS + 255) / 256, 256>>>(Wc1, Wg1, Wc2, Wg2, We1, We2, Wn1, Wn2);
    k_pre1<<<PE_BLKS + 2 * PN_BLKS, 512, PRE1_DYN>>>(edge_feat, node_feat);

    k_mega<<<EUN / 32, 256, MEGA_DYN>>>(target_index, source_index,
                                        ln_c_g, ln_c_b, ln_g_g, ln_g_b,
                                        smooth_weight, W_env,
                                        edge_feat, edge_res_w, out_edge);

    // join: node_fused needs both k_mega (msg) and the CSR chain
    cudaStreamWaitEvent(0, evJoin, 0);
    k_node_fused<<<(NN + 63) / 64, 256>>>(node_feat, node_res_w, out_node);
}